// round 11
// baseline (speedup 1.0000x reference)
#include <cuda_runtime.h>
#include <cuda_bf16.h>
#include <math.h>
#include <stdint.h>

// Problem constants
#define Bc 8
#define Hc 8
#define Fc 768
#define Dc 128
#define Ec 256
#define Lc 13
#define Tc 1000
#define DCORR 8128
#define TP 1024                 // padded T
#define DT (128*TP)             // plane size per (kv,bh)

// ---------------- device scratch ----------------
__device__ float g_kw[Hc*Lc];
__device__ float g_vw[Hc*Lc];
__device__ __nv_bfloat16 g_ahi[(size_t)2*Bc*Hc*Tc*Fc];   // raw activations [kv][bh][t][f]
__device__ __nv_bfloat16 g_alo[(size_t)2*Bc*Hc*Tc*Fc];
__device__ __nv_bfloat16 g_whi[(size_t)2*Hc*Dc*Fc];      // weights [kv][h][d][f]
__device__ __nv_bfloat16 g_wlo[(size_t)2*Hc*Dc*Fc];
__device__ __nv_bfloat16 g_chi[(size_t)2*Bc*Hc*DT];      // GEMM out planes [kv][bh][d][t]
__device__ __nv_bfloat16 g_clo[(size_t)2*Bc*Hc*DT];
__device__ float g_s1[2*Bc*Hc*Dc];
__device__ float g_s2[2*Bc*Hc*Dc];
__device__ float g_muk[Bc*Hc*Dc];
__device__ float g_sdk[Bc*Hc*Dc];
__device__ float g_muv[Bc*Hc*Dc];
__device__ float g_sdv[Bc*Hc*Dc];
__device__ float g_o1[Bc*Hc*Dc];
__device__ float g_S[(size_t)Bc*Hc*Dc*Dc];
__device__ float g_corr[(size_t)Bc*Hc*DCORR];
__device__ float g_outs[Bc*Hc*Ec];

__device__ __forceinline__ uint32_t smem_u32(const void* p) {
    uint32_t a;
    asm("{ .reg .u64 t; cvta.to.shared.u64 t, %1; cvt.u32.u64 %0, t; }" : "=r"(a) : "l"(p));
    return a;
}
#define CP_COMMIT()  asm volatile("cp.async.commit_group;" ::: "memory")
#define CP_WAIT(n)   asm volatile("cp.async.wait_group %0;" :: "n"(n) : "memory")
#define LDSM4(r0, r1, r2, r3, a) \
    asm volatile("ldmatrix.sync.aligned.m8n8.x4.shared.b16 {%0,%1,%2,%3}, [%4];" \
        : "=r"(r0), "=r"(r1), "=r"(r2), "=r"(r3) : "r"(a))
#define MMA_BF16(d, a, b) asm volatile( \
    "mma.sync.aligned.m16n8k16.row.col.f32.bf16.bf16.f32 " \
    "{%0,%1,%2,%3},{%4,%5,%6,%7},{%8,%9},{%0,%1,%2,%3};\n" \
    : "+f"((d)[0]), "+f"((d)[1]), "+f"((d)[2]), "+f"((d)[3]) \
    : "r"((a)[0]), "r"((a)[1]), "r"((a)[2]), "r"((a)[3]), "r"((b)[0]), "r"((b)[1]))

// hi+lo bf16 reconstruction of 4 packed values
__device__ __forceinline__ float4 un4(uint2 h, uint2 l) {
    float4 r;
    r.x = __int_as_float(h.x << 16)        + __int_as_float(l.x << 16);
    r.y = __int_as_float(h.x & 0xffff0000u) + __int_as_float(l.x & 0xffff0000u);
    r.z = __int_as_float(h.y << 16)        + __int_as_float(l.y << 16);
    r.w = __int_as_float(h.y & 0xffff0000u) + __int_as_float(l.y & 0xffff0000u);
    return r;
}

// ---------------- stage 0: init (zero accumulators + softmax weights) ----------------
__global__ void k_init(const float* __restrict__ wk, const float* __restrict__ wv) {
    int i = blockIdx.x*blockDim.x + threadIdx.x;
    float4 z = make_float4(0.f,0.f,0.f,0.f);
    if (i < 262144) ((float4*)g_S)[i] = z;
    else {
        int j = i - 262144;
        if (j < 4096) ((float4*)g_s1)[j] = z;
        else ((float4*)g_s2)[j - 4096] = z;
    }
    if (blockIdx.x == 0 && threadIdx.x < 2*Hc) {
        int tid = threadIdx.x;
        int h = tid % Hc;
        const float* src = (tid < Hc ? wk : wv) + h*Lc;
        float* dst = (tid < Hc ? g_kw : g_vw) + h*Lc;
        float m = -1e30f;
        for (int l = 0; l < Lc; l++) m = fmaxf(m, src[l]);
        float e[Lc]; float s = 0.f;
        for (int l = 0; l < Lc; l++) { e[l] = expf(src[l]-m); s += e[l]; }
        float inv = 1.f/s;
        for (int l = 0; l < Lc; l++) dst[l] = e[l]*inv;
    }
}

// ---------------- pack W to bf16 hi/lo ----------------
__global__ void k_wconv(const float* __restrict__ Wk, const float* __restrict__ Wv) {
    size_t i = (size_t)blockIdx.x*256 + threadIdx.x;
    const float* W = blockIdx.y ? Wv : Wk;
    float v = W[i];
    __nv_bfloat16 h16 = __float2bfloat16(v);
    __nv_bfloat16 l16 = __float2bfloat16(v - __bfloat162float(h16));
    size_t o = (size_t)blockIdx.y*(Hc*Dc*Fc) + i;
    g_whi[o] = h16;
    g_wlo[o] = l16;
}

// ---------------- stage 1: L-contraction -> bf16 hi/lo [t][f] ----------------
__global__ __launch_bounds__(128) void k_raw(const float* __restrict__ x) {
    __shared__ float2 skv[Hc*Lc];
    __shared__ float xs[2][16][212];
    __shared__ __align__(8) unsigned s_ohi[2][Hc][16][10];
    __shared__ __align__(8) unsigned s_olo[2][Hc][16][10];
    int tx = threadIdx.x;
    int ty = threadIdx.y;
    int tid = ty*16 + tx;
    if (tid < Hc*Lc) skv[tid] = make_float2(g_kw[tid], g_vw[tid]);

    int tbase = blockIdx.x*64;
    int f0 = blockIdx.y*16;
    int b  = blockIdx.z;
    const float* xb = x + (size_t)(b*Fc + f0)*Tc*13;

    auto stage_x = [&](int buf, int st0) {
        int n = Tc - st0;
        int maxf4 = (n >= 16) ? 52 : (n > 0 ? ((n*13) >> 2) : 0);
#pragma unroll
        for (int it = 0; it < 7; it++) {
            int idx = tid + it*128;
            if (idx < 832) {
                int row = idx / 52, col = idx % 52;
                unsigned sz = (col < maxf4) ? 16u : 0u;
                int scol = (col < maxf4) ? col : 0;
                uint32_t dst = smem_u32(&xs[buf][row][col*4]);
                const float* src = xb + (size_t)row*(Tc*13) + st0*13 + scol*4;
                asm volatile("cp.async.cg.shared.global [%0], [%1], 16, %2;"
                             :: "r"(dst), "l"(src), "r"(sz));
            }
        }
        CP_COMMIT();
    };

    stage_x(0, tbase);

#pragma unroll 1
    for (int s = 0; s < 4; s++) {
        int st0 = tbase + s*16;
        if (s < 3) { stage_x((s+1) & 1, st0 + 16); CP_WAIT(1); }
        else CP_WAIT(0);
        __syncthreads();

        int buf = s & 1;
        float xv0[Lc], xv1[Lc];
#pragma unroll
        for (int l = 0; l < Lc; l++) {
            xv0[l] = xs[buf][ty*2][tx*13 + l];
            xv1[l] = xs[buf][ty*2 + 1][tx*13 + l];
        }

#pragma unroll
        for (int h = 0; h < Hc; h++) {
            float k0 = 0.f, v0 = 0.f, k1 = 0.f, v1 = 0.f;
#pragma unroll
            for (int l = 0; l < Lc; l++) {
                float2 w = skv[h*Lc + l];
                k0 += xv0[l]*w.x; v0 += xv0[l]*w.y;
                k1 += xv1[l]*w.x; v1 += xv1[l]*w.y;
            }
            {
                unsigned b0 = __float_as_uint(k0), b1 = __float_as_uint(k1);
                unsigned hiw = __byte_perm(b0, b1, 0x7632);
                float d0 = k0 - __uint_as_float(b0 & 0xffff0000u);
                float d1 = k1 - __uint_as_float(b1 & 0xffff0000u);
                unsigned low;
                asm("cvt.rn.bf16x2.f32 %0, %1, %2;" : "=r"(low) : "f"(d1), "f"(d0));
                s_ohi[0][h][tx][ty] = hiw;
                s_olo[0][h][tx][ty] = low;
            }
            {
                unsigned b0 = __float_as_uint(v0), b1 = __float_as_uint(v1);
                unsigned hiw = __byte_perm(b0, b1, 0x7632);
                float d0 = v0 - __uint_as_float(b0 & 0xffff0000u);
                float d1 = v1 - __uint_as_float(b1 & 0xffff0000u);
                unsigned low;
                asm("cvt.rn.bf16x2.f32 %0, %1, %2;" : "=r"(low) : "f"(d1), "f"(d0));
                s_ohi[1][h][tx][ty] = hiw;
                s_olo[1][h][tx][ty] = low;
            }
        }
        __syncthreads();

        int w = tid >> 5, lane = tid & 31;
        int f4 = lane & 3;
        int tq = lane >> 2;
#pragma unroll
        for (int it = 0; it < 4; it++) {
            int job = w*4 + it;
            int kv = job >> 3;
            int h = job & 7;
            size_t rowbase = ((size_t)(kv*Bc + b)*Hc + h)*Tc;
#pragma unroll
            for (int ti = 0; ti < 2; ti++) {
                int tl = ti*8 + tq;
                int tt = st0 + tl;
                if (tt < Tc) {
                    size_t off = (rowbase + tt)*Fc + f0 + f4*4;
                    *(uint2*)(g_ahi + off) = *(uint2*)&s_ohi[kv][h][tl][f4*2];
                    *(uint2*)(g_alo + off) = *(uint2*)&s_olo[kv][h][tl][f4*2];
                }
            }
        }
        __syncthreads();
    }
}

// ---------------- stage 2: mma.sync GEMM (128x64 tile, 3-stage, 1 barrier/chunk) ----------------
#define RS 80
#define A_PL (128*RS)            // 10240
#define B_PL (64*RS)             // 5120
#define STAGE_G (2*A_PL + 2*B_PL)  // 30720
#define GSMEM (3*STAGE_G)          // 92160
#define NCH (Fc/32)

__device__ __forceinline__ void prefetch_g(
    int c, int stage, uint32_t sb, int t0, int tid,
    const __nv_bfloat16* __restrict__ Ahi, const __nv_bfloat16* __restrict__ Alo,
    const __nv_bfloat16* __restrict__ Bhi, const __nv_bfloat16* __restrict__ Blo) {
    int kc = c*32;
    uint32_t stb = sb + stage*STAGE_G;
#pragma unroll
    for (int it = 0; it < 6; it++) {
        int idx = tid + it*256;        // 0..1535
        if (idx < 1024) {
            int plane = idx >> 9;
            int row = (idx >> 2) & 127;
            int seg = idx & 3;
            uint32_t dst = stb + plane*A_PL + row*RS + seg*16;
            int t = t0 + row;
            unsigned sz = 16;
            if (t >= Tc) { t = 0; sz = 0; }
            const __nv_bfloat16* src = (plane ? Alo : Ahi) + (size_t)t*Fc + kc + seg*8;
            asm volatile("cp.async.cg.shared.global [%0], [%1], 16, %2;"
                         :: "r"(dst), "l"(src), "r"(sz));
        } else {
            int j = idx - 1024;        // 0..511
            int plane = j >> 8;
            int row = (j >> 2) & 63;
            int seg = j & 3;
            uint32_t dst = stb + 2*A_PL + plane*B_PL + row*RS + seg*16;
            const __nv_bfloat16* src = (plane ? Blo : Bhi) + (size_t)row*Fc + kc + seg*8;
            asm volatile("cp.async.cg.shared.global [%0], [%1], 16;"
                         :: "r"(dst), "l"(src));
        }
    }
    CP_COMMIT();
}

__global__ __launch_bounds__(256, 2) void k_gemm(
    const float* __restrict__ bk, const float* __restrict__ bv) {
    extern __shared__ __align__(1024) char dynsmem[];
    uint32_t sb = smem_u32(dynsmem);

    int tid = threadIdx.x;
    int warp = tid >> 5, lane = tid & 31;
    int bh = blockIdx.y;
    int h = bh & 7;
    int kv = blockIdx.z >> 1;
    int dh = blockIdx.z & 1;
    int d0 = dh*64;
    int t0 = blockIdx.x*128;

    const __nv_bfloat16* Ahi = g_ahi + (size_t)(kv*Bc*Hc + bh)*Tc*Fc;
    const __nv_bfloat16* Alo = g_alo + (size_t)(kv*Bc*Hc + bh)*Tc*Fc;
    const __nv_bfloat16* Bhi = g_whi + ((size_t)(kv*Hc + h)*Dc + d0)*Fc;
    const __nv_bfloat16* Blo = g_wlo + ((size_t)(kv*Hc + h)*Dc + d0)*Fc;
    const float* bias = (kv ? bv : bk) + h*Dc + d0;

    int m0w = (warp >> 1)*32;       // 0,32,64,96
    int n0w = (warp & 1)*32;        // 0,32
    int arow = (lane & 7) + ((lane >> 3) & 1)*8;
    int akb  = ((lane >> 4) & 1)*16;
    int brow = (lane & 7) + ((lane >> 4) & 1)*8;
    int bkb  = ((lane >> 3) & 1)*16;

    float acc[2][4][4];
#pragma unroll
    for (int i = 0; i < 2; i++)
#pragma unroll
        for (int j = 0; j < 4; j++)
#pragma unroll
            for (int r = 0; r < 4; r++) acc[i][j][r] = 0.f;

    prefetch_g(0, 0, sb, t0, tid, Ahi, Alo, Bhi, Blo);
    prefetch_g(1, 1, sb, t0, tid, Ahi, Alo, Bhi, Blo);

#pragma unroll 1
    for (int c = 0; c < NCH; c++) {
        // 1) my oldest pending group (stage c%3) completes
        if (c < NCH-1) CP_WAIT(1); else CP_WAIT(0);
        // 2) ALL threads past their waits -> stage c%3 fully visible;
        //    also proves all warps done reading stage (c-1)%3 == (c+2)%3
        __syncthreads();
        // 3) refill the freed stage while we compute
        if (c + 2 < NCH)
            prefetch_g(c+2, (c+2)%3, sb, t0, tid, Ahi, Alo, Bhi, Blo);
        // 4) compute stage c%3
        uint32_t st = sb + (c%3)*STAGE_G;
#pragma unroll
        for (int ks = 0; ks < 2; ks++) {
            unsigned ah[2][4], al[2][4];
#pragma unroll
            for (int mi = 0; mi < 2; mi++) {
                uint32_t a0 = st + (uint32_t)((m0w + mi*16 + arow)*RS + ks*32 + akb);
                LDSM4(ah[mi][0], ah[mi][1], ah[mi][2], ah[mi][3], a0);
                LDSM4(al[mi][0], al[mi][1], al[mi][2], al[mi][3], a0 + A_PL);
            }
#pragma unroll
            for (int ni = 0; ni < 2; ni++) {
                uint32_t b0 = st + 2*A_PL + (uint32_t)((n0w + ni*16 + brow)*RS + ks*32 + bkb);
                unsigned bhv[4], blv[4];
                LDSM4(bhv[0], bhv[1], bhv[2], bhv[3], b0);
                LDSM4(blv[0], blv[1], blv[2], blv[3], b0 + B_PL);
#pragma unroll
                for (int mi = 0; mi < 2; mi++)
#pragma unroll
                    for (int j2 = 0; j2 < 2; j2++) {
                        int nj = ni*2 + j2;
                        MMA_BF16(acc[mi][nj], ah[mi], &bhv[j2*2]);
                        MMA_BF16(acc[mi][nj], ah[mi], &blv[j2*2]);
                        MMA_BF16(acc[mi][nj], al[mi], &bhv[j2*2]);
                    }
            }
        }
    }

    // epilogue: transpose through smem to [d][t], emit bf16 hi/lo planes + stats
    __syncthreads();
    float* Cs = (float*)dynsmem;           // [64 d][132]
    int g = lane >> 2, q = lane & 3;
#pragma unroll
    for (int nj = 0; nj < 4; nj++) {
        int d = n0w + nj*8 + q*2;
        float2 bb = *(const float2*)(bias + d);
#pragma unroll
        for (int mi = 0; mi < 2; mi++) {
            int r = m0w + mi*16 + g;
            Cs[d*132 + r]         = acc[mi][nj][0] + bb.x;
            Cs[(d+1)*132 + r]     = acc[mi][nj][1] + bb.y;
            Cs[d*132 + r + 8]     = acc[mi][nj][2] + bb.x;
            Cs[(d+1)*132 + r + 8] = acc[mi][nj][3] + bb.y;
        }
    }
    __syncthreads();

    __nv_bfloat16* Phi = g_chi + ((size_t)kv*64 + bh)*DT + (size_t)d0*TP;
    __nv_bfloat16* Plo = g_clo + ((size_t)kv*64 + bh)*DT + (size_t)d0*TP;
    size_t so = ((size_t)kv*64 + bh)*Dc + d0;
    int tb = t0 + lane*4;
#pragma unroll 1
    for (int rr = 0; rr < 8; rr++) {
        int d = warp*8 + rr;
        float4 v = *(float4*)&Cs[d*132 + lane*4];
        v.x = (tb+0 < Tc) ? v.x : 0.f;
        v.y = (tb+1 < Tc) ? v.y : 0.f;
        v.z = (tb+2 < Tc) ? v.z : 0.f;
        v.w = (tb+3 < Tc) ? v.w : 0.f;
        __nv_bfloat162 h01 = __floats2bfloat162_rn(v.x, v.y);
        __nv_bfloat162 h23 = __floats2bfloat162_rn(v.z, v.w);
        unsigned uh01 = *(unsigned*)&h01, uh23 = *(unsigned*)&h23;
        float f0 = __int_as_float(uh01 << 16);
        float f1 = __int_as_float(uh01 & 0xffff0000u);
        float f2 = __int_as_float(uh23 << 16);
        float f3 = __int_as_float(uh23 & 0xffff0000u);
        __nv_bfloat162 l01 = __floats2bfloat162_rn(v.x - f0, v.y - f1);
        __nv_bfloat162 l23 = __floats2bfloat162_rn(v.z - f2, v.w - f3);
        *(uint2*)(Phi + (size_t)d*TP + tb) = make_uint2(uh01, uh23);
        *(uint2*)(Plo + (size_t)d*TP + tb) = make_uint2(*(unsigned*)&l01, *(unsigned*)&l23);
        float p1 = v.x + v.y + v.z + v.w;
        float p2 = v.x*v.x + v.y*v.y + v.z*v.z + v.w*v.w;
        for (int off = 16; off; off >>= 1) {
            p1 += __shfl_down_sync(~0u, p1, off);
            p2 += __shfl_down_sync(~0u, p2, off);
        }
        if (lane == 0) {
            atomicAdd(&g_s1[so + d], p1);
            atomicAdd(&g_s2[so + d], p2);
        }
    }
}

// ---------------- stats finalize + outs init ----------------
__global__ void k_statfin(const float* __restrict__ bproj) {
    int bid = blockIdx.x;
    int tid = threadIdx.x;
    if (bid < 64) {
        int kv = tid >> 7;
        int d = tid & 127;
        size_t o = ((size_t)kv*64 + bid)*Dc + d;
        float s1 = g_s1[o], s2 = g_s2[o];
        float mu = s1 * (1.f/Tc);
        float var = (s2 - (float)Tc*mu*mu) * (1.f/(Tc-1));
        var = fmaxf(var, 0.f);
        float sd = sqrtf(var) + 1e-9f;
        if (kv == 0) { g_muk[bid*Dc + d] = mu; g_sdk[bid*Dc + d] = sd; }
        else         { g_muv[bid*Dc + d] = mu; g_sdv[bid*Dc + d] = sd; }
    } else {
        for (int i = tid; i < Bc*Hc*Ec; i += 256)
            g_outs[i] = bproj[i & (Hc*Ec - 1)];
    }
}

// ---------------- stage 3a: attention + o1 (coalesced [d][t]) ----------------
__global__ __launch_bounds__(256) void k_attn(const float* __restrict__ q) {
    __shared__ float s_sc[TP];
    __shared__ float s_red[256];
    __shared__ float s_q[Dc];
    int tid = threadIdx.x;
    int bh = blockIdx.x;
    int h = bh & 7;
    const __nv_bfloat16* Khi = g_chi + (size_t)bh*DT;
    const __nv_bfloat16* Klo = g_clo + (size_t)bh*DT;
    const __nv_bfloat16* Vhi = g_chi + (size_t)(64 + bh)*DT;
    const __nv_bfloat16* Vlo = g_clo + (size_t)(64 + bh)*DT;
    if (tid < Dc) s_q[tid] = q[h*Dc + tid];
    __syncthreads();

    if (tid < 250) {
        float a0 = 0.f, a1 = 0.f, a2 = 0.f, a3 = 0.f;
#pragma unroll 4
        for (int d = 0; d < Dc; d++) {
            uint2 ph = *(const uint2*)(Khi + (size_t)d*TP + tid*4);
            uint2 pl = *(const uint2*)(Klo + (size_t)d*TP + tid*4);
            float qd = s_q[d];
            float4 kv4 = un4(ph, pl);
            a0 += qd*kv4.x; a1 += qd*kv4.y; a2 += qd*kv4.z; a3 += qd*kv4.w;
        }
        const float sc = 0.08838834764831845f;
        *(float4*)&s_sc[tid*4] = make_float4(a0*sc, a1*sc, a2*sc, a3*sc);
    }
    if (tid < 24) s_sc[1000 + tid] = 0.f;
    __syncthreads();

    float lm = -1e30f;
    for (int t = tid; t < Tc; t += 256) lm = fmaxf(lm, s_sc[t]);
    s_red[tid] = lm; __syncthreads();
    for (int s = 128; s; s >>= 1) { if (tid < s) s_red[tid] = fmaxf(s_red[tid], s_red[tid+s]); __syncthreads(); }
    float m = s_red[0];
    __syncthreads();
    float ls = 0.f;
    for (int t = tid; t < Tc; t += 256) { float e = expf(s_sc[t]-m); s_sc[t] = e; ls += e; }
    s_red[tid] = ls; __syncthreads();
    for (int s = 128; s; s >>= 1) { if (tid < s) s_red[tid] += s_red[tid+s]; __syncthreads(); }
    float inv = 1.f / s_red[0];
    __syncthreads();

    int w = tid >> 5, lane = tid & 31;
#pragma unroll 1
    for (int rr = 0; rr < 16; rr++) {
        int d = w*16 + rr;
        float acc = 0.f;
#pragma unroll
        for (int cc = 0; cc < 8; cc++) {
            int grp = lane + cc*32;
            uint2 ph = *(const uint2*)(Vhi + (size_t)d*TP + grp*4);
            uint2 pl = *(const uint2*)(Vlo + (size_t)d*TP + grp*4);
            float4 vv = un4(ph, pl);
            float4 aa = *(float4*)&s_sc[grp*4];
            acc += aa.x*vv.x + aa.y*vv.y + aa.z*vv.z + aa.w*vv.w;
        }
        for (int off = 16; off; off >>= 1) acc += __shfl_down_sync(~0u, acc, off);
        if (lane == 0) g_o1[bh*Dc + d] = acc * inv;
    }
}

// ---------------- stage 3b: S = K^T V via tensor cores on [d][t] planes ----------------
#define SPLANE_B (128*RS)
#define SSTAGE_B (4*SPLANE_B)
#define SSMEM (2*SSTAGE_B)
#define NCHS 16

__device__ __forceinline__ void prefetch_smat(
    int c, int stage, uint32_t sb, int tid,
    const __nv_bfloat16* __restrict__ Ahi, const __nv_bfloat16* __restrict__ Alo,
    const __nv_bfloat16* __restrict__ Bhi, const __nv_bfloat16* __restrict__ Blo) {
    int kc = c*32;
    uint32_t stb = sb + stage*SSTAGE_B;
#pragma unroll
    for (int it = 0; it < 8; it++) {
        int idx = tid + it*256;
        int plane = idx >> 9;
        int row = (idx >> 2) & 127;
        int seg = idx & 3;
        uint32_t dst = stb + plane*SPLANE_B + row*RS + seg*16;
        const __nv_bfloat16* src =
            (plane == 0 ? Ahi : plane == 1 ? Alo : plane == 2 ? Bhi : Blo)
            + (size_t)row*TP + kc + seg*8;
        asm volatile("cp.async.cg.shared.global [%0], [%1], 16;" :: "r"(dst), "l"(src));
    }
    CP_COMMIT();
}

__global__ __launch_bounds__(256, 2) void k_smat() {
    extern __shared__ __align__(1024) char dynsmem[];
    uint32_t sb = smem_u32(dynsmem);
    int tid = threadIdx.x;
    int warp = tid >> 5, lane = tid & 31;
    int bh = blockIdx.y;
    int seg = blockIdx.x;
    const __nv_bfloat16* Ahi = g_chi + (size_t)bh*DT + seg*512;
    const __nv_bfloat16* Alo = g_clo + (size_t)bh*DT + seg*512;
    const __nv_bfloat16* Bhi = g_chi + (size_t)(64 + bh)*DT + seg*512;
    const __nv_bfloat16* Blo = g_clo + (size_t)(64 + bh)*DT + seg*512;

    int m0w = (warp >> 1)*32;
    int n0w = (warp & 1)*64;
    int arow = (lane & 7) + ((lane >> 3) & 1)*8;
    int akb  = ((lane >> 4) & 1)*16;
    int brow = (lane & 7) + ((lane >> 4) & 1)*8;
    int bkb  = ((lane >> 3) & 1)*16;

    float acc[2][8][4];
#pragma unroll
    for (int i = 0; i < 2; i++)
#pragma unroll
        for (int j = 0; j < 8; j++)
#pragma unroll
            for (int r = 0; r < 4; r++) acc[i][j][r] = 0.f;

    prefetch_smat(0, 0, sb, tid, Ahi, Alo, Bhi, Blo);
    prefetch_smat(1, 1, sb, tid, Ahi, Alo, Bhi, Blo);

#pragma unroll 1
    for (int c = 0; c < NCHS; c++) {
        if (c < NCHS-1) CP_WAIT(1); else CP_WAIT(0);
        __syncthreads();
        uint32_t st = sb + (c & 1)*SSTAGE_B;
#pragma unroll
        for (int ks = 0; ks < 2; ks++) {
            unsigned ah[2][4], al[2][4];
#pragma unroll
            for (int mi = 0; mi < 2; mi++) {
                uint32_t a0 = st + (uint32_t)((m0w + mi*16 + arow)*RS + ks*32 + akb);
                LDSM4(ah[mi][0], ah[mi][1], ah[mi][2], ah[mi][3], a0);
                LDSM4(al[mi][0], al[mi][1], al[mi][2], al[mi][3], a0 + SPLANE_B);
            }
#pragma unroll
            for (int ni = 0; ni < 4; ni++) {
                uint32_t b0 = st + 2*SPLANE_B + (uint32_t)((n0w + ni*16 + brow)*RS + ks*32 + bkb);
                unsigned bhv[4], blv[4];
                LDSM4(bhv[0], bhv[1], bhv[2], bhv[3], b0);
                LDSM4(blv[0], blv[1], blv[2], blv[3], b0 + SPLANE_B);
#pragma unroll
                for (int mi = 0; mi < 2; mi++)
#pragma unroll
                    for (int j2 = 0; j2 < 2; j2++) {
                        int nj = ni*2 + j2;
                        MMA_BF16(acc[mi][nj], ah[mi], &bhv[j2*2]);
                        MMA_BF16(acc[mi][nj], ah[mi], &blv[j2*2]);
                        MMA_BF16(acc[mi][nj], al[mi], &bhv[j2*2]);
                    }
            }
        }
        __syncthreads();
        if (c + 2 < NCHS)
            prefetch_smat(c+2, c & 1, sb, tid, Ahi, Alo, Bhi, Blo);
    }

    float* Sp = g_S + (size_t)bh*Dc*Dc;
    int g = lane >> 2, q = lane & 3;
#pragma unroll
    for (int nj = 0; nj < 8; nj++) {
        int l = n0w + nj*8 + q*2;
#pragma unroll
        for (int mi = 0; mi < 2; mi++) {
            int k0 = m0w + mi*16 + g;
            atomicAdd(&Sp[k0*Dc + l],       acc[mi][nj][0]);
            atomicAdd(&Sp[k0*Dc + l + 1],   acc[mi][nj][1]);
            atomicAdd(&Sp[(k0+8)*Dc + l],   acc[mi][nj][2]);
            atomicAdd(&Sp[(k0+8)*Dc + l+1], acc[mi][nj][3]);
        }
    }
}

// ---------------- stage 3c: normalized correlation ----------------
__global__ void k_corr() {
    int c = blockIdx.x*256 + threadIdx.x;
    int bh = blockIdx.y;
    if (c >= DCORR) return;
    float disc = 65025.0f - 8.0f*(float)c;
    int k = (int)((255.0f - sqrtf(disc))*0.5f);
    if (k < 0) k = 0;
    if (k > 126) k = 126;
    while (k > 0 && k*(255-k)/2 > c) k--;
    while ((k+1)*(254-k)/2 <= c) k++;
    int l = k + 1 + (c - k*(255-k)/2);
    float muk = g_muk[bh*Dc + k], sdk = g_sdk[bh*Dc + k];
    float muv = g_muv[bh*Dc + l], sdv = g_sdv[bh*Dc + l];
    float S = g_S[(size_t)bh*Dc*Dc + k*Dc + l];
    g_corr[(size_t)bh*DCORR + c] = (S - (float)Tc*muk*muv) / ((float)Tc*sdk*sdv);
}

// ---------------- stage 4: outs += corr . Wproj ----------------
__global__ __launch_bounds__(256) void k_proj(const float* __restrict__ Wproj) {
    __shared__ float sc[8][128];
    int tid = threadIdx.x;
    int h = blockIdx.y;
    int cs = blockIdx.z;
    int el = tid & 31;
    int b = tid >> 5;
    int e = blockIdx.x*32 + el;
    int lrow = tid >> 5;
    int lc = (tid & 31)*4;
    int start = cs*2032, end = start + 2032;
    const float* wrow = Wproj + ((size_t)h*Ec + e)*DCORR;
    float acc = 0.f;
    for (int c0 = start; c0 < end; c0 += 128) {
        int lim = end - c0; if (lim > 128) lim = 128;
        float4 cv = make_float4(0.f,0.f,0.f,0.f);
        if (lc < lim) cv = *(const float4*)(g_corr + ((size_t)lrow*Hc + h)*DCORR + c0 + lc);
        *(float4*)&sc[lrow][lc] = cv;
        __syncthreads();
#pragma unroll 8
        for (int j = 0; j < lim; j += 4) {
            float4 wv = *(const float4*)(wrow + c0 + j);
            float4 sv = *(const float4*)&sc[b][j];
            acc += wv.x*sv.x + wv.y*sv.y + wv.z*sv.z + wv.w*sv.w;
        }
        __syncthreads();
    }
    atomicAdd(&g_outs[b*(Hc*Ec) + h*Ec + e], acc);
}

// ---------------- stage 5: final linears + mix ----------------
__global__ __launch_bounds__(256) void k_final(
    const float* __restrict__ WT, const float* __restrict__ bT,
    const float* __restrict__ Wp, const float* __restrict__ bp,
    float* __restrict__ out) {
    __shared__ float so1[Hc*Dc];
    __shared__ float sout[Hc*Ec];
    __shared__ float sred[256];
    int b = blockIdx.x, ec = blockIdx.y;
    int tid = threadIdx.x;
    for (int j = tid; j < Hc*Dc; j += 256) so1[j]  = g_o1[b*Hc*Dc + j];
    for (int j = tid; j < Hc*Ec; j += 256) sout[j] = g_outs[b*Hc*Ec + j];
    __syncthreads();
    int e_l = tid >> 3, js = tid & 7;
    int e = ec*32 + e_l;
    float a = 0.f;
    const float* wt = WT + (size_t)e*(Hc*Dc) + js*128;
    const float* s1p = so1 + js*128;
#pragma unroll 4
    for (int j = 0; j < 128; j += 4) {
        float4 wv = *(const float4*)(wt + j);
        float4 sv = *(const float4*)(s1p + j);
        a += wv.x*sv.x + wv.y*sv.y + wv.z*sv.z + wv.w*sv.w;
    }
    const float* wp = Wp + (size_t)e*(Hc*Ec) + js*256;
    const float* s2p = sout + js*256;
#pragma unroll 4
    for (int j = 0; j < 256; j += 4) {
        float4 wv = *(const float4*)(wp + j);
        float4 sv = *(const float4*)(s2p + j);
        a += wv.x*sv.x + wv.y*sv.y + wv.z*sv.z + wv.w*sv.w;
    }
    if (js == 0) a += bT[e] + bp[e];
    sred[tid] = a;
    __syncthreads();
    if (tid < 32) {
        float s = 0.f;
#pragma unroll
        for (int k = 0; k < 8; k++) s += sred[tid*8 + k];
        out[b*Ec + ec*32 + tid] = 0.5f*s;
    }
}

// ---------------- launch ----------------
extern "C" void kernel_launch(void* const* d_in, const int* in_sizes, int n_in,
                              void* d_out, int out_size) {
    const float* x     = (const float*)d_in[0];
    const float* wk    = (const float*)d_in[1];
    const float* wv    = (const float*)d_in[2];
    const float* q     = (const float*)d_in[3];
    const float* Wk    = (const float*)d_in[4];
    const float* bk    = (const float*)d_in[5];
    const float* Wv    = (const float*)d_in[6];
    const float* bv    = (const float*)d_in[7];
    const float* Wproj = (const float*)d_in[8];
    const float* bproj = (const float*)d_in[9];
    const float* WT    = (const float*)d_in[10];
    const float* bT    = (const float*)d_in[11];
    const float* Wp    = (const float*)d_in[12];
    const float* bp    = (const float*)d_in[13];
    float* out = (float*)d_out;

    cudaFuncSetAttribute(k_gemm, cudaFuncAttributeMaxDynamicSharedMemorySize, GSMEM);
    cudaFuncSetAttribute(k_smat, cudaFuncAttributeMaxDynamicSharedMemorySize, SSMEM);

    k_init<<<1056, 256>>>(wk, wv);
    k_raw<<<dim3(16, Fc/16, Bc), dim3(16, 8)>>>(x);
    k_wconv<<<dim3((Hc*Dc*Fc)/256, 2), 256>>>(Wk, Wv);
    k_gemm<<<dim3(8, Bc*Hc, 4), 256, GSMEM>>>(bk, bv);   // 4th launch -> ncu target
    k_statfin<<<65, 256>>>(bproj);
    k_attn<<<Bc*Hc, 256>>>(q);
    k_smat<<<dim3(2, Bc*Hc), 256, SSMEM>>>();
    k_corr<<<dim3((DCORR+255)/256, Bc*Hc), 256>>>();
    k_proj<<<dim3(Ec/32, Hc, 4), 256>>>(Wproj);
    k_final<<<dim3(Bc, Ec/32), 256>>>(WT, bT, Wp, bp, out);
}

// round 12
// speedup vs baseline: 1.1348x; 1.1348x over previous
#include <cuda_runtime.h>
#include <cuda_bf16.h>
#include <math.h>
#include <stdint.h>

// Problem constants
#define Bc 8
#define Hc 8
#define Fc 768
#define Dc 128
#define Ec 256
#define Lc 13
#define Tc 1000
#define DCORR 8128
#define TP 1024                 // padded T
#define DT (128*TP)             // plane size per (kv,bh)

// ---------------- device scratch ----------------
__device__ float g_kw[Hc*Lc];
__device__ float g_vw[Hc*Lc];
__device__ __nv_bfloat16 g_ahi[(size_t)2*Bc*Hc*Tc*Fc];   // raw activations [kv][bh][t][f]
__device__ __nv_bfloat16 g_alo[(size_t)2*Bc*Hc*Tc*Fc];
__device__ __nv_bfloat16 g_whi[(size_t)2*Hc*Dc*Fc];      // weights [kv][h][d][f]
__device__ __nv_bfloat16 g_wlo[(size_t)2*Hc*Dc*Fc];
__device__ __nv_bfloat16 g_chi[(size_t)2*Bc*Hc*DT];      // GEMM out planes [kv][bh][d][t]
__device__ __nv_bfloat16 g_clo[(size_t)2*Bc*Hc*DT];
__device__ float g_s1[2*Bc*Hc*Dc];
__device__ float g_s2[2*Bc*Hc*Dc];
__device__ float g_muk[Bc*Hc*Dc];
__device__ float g_sdk[Bc*Hc*Dc];
__device__ float g_muv[Bc*Hc*Dc];
__device__ float g_sdv[Bc*Hc*Dc];
__device__ float g_o1[Bc*Hc*Dc];
__device__ float g_S[(size_t)Bc*Hc*Dc*Dc];
__device__ float g_corr[(size_t)Bc*Hc*DCORR];
__device__ float g_outs[Bc*Hc*Ec];

__device__ __forceinline__ uint32_t smem_u32(const void* p) {
    uint32_t a;
    asm("{ .reg .u64 t; cvta.to.shared.u64 t, %1; cvt.u32.u64 %0, t; }" : "=r"(a) : "l"(p));
    return a;
}
#define CP_COMMIT()  asm volatile("cp.async.commit_group;" ::: "memory")
#define CP_WAIT(n)   asm volatile("cp.async.wait_group %0;" :: "n"(n) : "memory")
#define LDSM4(r0, r1, r2, r3, a) \
    asm volatile("ldmatrix.sync.aligned.m8n8.x4.shared.b16 {%0,%1,%2,%3}, [%4];" \
        : "=r"(r0), "=r"(r1), "=r"(r2), "=r"(r3) : "r"(a))
#define MMA_BF16(d, a, b) asm volatile( \
    "mma.sync.aligned.m16n8k16.row.col.f32.bf16.bf16.f32 " \
    "{%0,%1,%2,%3},{%4,%5,%6,%7},{%8,%9},{%0,%1,%2,%3};\n" \
    : "+f"((d)[0]), "+f"((d)[1]), "+f"((d)[2]), "+f"((d)[3]) \
    : "r"((a)[0]), "r"((a)[1]), "r"((a)[2]), "r"((a)[3]), "r"((b)[0]), "r"((b)[1]))

// hi+lo bf16 reconstruction of 4 packed values
__device__ __forceinline__ float4 un4(uint2 h, uint2 l) {
    float4 r;
    r.x = __int_as_float(h.x << 16)        + __int_as_float(l.x << 16);
    r.y = __int_as_float(h.x & 0xffff0000u) + __int_as_float(l.x & 0xffff0000u);
    r.z = __int_as_float(h.y << 16)        + __int_as_float(l.y << 16);
    r.w = __int_as_float(h.y & 0xffff0000u) + __int_as_float(l.y & 0xffff0000u);
    return r;
}

// ---------------- stage 0: init (zero accumulators + softmax weights) ----------------
__global__ void k_init(const float* __restrict__ wk, const float* __restrict__ wv) {
    int i = blockIdx.x*blockDim.x + threadIdx.x;
    float4 z = make_float4(0.f,0.f,0.f,0.f);
    if (i < 262144) ((float4*)g_S)[i] = z;
    else {
        int j = i - 262144;
        if (j < 4096) ((float4*)g_s1)[j] = z;
        else ((float4*)g_s2)[j - 4096] = z;
    }
    if (blockIdx.x == 0 && threadIdx.x < 2*Hc) {
        int tid = threadIdx.x;
        int h = tid % Hc;
        const float* src = (tid < Hc ? wk : wv) + h*Lc;
        float* dst = (tid < Hc ? g_kw : g_vw) + h*Lc;
        float m = -1e30f;
        for (int l = 0; l < Lc; l++) m = fmaxf(m, src[l]);
        float e[Lc]; float s = 0.f;
        for (int l = 0; l < Lc; l++) { e[l] = expf(src[l]-m); s += e[l]; }
        float inv = 1.f/s;
        for (int l = 0; l < Lc; l++) dst[l] = e[l]*inv;
    }
}

// ---------------- pack W to bf16 hi/lo ----------------
__global__ void k_wconv(const float* __restrict__ Wk, const float* __restrict__ Wv) {
    size_t i = (size_t)blockIdx.x*256 + threadIdx.x;
    const float* W = blockIdx.y ? Wv : Wk;
    float v = W[i];
    __nv_bfloat16 h16 = __float2bfloat16(v);
    __nv_bfloat16 l16 = __float2bfloat16(v - __bfloat162float(h16));
    size_t o = (size_t)blockIdx.y*(Hc*Dc*Fc) + i;
    g_whi[o] = h16;
    g_wlo[o] = l16;
}

// ---------------- stage 1: L-contraction -> bf16 hi/lo [t][f] ----------------
__global__ __launch_bounds__(128) void k_raw(const float* __restrict__ x) {
    __shared__ float2 skv[Hc*Lc];
    __shared__ float xs[2][16][212];
    __shared__ __align__(8) unsigned s_ohi[2][Hc][16][10];
    __shared__ __align__(8) unsigned s_olo[2][Hc][16][10];
    int tx = threadIdx.x;
    int ty = threadIdx.y;
    int tid = ty*16 + tx;
    if (tid < Hc*Lc) skv[tid] = make_float2(g_kw[tid], g_vw[tid]);

    int tbase = blockIdx.x*64;
    int f0 = blockIdx.y*16;
    int b  = blockIdx.z;
    const float* xb = x + (size_t)(b*Fc + f0)*Tc*13;

    auto stage_x = [&](int buf, int st0) {
        int n = Tc - st0;
        int maxf4 = (n >= 16) ? 52 : (n > 0 ? ((n*13) >> 2) : 0);
#pragma unroll
        for (int it = 0; it < 7; it++) {
            int idx = tid + it*128;
            if (idx < 832) {
                int row = idx / 52, col = idx % 52;
                unsigned sz = (col < maxf4) ? 16u : 0u;
                int scol = (col < maxf4) ? col : 0;
                uint32_t dst = smem_u32(&xs[buf][row][col*4]);
                const float* src = xb + (size_t)row*(Tc*13) + st0*13 + scol*4;
                asm volatile("cp.async.cg.shared.global [%0], [%1], 16, %2;"
                             :: "r"(dst), "l"(src), "r"(sz));
            }
        }
        CP_COMMIT();
    };

    stage_x(0, tbase);

#pragma unroll 1
    for (int s = 0; s < 4; s++) {
        int st0 = tbase + s*16;
        if (s < 3) { stage_x((s+1) & 1, st0 + 16); CP_WAIT(1); }
        else CP_WAIT(0);
        __syncthreads();

        int buf = s & 1;
        float xv0[Lc], xv1[Lc];
#pragma unroll
        for (int l = 0; l < Lc; l++) {
            xv0[l] = xs[buf][ty*2][tx*13 + l];
            xv1[l] = xs[buf][ty*2 + 1][tx*13 + l];
        }

#pragma unroll
        for (int h = 0; h < Hc; h++) {
            float k0 = 0.f, v0 = 0.f, k1 = 0.f, v1 = 0.f;
#pragma unroll
            for (int l = 0; l < Lc; l++) {
                float2 w = skv[h*Lc + l];
                k0 += xv0[l]*w.x; v0 += xv0[l]*w.y;
                k1 += xv1[l]*w.x; v1 += xv1[l]*w.y;
            }
            {
                unsigned b0 = __float_as_uint(k0), b1 = __float_as_uint(k1);
                unsigned hiw = __byte_perm(b0, b1, 0x7632);
                float d0 = k0 - __uint_as_float(b0 & 0xffff0000u);
                float d1 = k1 - __uint_as_float(b1 & 0xffff0000u);
                unsigned low;
                asm("cvt.rn.bf16x2.f32 %0, %1, %2;" : "=r"(low) : "f"(d1), "f"(d0));
                s_ohi[0][h][tx][ty] = hiw;
                s_olo[0][h][tx][ty] = low;
            }
            {
                unsigned b0 = __float_as_uint(v0), b1 = __float_as_uint(v1);
                unsigned hiw = __byte_perm(b0, b1, 0x7632);
                float d0 = v0 - __uint_as_float(b0 & 0xffff0000u);
                float d1 = v1 - __uint_as_float(b1 & 0xffff0000u);
                unsigned low;
                asm("cvt.rn.bf16x2.f32 %0, %1, %2;" : "=r"(low) : "f"(d1), "f"(d0));
                s_ohi[1][h][tx][ty] = hiw;
                s_olo[1][h][tx][ty] = low;
            }
        }
        __syncthreads();

        int w = tid >> 5, lane = tid & 31;
        int f4 = lane & 3;
        int tq = lane >> 2;
#pragma unroll
        for (int it = 0; it < 4; it++) {
            int job = w*4 + it;
            int kv = job >> 3;
            int h = job & 7;
            size_t rowbase = ((size_t)(kv*Bc + b)*Hc + h)*Tc;
#pragma unroll
            for (int ti = 0; ti < 2; ti++) {
                int tl = ti*8 + tq;
                int tt = st0 + tl;
                if (tt < Tc) {
                    size_t off = (rowbase + tt)*Fc + f0 + f4*4;
                    *(uint2*)(g_ahi + off) = *(uint2*)&s_ohi[kv][h][tl][f4*2];
                    *(uint2*)(g_alo + off) = *(uint2*)&s_olo[kv][h][tl][f4*2];
                }
            }
        }
        __syncthreads();
    }
}

// ---------------- stage 2: mma.sync GEMM (R9 config: 128x128, 2-stage, 2 CTA/SM) ----------------
#define RS 80
#define PLANE_B (128*RS)
#define STAGE_B (4*PLANE_B)
#define NSTAGE 2
#define GSMEM (NSTAGE*STAGE_B)   // 81920
#define NCH (Fc/32)

__device__ __forceinline__ void prefetch_chunk(
    int c, int stage, uint32_t sb, int t0, int tid,
    const __nv_bfloat16* __restrict__ Ahi, const __nv_bfloat16* __restrict__ Alo,
    const __nv_bfloat16* __restrict__ Bhi, const __nv_bfloat16* __restrict__ Blo) {
    int kc = c*32;
    uint32_t stb = sb + stage*STAGE_B;
#pragma unroll
    for (int it = 0; it < 8; it++) {
        int idx = tid + it*256;
        int plane = idx >> 9;
        int row = (idx >> 2) & 127;
        int seg = idx & 3;
        uint32_t dst = stb + plane*PLANE_B + row*RS + seg*16;
        const __nv_bfloat16* src;
        unsigned sz = 16;
        if (plane < 2) {
            int t = t0 + row;
            if (t >= Tc) { t = 0; sz = 0; }
            src = (plane ? Alo : Ahi) + (size_t)t*Fc + kc + seg*8;
        } else {
            src = (plane == 2 ? Bhi : Blo) + (size_t)row*Fc + kc + seg*8;
        }
        asm volatile("cp.async.cg.shared.global [%0], [%1], 16, %2;"
                     :: "r"(dst), "l"(src), "r"(sz));
    }
    CP_COMMIT();
}

__global__ __launch_bounds__(256, 2) void k_gemm(
    const float* __restrict__ bk, const float* __restrict__ bv) {
    extern __shared__ __align__(1024) char dynsmem[];
    uint32_t sb = smem_u32(dynsmem);

    int tid = threadIdx.x;
    int warp = tid >> 5, lane = tid & 31;
    int bh = blockIdx.y;
    int h = bh & 7;
    int kv = blockIdx.z;
    int t0 = blockIdx.x*128;

    const __nv_bfloat16* Ahi = g_ahi + (size_t)(kv*Bc*Hc + bh)*Tc*Fc;
    const __nv_bfloat16* Alo = g_alo + (size_t)(kv*Bc*Hc + bh)*Tc*Fc;
    const __nv_bfloat16* Bhi = g_whi + (size_t)(kv*Hc + h)*Dc*Fc;
    const __nv_bfloat16* Blo = g_wlo + (size_t)(kv*Hc + h)*Dc*Fc;
    const float* bias = (kv ? bv : bk) + h*Dc;

    int m0w = (warp >> 1)*32;
    int n0w = (warp & 1)*64;
    int arow = (lane & 7) + ((lane >> 3) & 1)*8;
    int akb  = ((lane >> 4) & 1)*16;
    int brow = (lane & 7) + ((lane >> 4) & 1)*8;
    int bkb  = ((lane >> 3) & 1)*16;

    float acc[2][8][4];
#pragma unroll
    for (int i = 0; i < 2; i++)
#pragma unroll
        for (int j = 0; j < 8; j++)
#pragma unroll
            for (int r = 0; r < 4; r++) acc[i][j][r] = 0.f;

    prefetch_chunk(0, 0, sb, t0, tid, Ahi, Alo, Bhi, Blo);
    prefetch_chunk(1, 1, sb, t0, tid, Ahi, Alo, Bhi, Blo);

#pragma unroll 1
    for (int c = 0; c < NCH; c++) {
        if (c < NCH-1) CP_WAIT(1); else CP_WAIT(0);
        __syncthreads();
        uint32_t st = sb + (c & 1)*STAGE_B;
#pragma unroll
        for (int ks = 0; ks < 2; ks++) {
            unsigned ah[2][4], al[2][4];
#pragma unroll
            for (int mi = 0; mi < 2; mi++) {
                uint32_t a0 = st + (uint32_t)((m0w + mi*16 + arow)*RS + ks*32 + akb);
                LDSM4(ah[mi][0], ah[mi][1], ah[mi][2], ah[mi][3], a0);
                LDSM4(al[mi][0], al[mi][1], al[mi][2], al[mi][3], a0 + PLANE_B);
            }
#pragma unroll
            for (int ni = 0; ni < 4; ni++) {
                uint32_t b0 = st + 2*PLANE_B + (uint32_t)((n0w + ni*16 + brow)*RS + ks*32 + bkb);
                unsigned bhv[4], blv[4];
                LDSM4(bhv[0], bhv[1], bhv[2], bhv[3], b0);
                LDSM4(blv[0], blv[1], blv[2], blv[3], b0 + PLANE_B);
#pragma unroll
                for (int mi = 0; mi < 2; mi++)
#pragma unroll
                    for (int j2 = 0; j2 < 2; j2++) {
                        int nj = ni*2 + j2;
                        MMA_BF16(acc[mi][nj], ah[mi], &bhv[j2*2]);
                        MMA_BF16(acc[mi][nj], ah[mi], &blv[j2*2]);
                        MMA_BF16(acc[mi][nj], al[mi], &bhv[j2*2]);
                    }
            }
        }
        __syncthreads();
        if (c + 2 < NCH)
            prefetch_chunk(c+2, c & 1, sb, t0, tid, Ahi, Alo, Bhi, Blo);
    }

    // epilogue: transpose through smem to [d][t], emit bf16 hi/lo planes + stats
    __syncthreads();
    float* Cs = (float*)dynsmem;           // [128 d][132]
    int g = lane >> 2, q = lane & 3;
#pragma unroll
    for (int nj = 0; nj < 8; nj++) {
        int d = n0w + nj*8 + q*2;
        float2 bb = *(const float2*)(bias + d);
#pragma unroll
        for (int mi = 0; mi < 2; mi++) {
            int r = m0w + mi*16 + g;
            Cs[d*132 + r]         = acc[mi][nj][0] + bb.x;
            Cs[(d+1)*132 + r]     = acc[mi][nj][1] + bb.y;
            Cs[d*132 + r + 8]     = acc[mi][nj][2] + bb.x;
            Cs[(d+1)*132 + r + 8] = acc[mi][nj][3] + bb.y;
        }
    }
    __syncthreads();

    __nv_bfloat16* Phi = g_chi + ((size_t)kv*64 + bh)*DT;
    __nv_bfloat16* Plo = g_clo + ((size_t)kv*64 + bh)*DT;
    size_t so = ((size_t)kv*64 + bh)*Dc;
    int tb = t0 + lane*4;
#pragma unroll 1
    for (int rr = 0; rr < 16; rr++) {
        int d = warp*16 + rr;
        float4 v = *(float4*)&Cs[d*132 + lane*4];
        v.x = (tb+0 < Tc) ? v.x : 0.f;
        v.y = (tb+1 < Tc) ? v.y : 0.f;
        v.z = (tb+2 < Tc) ? v.z : 0.f;
        v.w = (tb+3 < Tc) ? v.w : 0.f;
        __nv_bfloat162 h01 = __floats2bfloat162_rn(v.x, v.y);
        __nv_bfloat162 h23 = __floats2bfloat162_rn(v.z, v.w);
        unsigned uh01 = *(unsigned*)&h01, uh23 = *(unsigned*)&h23;
        float f0 = __int_as_float(uh01 << 16);
        float f1 = __int_as_float(uh01 & 0xffff0000u);
        float f2 = __int_as_float(uh23 << 16);
        float f3 = __int_as_float(uh23 & 0xffff0000u);
        __nv_bfloat162 l01 = __floats2bfloat162_rn(v.x - f0, v.y - f1);
        __nv_bfloat162 l23 = __floats2bfloat162_rn(v.z - f2, v.w - f3);
        *(uint2*)(Phi + (size_t)d*TP + tb) = make_uint2(uh01, uh23);
        *(uint2*)(Plo + (size_t)d*TP + tb) = make_uint2(*(unsigned*)&l01, *(unsigned*)&l23);
        float p1 = v.x + v.y + v.z + v.w;
        float p2 = v.x*v.x + v.y*v.y + v.z*v.z + v.w*v.w;
        for (int off = 16; off; off >>= 1) {
            p1 += __shfl_down_sync(~0u, p1, off);
            p2 += __shfl_down_sync(~0u, p2, off);
        }
        if (lane == 0) {
            atomicAdd(&g_s1[so + d], p1);
            atomicAdd(&g_s2[so + d], p2);
        }
    }
}

// ---------------- stats finalize + outs init ----------------
__global__ void k_statfin(const float* __restrict__ bproj) {
    int bid = blockIdx.x;
    int tid = threadIdx.x;
    if (bid < 64) {
        int kv = tid >> 7;
        int d = tid & 127;
        size_t o = ((size_t)kv*64 + bid)*Dc + d;
        float s1 = g_s1[o], s2 = g_s2[o];
        float mu = s1 * (1.f/Tc);
        float var = (s2 - (float)Tc*mu*mu) * (1.f/(Tc-1));
        var = fmaxf(var, 0.f);
        float sd = sqrtf(var) + 1e-9f;
        if (kv == 0) { g_muk[bid*Dc + d] = mu; g_sdk[bid*Dc + d] = sd; }
        else         { g_muv[bid*Dc + d] = mu; g_sdv[bid*Dc + d] = sd; }
    } else {
        for (int i = tid; i < Bc*Hc*Ec; i += 256)
            g_outs[i] = bproj[i & (Hc*Ec - 1)];
    }
}

// ---------------- fused stage 3: attention (blocks 0..63) + S=K^T V (blocks 64..191) ----------------
#define NCHS 16

__device__ __forceinline__ void prefetch_smat(
    int c, int stage, uint32_t sb, int tid,
    const __nv_bfloat16* __restrict__ Ahi, const __nv_bfloat16* __restrict__ Alo,
    const __nv_bfloat16* __restrict__ Bhi, const __nv_bfloat16* __restrict__ Blo) {
    int kc = c*32;
    uint32_t stb = sb + stage*STAGE_B;
#pragma unroll
    for (int it = 0; it < 8; it++) {
        int idx = tid + it*256;
        int plane = idx >> 9;
        int row = (idx >> 2) & 127;
        int seg = idx & 3;
        uint32_t dst = stb + plane*PLANE_B + row*RS + seg*16;
        const __nv_bfloat16* src =
            (plane == 0 ? Ahi : plane == 1 ? Alo : plane == 2 ? Bhi : Blo)
            + (size_t)row*TP + kc + seg*8;
        asm volatile("cp.async.cg.shared.global [%0], [%1], 16;" :: "r"(dst), "l"(src));
    }
    CP_COMMIT();
}

__global__ __launch_bounds__(256, 2) void k_as(const float* __restrict__ q) {
    extern __shared__ __align__(1024) char dynsmem[];
    int tid = threadIdx.x;

    if (blockIdx.x < 64) {
        // ---------- attention branch ----------
        float* s_sc  = (float*)dynsmem;           // TP floats
        float* s_red = s_sc + TP;                 // 256
        float* s_q   = s_red + 256;               // 128
        int bh = blockIdx.x;
        int h = bh & 7;
        const __nv_bfloat16* Khi = g_chi + (size_t)bh*DT;
        const __nv_bfloat16* Klo = g_clo + (size_t)bh*DT;
        const __nv_bfloat16* Vhi = g_chi + (size_t)(64 + bh)*DT;
        const __nv_bfloat16* Vlo = g_clo + (size_t)(64 + bh)*DT;
        if (tid < Dc) s_q[tid] = q[h*Dc + tid];
        __syncthreads();

        if (tid < 250) {
            float a0 = 0.f, a1 = 0.f, a2 = 0.f, a3 = 0.f;
#pragma unroll 4
            for (int d = 0; d < Dc; d++) {
                uint2 ph = *(const uint2*)(Khi + (size_t)d*TP + tid*4);
                uint2 pl = *(const uint2*)(Klo + (size_t)d*TP + tid*4);
                float qd = s_q[d];
                float4 kv4 = un4(ph, pl);
                a0 += qd*kv4.x; a1 += qd*kv4.y; a2 += qd*kv4.z; a3 += qd*kv4.w;
            }
            const float sc = 0.08838834764831845f;
            *(float4*)&s_sc[tid*4] = make_float4(a0*sc, a1*sc, a2*sc, a3*sc);
        }
        if (tid < 24) s_sc[1000 + tid] = 0.f;
        __syncthreads();

        float lm = -1e30f;
        for (int t = tid; t < Tc; t += 256) lm = fmaxf(lm, s_sc[t]);
        s_red[tid] = lm; __syncthreads();
        for (int s = 128; s; s >>= 1) { if (tid < s) s_red[tid] = fmaxf(s_red[tid], s_red[tid+s]); __syncthreads(); }
        float m = s_red[0];
        __syncthreads();
        float ls = 0.f;
        for (int t = tid; t < Tc; t += 256) { float e = expf(s_sc[t]-m); s_sc[t] = e; ls += e; }
        s_red[tid] = ls; __syncthreads();
        for (int s = 128; s; s >>= 1) { if (tid < s) s_red[tid] += s_red[tid+s]; __syncthreads(); }
        float inv = 1.f / s_red[0];
        __syncthreads();

        int w = tid >> 5, lane = tid & 31;
#pragma unroll 1
        for (int rr = 0; rr < 16; rr++) {
            int d = w*16 + rr;
            float acc = 0.f;
#pragma unroll
            for (int cc = 0; cc < 8; cc++) {
                int grp = lane + cc*32;
                uint2 ph = *(const uint2*)(Vhi + (size_t)d*TP + grp*4);
                uint2 pl = *(const uint2*)(Vlo + (size_t)d*TP + grp*4);
                float4 vv = un4(ph, pl);
                float4 aa = *(float4*)&s_sc[grp*4];
                acc += aa.x*vv.x + aa.y*vv.y + aa.z*vv.z + aa.w*vv.w;
            }
            for (int off = 16; off; off >>= 1) acc += __shfl_down_sync(~0u, acc, off);
            if (lane == 0) g_o1[bh*Dc + d] = acc * inv;
        }
        return;
    }

    // ---------- S = K^T V branch ----------
    uint32_t sb = smem_u32(dynsmem);
    int warp = tid >> 5, lane = tid & 31;
    int job = blockIdx.x - 64;       // 0..127
    int bh = job >> 1;
    int seg = job & 1;
    const __nv_bfloat16* Ahi = g_chi + (size_t)bh*DT + seg*512;
    const __nv_bfloat16* Alo = g_clo + (size_t)bh*DT + seg*512;
    const __nv_bfloat16* Bhi = g_chi + (size_t)(64 + bh)*DT + seg*512;
    const __nv_bfloat16* Blo = g_clo + (size_t)(64 + bh)*DT + seg*512;

    int m0w = (warp >> 1)*32;
    int n0w = (warp & 1)*64;
    int arow = (lane & 7) + ((lane >> 3) & 1)*8;
    int akb  = ((lane >> 4) & 1)*16;
    int brow = (lane & 7) + ((lane >> 4) & 1)*8;
    int bkb  = ((lane >> 3) & 1)*16;

    float acc[2][8][4];
#pragma unroll
    for (int i = 0; i < 2; i++)
#pragma unroll
        for (int j = 0; j < 8; j++)
#pragma unroll
            for (int r = 0; r < 4; r++) acc[i][j][r] = 0.f;

    prefetch_smat(0, 0, sb, tid, Ahi, Alo, Bhi, Blo);
    prefetch_smat(1, 1, sb, tid, Ahi, Alo, Bhi, Blo);

#pragma unroll 1
    for (int c = 0; c < NCHS; c++) {
        if (c < NCHS-1) CP_WAIT(1); else CP_WAIT(0);
        __syncthreads();
        uint32_t st = sb + (c & 1)*STAGE_B;
#pragma unroll
        for (int ks = 0; ks < 2; ks++) {
            unsigned ah[2][4], al[2][4];
#pragma unroll
            for (int mi = 0; mi < 2; mi++) {
                uint32_t a0 = st + (uint32_t)((m0w + mi*16 + arow)*RS + ks*32 + akb);
                LDSM4(ah[mi][0], ah[mi][1], ah[mi][2], ah[mi][3], a0);
                LDSM4(al[mi][0], al[mi][1], al[mi][2], al[mi][3], a0 + PLANE_B);
            }
#pragma unroll
            for (int ni = 0; ni < 4; ni++) {
                uint32_t b0 = st + 2*PLANE_B + (uint32_t)((n0w + ni*16 + brow)*RS + ks*32 + bkb);
                unsigned bhv[4], blv[4];
                LDSM4(bhv[0], bhv[1], bhv[2], bhv[3], b0);
                LDSM4(blv[0], blv[1], blv[2], blv[3], b0 + PLANE_B);
#pragma unroll
                for (int mi = 0; mi < 2; mi++)
#pragma unroll
                    for (int j2 = 0; j2 < 2; j2++) {
                        int nj = ni*2 + j2;
                        MMA_BF16(acc[mi][nj], ah[mi], &bhv[j2*2]);
                        MMA_BF16(acc[mi][nj], ah[mi], &blv[j2*2]);
                        MMA_BF16(acc[mi][nj], al[mi], &bhv[j2*2]);
                    }
            }
        }
        __syncthreads();
        if (c + 2 < NCHS)
            prefetch_smat(c+2, c & 1, sb, tid, Ahi, Alo, Bhi, Blo);
    }

    float* Sp = g_S + (size_t)bh*Dc*Dc;
    int g = lane >> 2, q4 = lane & 3;
#pragma unroll
    for (int nj = 0; nj < 8; nj++) {
        int l = n0w + nj*8 + q4*2;
#pragma unroll
        for (int mi = 0; mi < 2; mi++) {
            int k0 = m0w + mi*16 + g;
            atomicAdd(&Sp[k0*Dc + l],       acc[mi][nj][0]);
            atomicAdd(&Sp[k0*Dc + l + 1],   acc[mi][nj][1]);
            atomicAdd(&Sp[(k0+8)*Dc + l],   acc[mi][nj][2]);
            atomicAdd(&Sp[(k0+8)*Dc + l+1], acc[mi][nj][3]);
        }
    }
}

// ---------------- stage 3c: normalized correlation ----------------
__global__ void k_corr() {
    int c = blockIdx.x*256 + threadIdx.x;
    int bh = blockIdx.y;
    if (c >= DCORR) return;
    float disc = 65025.0f - 8.0f*(float)c;
    int k = (int)((255.0f - sqrtf(disc))*0.5f);
    if (k < 0) k = 0;
    if (k > 126) k = 126;
    while (k > 0 && k*(255-k)/2 > c) k--;
    while ((k+1)*(254-k)/2 <= c) k++;
    int l = k + 1 + (c - k*(255-k)/2);
    float muk = g_muk[bh*Dc + k], sdk = g_sdk[bh*Dc + k];
    float muv = g_muv[bh*Dc + l], sdv = g_sdv[bh*Dc + l];
    float S = g_S[(size_t)bh*Dc*Dc + k*Dc + l];
    g_corr[(size_t)bh*DCORR + c] = (S - (float)Tc*muk*muv) / ((float)Tc*sdk*sdv);
}

// ---------------- stage 4: outs += corr . Wproj ----------------
__global__ __launch_bounds__(256) void k_proj(const float* __restrict__ Wproj) {
    __shared__ float sc[8][128];
    int tid = threadIdx.x;
    int h = blockIdx.y;
    int cs = blockIdx.z;
    int el = tid & 31;
    int b = tid >> 5;
    int e = blockIdx.x*32 + el;
    int lrow = tid >> 5;
    int lc = (tid & 31)*4;
    int start = cs*2032, end = start + 2032;
    const float* wrow = Wproj + ((size_t)h*Ec + e)*DCORR;
    float acc = 0.f;
    for (int c0 = start; c0 < end; c0 += 128) {
        int lim = end - c0; if (lim > 128) lim = 128;
        float4 cv = make_float4(0.f,0.f,0.f,0.f);
        if (lc < lim) cv = *(const float4*)(g_corr + ((size_t)lrow*Hc + h)*DCORR + c0 + lc);
        *(float4*)&sc[lrow][lc] = cv;
        __syncthreads();
#pragma unroll 8
        for (int j = 0; j < lim; j += 4) {
            float4 wv = *(const float4*)(wrow + c0 + j);
            float4 sv = *(const float4*)&sc[b][j];
            acc += wv.x*sv.x + wv.y*sv.y + wv.z*sv.z + wv.w*sv.w;
        }
        __syncthreads();
    }
    atomicAdd(&g_outs[b*(Hc*Ec) + h*Ec + e], acc);
}

// ---------------- stage 5: final linears + mix ----------------
__global__ __launch_bounds__(256) void k_final(
    const float* __restrict__ WT, const float* __restrict__ bT,
    const float* __restrict__ Wp, const float* __restrict__ bp,
    float* __restrict__ out) {
    __shared__ float so1[Hc*Dc];
    __shared__ float sout[Hc*Ec];
    __shared__ float sred[256];
    int b = blockIdx.x, ec = blockIdx.y;
    int tid = threadIdx.x;
    for (int j = tid; j < Hc*Dc; j += 256) so1[j]  = g_o1[b*Hc*Dc + j];
    for (int j = tid; j < Hc*Ec; j += 256) sout[j] = g_outs[b*Hc*Ec + j];
    __syncthreads();
    int e_l = tid >> 3, js = tid & 7;
    int e = ec*32 + e_l;
    float a = 0.f;
    const float* wt = WT + (size_t)e*(Hc*Dc) + js*128;
    const float* s1p = so1 + js*128;
#pragma unroll 4
    for (int j = 0; j < 128; j += 4) {
        float4 wv = *(const float4*)(wt + j);
        float4 sv = *(const float4*)(s1p + j);
        a += wv.x*sv.x + wv.y*sv.y + wv.z*sv.z + wv.w*sv.w;
    }
    const float* wp = Wp + (size_t)e*(Hc*Ec) + js*256;
    const float* s2p = sout + js*256;
#pragma unroll 4
    for (int j = 0; j < 256; j += 4) {
        float4 wv = *(const float4*)(wp + j);
        float4 sv = *(const float4*)(s2p + j);
        a += wv.x*sv.x + wv.y*sv.y + wv.z*sv.z + wv.w*sv.w;
    }
    if (js == 0) a += bT[e] + bp[e];
    sred[tid] = a;
    __syncthreads();
    if (tid < 32) {
        float s = 0.f;
#pragma unroll
        for (int k = 0; k < 8; k++) s += sred[tid*8 + k];
        out[b*Ec + ec*32 + tid] = 0.5f*s;
    }
}

// ---------------- launch ----------------
extern "C" void kernel_launch(void* const* d_in, const int* in_sizes, int n_in,
                              void* d_out, int out_size) {
    const float* x     = (const float*)d_in[0];
    const float* wk    = (const float*)d_in[1];
    const float* wv    = (const float*)d_in[2];
    const float* q     = (const float*)d_in[3];
    const float* Wk    = (const float*)d_in[4];
    const float* bk    = (const float*)d_in[5];
    const float* Wv    = (const float*)d_in[6];
    const float* bv    = (const float*)d_in[7];
    const float* Wproj = (const float*)d_in[8];
    const float* bproj = (const float*)d_in[9];
    const float* WT    = (const float*)d_in[10];
    const float* bT    = (const float*)d_in[11];
    const float* Wp    = (const float*)d_in[12];
    const float* bp    = (const float*)d_in[13];
    float* out = (float*)d_out;

    cudaFuncSetAttribute(k_gemm, cudaFuncAttributeMaxDynamicSharedMemorySize, GSMEM);
    cudaFuncSetAttribute(k_as,   cudaFuncAttributeMaxDynamicSharedMemorySize, GSMEM);

    k_init<<<1056, 256>>>(wk, wv);
    k_raw<<<dim3(16, Fc/16, Bc), dim3(16, 8)>>>(x);
    k_wconv<<<dim3((Hc*Dc*Fc)/256, 2), 256>>>(Wk, Wv);
    k_gemm<<<dim3(8, Bc*Hc, 2), 256, GSMEM>>>(bk, bv);   // 4th launch -> ncu target
    k_statfin<<<65, 256>>>(bproj);
    k_as<<<192, 256, GSMEM>>>(q);                        // fused attn + smat
    k_corr<<<dim3((DCORR+255)/256, Bc*Hc), 256>>>();
    k_proj<<<dim3(Ec/32, Hc, 4), 256>>>(Wproj);
    k_final<<<dim3(Bc, Ec/32), 256>>>(WT, bT, Wp, bp, out);
}

// round 13
// speedup vs baseline: 1.1837x; 1.0431x over previous
#include <cuda_runtime.h>
#include <cuda_bf16.h>
#include <math.h>
#include <stdint.h>

// Problem constants
#define Bc 8
#define Hc 8
#define Fc 768
#define Dc 128
#define Ec 256
#define Lc 13
#define Tc 1000
#define DCORR 8128
#define TP 1024                 // padded T
#define DT (128*TP)             // plane size per (kv,bh)

// ---------------- device scratch ----------------
__device__ float g_kw[Hc*Lc];
__device__ float g_vw[Hc*Lc];
__device__ __nv_bfloat16 g_ahi[(size_t)2*Bc*Hc*Tc*Fc];   // raw activations [kv][bh][t][f]
__device__ __nv_bfloat16 g_alo[(size_t)2*Bc*Hc*Tc*Fc];
__device__ __nv_bfloat16 g_whi[(size_t)2*Hc*Dc*Fc];      // weights [kv][h][d][f]
__device__ __nv_bfloat16 g_wlo[(size_t)2*Hc*Dc*Fc];
__device__ __nv_bfloat16 g_chi[(size_t)2*Bc*Hc*DT];      // GEMM out planes [kv][bh][d][t]
__device__ __nv_bfloat16 g_clo[(size_t)2*Bc*Hc*DT];
__device__ float g_s1[2*Bc*Hc*Dc];
__device__ float g_s2[2*Bc*Hc*Dc];
__device__ float g_muk[Bc*Hc*Dc];
__device__ float g_sdk[Bc*Hc*Dc];
__device__ float g_muv[Bc*Hc*Dc];
__device__ float g_sdv[Bc*Hc*Dc];
__device__ float g_o1[Bc*Hc*Dc];
__device__ float g_S[(size_t)Bc*Hc*Dc*Dc];
__device__ float g_corr[(size_t)Bc*Hc*DCORR];
__device__ float g_outs[Bc*Hc*Ec];

__device__ __forceinline__ uint32_t smem_u32(const void* p) {
    uint32_t a;
    asm("{ .reg .u64 t; cvta.to.shared.u64 t, %1; cvt.u32.u64 %0, t; }" : "=r"(a) : "l"(p));
    return a;
}
#define CP_COMMIT()  asm volatile("cp.async.commit_group;" ::: "memory")
#define CP_WAIT(n)   asm volatile("cp.async.wait_group %0;" :: "n"(n) : "memory")
#define LDSM4(r0, r1, r2, r3, a) \
    asm volatile("ldmatrix.sync.aligned.m8n8.x4.shared.b16 {%0,%1,%2,%3}, [%4];" \
        : "=r"(r0), "=r"(r1), "=r"(r2), "=r"(r3) : "r"(a))
#define MMA_BF16(d, a, b) asm volatile( \
    "mma.sync.aligned.m16n8k16.row.col.f32.bf16.bf16.f32 " \
    "{%0,%1,%2,%3},{%4,%5,%6,%7},{%8,%9},{%0,%1,%2,%3};\n" \
    : "+f"((d)[0]), "+f"((d)[1]), "+f"((d)[2]), "+f"((d)[3]) \
    : "r"((a)[0]), "r"((a)[1]), "r"((a)[2]), "r"((a)[3]), "r"((b)[0]), "r"((b)[1]))

// hi+lo bf16 reconstruction of 4 packed values
__device__ __forceinline__ float4 un4(uint2 h, uint2 l) {
    float4 r;
    r.x = __int_as_float(h.x << 16)        + __int_as_float(l.x << 16);
    r.y = __int_as_float(h.x & 0xffff0000u) + __int_as_float(l.x & 0xffff0000u);
    r.z = __int_as_float(h.y << 16)        + __int_as_float(l.y << 16);
    r.w = __int_as_float(h.y & 0xffff0000u) + __int_as_float(l.y & 0xffff0000u);
    return r;
}

// ---------------- stage 0: init (zero accumulators + softmax weights) ----------------
__global__ void k_init(const float* __restrict__ wk, const float* __restrict__ wv) {
    int i = blockIdx.x*blockDim.x + threadIdx.x;
    float4 z = make_float4(0.f,0.f,0.f,0.f);
    if (i < 262144) ((float4*)g_S)[i] = z;
    else {
        int j = i - 262144;
        if (j < 4096) ((float4*)g_s1)[j] = z;
        else ((float4*)g_s2)[j - 4096] = z;
    }
    if (blockIdx.x == 0 && threadIdx.x < 2*Hc) {
        int tid = threadIdx.x;
        int h = tid % Hc;
        const float* src = (tid < Hc ? wk : wv) + h*Lc;
        float* dst = (tid < Hc ? g_kw : g_vw) + h*Lc;
        float m = -1e30f;
        for (int l = 0; l < Lc; l++) m = fmaxf(m, src[l]);
        float e[Lc]; float s = 0.f;
        for (int l = 0; l < Lc; l++) { e[l] = expf(src[l]-m); s += e[l]; }
        float inv = 1.f/s;
        for (int l = 0; l < Lc; l++) dst[l] = e[l]*inv;
    }
}

// ---------------- pack W to bf16 hi/lo ----------------
__global__ void k_wconv(const float* __restrict__ Wk, const float* __restrict__ Wv) {
    size_t i = (size_t)blockIdx.x*256 + threadIdx.x;
    const float* W = blockIdx.y ? Wv : Wk;
    float v = W[i];
    __nv_bfloat16 h16 = __float2bfloat16(v);
    __nv_bfloat16 l16 = __float2bfloat16(v - __bfloat162float(h16));
    size_t o = (size_t)blockIdx.y*(Hc*Dc*Fc) + i;
    g_whi[o] = h16;
    g_wlo[o] = l16;
}

// ---------------- stage 1: L-contraction -> bf16 hi/lo [t][f] ----------------
__global__ __launch_bounds__(128) void k_raw(const float* __restrict__ x) {
    __shared__ float2 skv[Hc*Lc];
    __shared__ float xs[2][16][212];
    __shared__ __align__(8) unsigned s_ohi[2][Hc][16][10];
    __shared__ __align__(8) unsigned s_olo[2][Hc][16][10];
    int tx = threadIdx.x;
    int ty = threadIdx.y;
    int tid = ty*16 + tx;
    if (tid < Hc*Lc) skv[tid] = make_float2(g_kw[tid], g_vw[tid]);

    int tbase = blockIdx.x*64;
    int f0 = blockIdx.y*16;
    int b  = blockIdx.z;
    const float* xb = x + (size_t)(b*Fc + f0)*Tc*13;

    auto stage_x = [&](int buf, int st0) {
        int n = Tc - st0;
        int maxf4 = (n >= 16) ? 52 : (n > 0 ? ((n*13) >> 2) : 0);
#pragma unroll
        for (int it = 0; it < 7; it++) {
            int idx = tid + it*128;
            if (idx < 832) {
                int row = idx / 52, col = idx % 52;
                unsigned sz = (col < maxf4) ? 16u : 0u;
                int scol = (col < maxf4) ? col : 0;
                uint32_t dst = smem_u32(&xs[buf][row][col*4]);
                const float* src = xb + (size_t)row*(Tc*13) + st0*13 + scol*4;
                asm volatile("cp.async.cg.shared.global [%0], [%1], 16, %2;"
                             :: "r"(dst), "l"(src), "r"(sz));
            }
        }
        CP_COMMIT();
    };

    stage_x(0, tbase);

#pragma unroll 1
    for (int s = 0; s < 4; s++) {
        int st0 = tbase + s*16;
        if (s < 3) { stage_x((s+1) & 1, st0 + 16); CP_WAIT(1); }
        else CP_WAIT(0);
        __syncthreads();

        int buf = s & 1;
        float xv0[Lc], xv1[Lc];
#pragma unroll
        for (int l = 0; l < Lc; l++) {
            xv0[l] = xs[buf][ty*2][tx*13 + l];
            xv1[l] = xs[buf][ty*2 + 1][tx*13 + l];
        }

#pragma unroll
        for (int h = 0; h < Hc; h++) {
            float k0 = 0.f, v0 = 0.f, k1 = 0.f, v1 = 0.f;
#pragma unroll
            for (int l = 0; l < Lc; l++) {
                float2 w = skv[h*Lc + l];
                k0 += xv0[l]*w.x; v0 += xv0[l]*w.y;
                k1 += xv1[l]*w.x; v1 += xv1[l]*w.y;
            }
            {
                unsigned b0 = __float_as_uint(k0), b1 = __float_as_uint(k1);
                unsigned hiw = __byte_perm(b0, b1, 0x7632);
                float d0 = k0 - __uint_as_float(b0 & 0xffff0000u);
                float d1 = k1 - __uint_as_float(b1 & 0xffff0000u);
                unsigned low;
                asm("cvt.rn.bf16x2.f32 %0, %1, %2;" : "=r"(low) : "f"(d1), "f"(d0));
                s_ohi[0][h][tx][ty] = hiw;
                s_olo[0][h][tx][ty] = low;
            }
            {
                unsigned b0 = __float_as_uint(v0), b1 = __float_as_uint(v1);
                unsigned hiw = __byte_perm(b0, b1, 0x7632);
                float d0 = v0 - __uint_as_float(b0 & 0xffff0000u);
                float d1 = v1 - __uint_as_float(b1 & 0xffff0000u);
                unsigned low;
                asm("cvt.rn.bf16x2.f32 %0, %1, %2;" : "=r"(low) : "f"(d1), "f"(d0));
                s_ohi[1][h][tx][ty] = hiw;
                s_olo[1][h][tx][ty] = low;
            }
        }
        __syncthreads();

        int w = tid >> 5, lane = tid & 31;
        int f4 = lane & 3;
        int tq = lane >> 2;
#pragma unroll
        for (int it = 0; it < 4; it++) {
            int job = w*4 + it;
            int kv = job >> 3;
            int h = job & 7;
            size_t rowbase = ((size_t)(kv*Bc + b)*Hc + h)*Tc;
#pragma unroll
            for (int ti = 0; ti < 2; ti++) {
                int tl = ti*8 + tq;
                int tt = st0 + tl;
                if (tt < Tc) {
                    size_t off = (rowbase + tt)*Fc + f0 + f4*4;
                    *(uint2*)(g_ahi + off) = *(uint2*)&s_ohi[kv][h][tl][f4*2];
                    *(uint2*)(g_alo + off) = *(uint2*)&s_olo[kv][h][tl][f4*2];
                }
            }
        }
        __syncthreads();
    }
}

// ---------------- stage 2: GEMM 128x128, XOR-swizzled smem, 3-stage, 1 barrier/chunk ----------------
// swizzle: 64B rows; 16B-slot index seg' = seg ^ ((row>>1)&3)  -> conflict-free ldmatrix phases
#define GA_PL 8192               // plane: 128 rows x 64B
#define GSTG (4*GA_PL)           // 32768: Ahi, Alo, Bhi, Blo
#define GSM (3*GSTG)             // 98304 per CTA; 2 CTAs = 192KB
#define NCH (Fc/32)

__device__ __forceinline__ void prefetch_g(
    int c, int stage, uint32_t sb, int t0, int tid,
    const __nv_bfloat16* __restrict__ Ahi, const __nv_bfloat16* __restrict__ Alo,
    const __nv_bfloat16* __restrict__ Bhi, const __nv_bfloat16* __restrict__ Blo) {
    int kc = c*32;
    uint32_t stb = sb + stage*GSTG;
#pragma unroll
    for (int it = 0; it < 8; it++) {
        int idx = tid + it*256;
        int plane = idx >> 9;
        int row = (idx >> 2) & 127;
        int seg = idx & 3;
        uint32_t dst = stb + plane*GA_PL + row*64 + (((seg ^ ((row >> 1) & 3))) << 4);
        const __nv_bfloat16* src;
        unsigned sz = 16;
        if (plane < 2) {
            int t = t0 + row;
            if (t >= Tc) { t = 0; sz = 0; }
            src = (plane ? Alo : Ahi) + (size_t)t*Fc + kc + seg*8;
        } else {
            src = (plane == 2 ? Bhi : Blo) + (size_t)row*Fc + kc + seg*8;
        }
        asm volatile("cp.async.cg.shared.global [%0], [%1], 16, %2;"
                     :: "r"(dst), "l"(src), "r"(sz));
    }
    CP_COMMIT();
}

__global__ __launch_bounds__(256, 2) void k_gemm(
    const float* __restrict__ bk, const float* __restrict__ bv) {
    extern __shared__ __align__(1024) char dynsmem[];
    uint32_t sb = smem_u32(dynsmem);

    int tid = threadIdx.x;
    int warp = tid >> 5, lane = tid & 31;
    int bh = blockIdx.y;
    int h = bh & 7;
    int kv = blockIdx.z;
    int t0 = blockIdx.x*128;

    const __nv_bfloat16* Ahi = g_ahi + (size_t)(kv*Bc*Hc + bh)*Tc*Fc;
    const __nv_bfloat16* Alo = g_alo + (size_t)(kv*Bc*Hc + bh)*Tc*Fc;
    const __nv_bfloat16* Bhi = g_whi + (size_t)(kv*Hc + h)*Dc*Fc;
    const __nv_bfloat16* Blo = g_wlo + (size_t)(kv*Hc + h)*Dc*Fc;
    const float* bias = (kv ? bv : bk) + h*Dc;

    int m0w = (warp >> 1)*32;
    int n0w = (warp & 1)*64;
    int arow = (lane & 7) + ((lane >> 3) & 1)*8;
    int abit = (lane >> 4) & 1;
    int brow = (lane & 7) + ((lane >> 4) & 1)*8;
    int bbit = (lane >> 3) & 1;

    float acc[2][8][4];
#pragma unroll
    for (int i = 0; i < 2; i++)
#pragma unroll
        for (int j = 0; j < 8; j++)
#pragma unroll
            for (int r = 0; r < 4; r++) acc[i][j][r] = 0.f;

    prefetch_g(0, 0, sb, t0, tid, Ahi, Alo, Bhi, Blo);
    prefetch_g(1, 1, sb, t0, tid, Ahi, Alo, Bhi, Blo);

#pragma unroll 1
    for (int c = 0; c < NCH; c++) {
        // oldest pending group (chunk c) completes for this thread...
        if (c < NCH-1) CP_WAIT(1); else CP_WAIT(0);
        // ...and for ALL threads; also proves everyone finished reading stage (c-1)%3
        __syncthreads();
        // refill freed stage (c+2)%3 == (c-1)%3 while computing stage c%3
        if (c + 2 < NCH)
            prefetch_g(c+2, (c+2)%3, sb, t0, tid, Ahi, Alo, Bhi, Blo);

        uint32_t st = sb + (c%3)*GSTG;
#pragma unroll
        for (int ks = 0; ks < 2; ks++) {
            unsigned ah[2][4], al[2][4];
#pragma unroll
            for (int mi = 0; mi < 2; mi++) {
                int rA = m0w + mi*16 + arow;
                uint32_t a0 = st + (uint32_t)(rA*64 + (((ks*2 + abit) ^ ((rA >> 1) & 3)) << 4));
                LDSM4(ah[mi][0], ah[mi][1], ah[mi][2], ah[mi][3], a0);
                LDSM4(al[mi][0], al[mi][1], al[mi][2], al[mi][3], a0 + GA_PL);
            }
#pragma unroll
            for (int ni = 0; ni < 4; ni++) {
                int rB = n0w + ni*16 + brow;
                uint32_t b0 = st + 2*GA_PL + (uint32_t)(rB*64 + (((ks*2 + bbit) ^ ((rB >> 1) & 3)) << 4));
                unsigned bhv[4], blv[4];
                LDSM4(bhv[0], bhv[1], bhv[2], bhv[3], b0);
                LDSM4(blv[0], blv[1], blv[2], blv[3], b0 + GA_PL);
#pragma unroll
                for (int mi = 0; mi < 2; mi++)
#pragma unroll
                    for (int j2 = 0; j2 < 2; j2++) {
                        int nj = ni*2 + j2;
                        MMA_BF16(acc[mi][nj], ah[mi], &bhv[j2*2]);
                        MMA_BF16(acc[mi][nj], ah[mi], &blv[j2*2]);
                        MMA_BF16(acc[mi][nj], al[mi], &bhv[j2*2]);
                    }
            }
        }
    }

    // epilogue: transpose through smem to [d][t], emit bf16 hi/lo planes + stats
    __syncthreads();
    float* Cs = (float*)dynsmem;           // [128 d][132]
    int g = lane >> 2, q = lane & 3;
#pragma unroll
    for (int nj = 0; nj < 8; nj++) {
        int d = n0w + nj*8 + q*2;
        float2 bb = *(const float2*)(bias + d);
#pragma unroll
        for (int mi = 0; mi < 2; mi++) {
            int r = m0w + mi*16 + g;
            Cs[d*132 + r]         = acc[mi][nj][0] + bb.x;
            Cs[(d+1)*132 + r]     = acc[mi][nj][1] + bb.y;
            Cs[d*132 + r + 8]     = acc[mi][nj][2] + bb.x;
            Cs[(d+1)*132 + r + 8] = acc[mi][nj][3] + bb.y;
        }
    }
    __syncthreads();

    __nv_bfloat16* Phi = g_chi + ((size_t)kv*64 + bh)*DT;
    __nv_bfloat16* Plo = g_clo + ((size_t)kv*64 + bh)*DT;
    size_t so = ((size_t)kv*64 + bh)*Dc;
    int tb = t0 + lane*4;
#pragma unroll 1
    for (int rr = 0; rr < 16; rr++) {
        int d = warp*16 + rr;
        float4 v = *(float4*)&Cs[d*132 + lane*4];
        v.x = (tb+0 < Tc) ? v.x : 0.f;
        v.y = (tb+1 < Tc) ? v.y : 0.f;
        v.z = (tb+2 < Tc) ? v.z : 0.f;
        v.w = (tb+3 < Tc) ? v.w : 0.f;
        __nv_bfloat162 h01 = __floats2bfloat162_rn(v.x, v.y);
        __nv_bfloat162 h23 = __floats2bfloat162_rn(v.z, v.w);
        unsigned uh01 = *(unsigned*)&h01, uh23 = *(unsigned*)&h23;
        float f0 = __int_as_float(uh01 << 16);
        float f1 = __int_as_float(uh01 & 0xffff0000u);
        float f2 = __int_as_float(uh23 << 16);
        float f3 = __int_as_float(uh23 & 0xffff0000u);
        __nv_bfloat162 l01 = __floats2bfloat162_rn(v.x - f0, v.y - f1);
        __nv_bfloat162 l23 = __floats2bfloat162_rn(v.z - f2, v.w - f3);
        *(uint2*)(Phi + (size_t)d*TP + tb) = make_uint2(uh01, uh23);
        *(uint2*)(Plo + (size_t)d*TP + tb) = make_uint2(*(unsigned*)&l01, *(unsigned*)&l23);
        float p1 = v.x + v.y + v.z + v.w;
        float p2 = v.x*v.x + v.y*v.y + v.z*v.z + v.w*v.w;
        for (int off = 16; off; off >>= 1) {
            p1 += __shfl_down_sync(~0u, p1, off);
            p2 += __shfl_down_sync(~0u, p2, off);
        }
        if (lane == 0) {
            atomicAdd(&g_s1[so + d], p1);
            atomicAdd(&g_s2[so + d], p2);
        }
    }
}

// ---------------- stats finalize + outs init ----------------
__global__ void k_statfin(const float* __restrict__ bproj) {
    int bid = blockIdx.x;
    int tid = threadIdx.x;
    if (bid < 64) {
        int kv = tid >> 7;
        int d = tid & 127;
        size_t o = ((size_t)kv*64 + bid)*Dc + d;
        float s1 = g_s1[o], s2 = g_s2[o];
        float mu = s1 * (1.f/Tc);
        float var = (s2 - (float)Tc*mu*mu) * (1.f/(Tc-1));
        var = fmaxf(var, 0.f);
        float sd = sqrtf(var) + 1e-9f;
        if (kv == 0) { g_muk[bid*Dc + d] = mu; g_sdk[bid*Dc + d] = sd; }
        else         { g_muv[bid*Dc + d] = mu; g_sdv[bid*Dc + d] = sd; }
    } else {
        for (int i = tid; i < Bc*Hc*Ec; i += 256)
            g_outs[i] = bproj[i & (Hc*Ec - 1)];
    }
}

// ---------------- fused stage 3: attention (blocks 0..63) + S=K^T V (blocks 64..191) ----------------
#define RS 80
#define PLANE_B (128*RS)
#define STAGE_B (4*PLANE_B)
#define SSM (2*STAGE_B)          // 81920
#define NCHS 16

__device__ __forceinline__ void prefetch_smat(
    int c, int stage, uint32_t sb, int tid,
    const __nv_bfloat16* __restrict__ Ahi, const __nv_bfloat16* __restrict__ Alo,
    const __nv_bfloat16* __restrict__ Bhi, const __nv_bfloat16* __restrict__ Blo) {
    int kc = c*32;
    uint32_t stb = sb + stage*STAGE_B;
#pragma unroll
    for (int it = 0; it < 8; it++) {
        int idx = tid + it*256;
        int plane = idx >> 9;
        int row = (idx >> 2) & 127;
        int seg = idx & 3;
        uint32_t dst = stb + plane*PLANE_B + row*RS + seg*16;
        const __nv_bfloat16* src =
            (plane == 0 ? Ahi : plane == 1 ? Alo : plane == 2 ? Bhi : Blo)
            + (size_t)row*TP + kc + seg*8;
        asm volatile("cp.async.cg.shared.global [%0], [%1], 16;" :: "r"(dst), "l"(src));
    }
    CP_COMMIT();
}

__global__ __launch_bounds__(256, 2) void k_as(const float* __restrict__ q) {
    extern __shared__ __align__(1024) char dynsmem[];
    int tid = threadIdx.x;

    if (blockIdx.x < 64) {
        // ---------- attention branch ----------
        float* s_sc  = (float*)dynsmem;           // TP floats
        float* s_red = s_sc + TP;                 // 256
        float* s_q   = s_red + 256;               // 128
        int bh = blockIdx.x;
        int h = bh & 7;
        const __nv_bfloat16* Khi = g_chi + (size_t)bh*DT;
        const __nv_bfloat16* Klo = g_clo + (size_t)bh*DT;
        const __nv_bfloat16* Vhi = g_chi + (size_t)(64 + bh)*DT;
        const __nv_bfloat16* Vlo = g_clo + (size_t)(64 + bh)*DT;
        if (tid < Dc) s_q[tid] = q[h*Dc + tid];
        __syncthreads();

        if (tid < 250) {
            float a0 = 0.f, a1 = 0.f, a2 = 0.f, a3 = 0.f;
#pragma unroll 4
            for (int d = 0; d < Dc; d++) {
                uint2 ph = *(const uint2*)(Khi + (size_t)d*TP + tid*4);
                uint2 pl = *(const uint2*)(Klo + (size_t)d*TP + tid*4);
                float qd = s_q[d];
                float4 kv4 = un4(ph, pl);
                a0 += qd*kv4.x; a1 += qd*kv4.y; a2 += qd*kv4.z; a3 += qd*kv4.w;
            }
            const float sc = 0.08838834764831845f;
            *(float4*)&s_sc[tid*4] = make_float4(a0*sc, a1*sc, a2*sc, a3*sc);
        }
        if (tid < 24) s_sc[1000 + tid] = 0.f;
        __syncthreads();

        float lm = -1e30f;
        for (int t = tid; t < Tc; t += 256) lm = fmaxf(lm, s_sc[t]);
        s_red[tid] = lm; __syncthreads();
        for (int s = 128; s; s >>= 1) { if (tid < s) s_red[tid] = fmaxf(s_red[tid], s_red[tid+s]); __syncthreads(); }
        float m = s_red[0];
        __syncthreads();
        float ls = 0.f;
        for (int t = tid; t < Tc; t += 256) { float e = expf(s_sc[t]-m); s_sc[t] = e; ls += e; }
        s_red[tid] = ls; __syncthreads();
        for (int s = 128; s; s >>= 1) { if (tid < s) s_red[tid] += s_red[tid+s]; __syncthreads(); }
        float inv = 1.f / s_red[0];
        __syncthreads();

        int w = tid >> 5, lane = tid & 31;
#pragma unroll 1
        for (int rr = 0; rr < 16; rr++) {
            int d = w*16 + rr;
            float acc = 0.f;
#pragma unroll
            for (int cc = 0; cc < 8; cc++) {
                int grp = lane + cc*32;
                uint2 ph = *(const uint2*)(Vhi + (size_t)d*TP + grp*4);
                uint2 pl = *(const uint2*)(Vlo + (size_t)d*TP + grp*4);
                float4 vv = un4(ph, pl);
                float4 aa = *(float4*)&s_sc[grp*4];
                acc += aa.x*vv.x + aa.y*vv.y + aa.z*vv.z + aa.w*vv.w;
            }
            for (int off = 16; off; off >>= 1) acc += __shfl_down_sync(~0u, acc, off);
            if (lane == 0) g_o1[bh*Dc + d] = acc * inv;
        }
        return;
    }

    // ---------- S = K^T V branch ----------
    uint32_t sb = smem_u32(dynsmem);
    int warp = tid >> 5, lane = tid & 31;
    int job = blockIdx.x - 64;       // 0..127
    int bh = job >> 1;
    int seg = job & 1;
    const __nv_bfloat16* Ahi = g_chi + (size_t)bh*DT + seg*512;
    const __nv_bfloat16* Alo = g_clo + (size_t)bh*DT + seg*512;
    const __nv_bfloat16* Bhi = g_chi + (size_t)(64 + bh)*DT + seg*512;
    const __nv_bfloat16* Blo = g_clo + (size_t)(64 + bh)*DT + seg*512;

    int m0w = (warp >> 1)*32;
    int n0w = (warp & 1)*64;
    int arow = (lane & 7) + ((lane >> 3) & 1)*8;
    int akb  = ((lane >> 4) & 1)*16;
    int brow = (lane & 7) + ((lane >> 4) & 1)*8;
    int bkb  = ((lane >> 3) & 1)*16;

    float acc[2][8][4];
#pragma unroll
    for (int i = 0; i < 2; i++)
#pragma unroll
        for (int j = 0; j < 8; j++)
#pragma unroll
            for (int r = 0; r < 4; r++) acc[i][j][r] = 0.f;

    prefetch_smat(0, 0, sb, tid, Ahi, Alo, Bhi, Blo);
    prefetch_smat(1, 1, sb, tid, Ahi, Alo, Bhi, Blo);

#pragma unroll 1
    for (int c = 0; c < NCHS; c++) {
        if (c < NCHS-1) CP_WAIT(1); else CP_WAIT(0);
        __syncthreads();
        uint32_t st = sb + (c & 1)*STAGE_B;
#pragma unroll
        for (int ks = 0; ks < 2; ks++) {
            unsigned ah[2][4], al[2][4];
#pragma unroll
            for (int mi = 0; mi < 2; mi++) {
                uint32_t a0 = st + (uint32_t)((m0w + mi*16 + arow)*RS + ks*32 + akb);
                LDSM4(ah[mi][0], ah[mi][1], ah[mi][2], ah[mi][3], a0);
                LDSM4(al[mi][0], al[mi][1], al[mi][2], al[mi][3], a0 + PLANE_B);
            }
#pragma unroll
            for (int ni = 0; ni < 4; ni++) {
                uint32_t b0 = st + 2*PLANE_B + (uint32_t)((n0w + ni*16 + brow)*RS + ks*32 + bkb);
                unsigned bhv[4], blv[4];
                LDSM4(bhv[0], bhv[1], bhv[2], bhv[3], b0);
                LDSM4(blv[0], blv[1], blv[2], blv[3], b0 + PLANE_B);
#pragma unroll
                for (int mi = 0; mi < 2; mi++)
#pragma unroll
                    for (int j2 = 0; j2 < 2; j2++) {
                        int nj = ni*2 + j2;
                        MMA_BF16(acc[mi][nj], ah[mi], &bhv[j2*2]);
                        MMA_BF16(acc[mi][nj], ah[mi], &blv[j2*2]);
                        MMA_BF16(acc[mi][nj], al[mi], &bhv[j2*2]);
                    }
            }
        }
        __syncthreads();
        if (c + 2 < NCHS)
            prefetch_smat(c+2, c & 1, sb, tid, Ahi, Alo, Bhi, Blo);
    }

    float* Sp = g_S + (size_t)bh*Dc*Dc;
    int g = lane >> 2, q4 = lane & 3;
#pragma unroll
    for (int nj = 0; nj < 8; nj++) {
        int l = n0w + nj*8 + q4*2;
#pragma unroll
        for (int mi = 0; mi < 2; mi++) {
            int k0 = m0w + mi*16 + g;
            atomicAdd(&Sp[k0*Dc + l],       acc[mi][nj][0]);
            atomicAdd(&Sp[k0*Dc + l + 1],   acc[mi][nj][1]);
            atomicAdd(&Sp[(k0+8)*Dc + l],   acc[mi][nj][2]);
            atomicAdd(&Sp[(k0+8)*Dc + l+1], acc[mi][nj][3]);
        }
    }
}

// ---------------- stage 3c: normalized correlation ----------------
__global__ void k_corr() {
    int c = blockIdx.x*256 + threadIdx.x;
    int bh = blockIdx.y;
    if (c >= DCORR) return;
    float disc = 65025.0f - 8.0f*(float)c;
    int k = (int)((255.0f - sqrtf(disc))*0.5f);
    if (k < 0) k = 0;
    if (k > 126) k = 126;
    while (k > 0 && k*(255-k)/2 > c) k--;
    while ((k+1)*(254-k)/2 <= c) k++;
    int l = k + 1 + (c - k*(255-k)/2);
    float muk = g_muk[bh*Dc + k], sdk = g_sdk[bh*Dc + k];
    float muv = g_muv[bh*Dc + l], sdv = g_sdv[bh*Dc + l];
    float S = g_S[(size_t)bh*Dc*Dc + k*Dc + l];
    g_corr[(size_t)bh*DCORR + c] = (S - (float)Tc*muk*muv) / ((float)Tc*sdk*sdv);
}

// ---------------- stage 4: outs += corr . Wproj ----------------
__global__ __launch_bounds__(256) void k_proj(const float* __restrict__ Wproj) {
    __shared__ float sc[8][128];
    int tid = threadIdx.x;
    int h = blockIdx.y;
    int cs = blockIdx.z;
    int el = tid & 31;
    int b = tid >> 5;
    int e = blockIdx.x*32 + el;
    int lrow = tid >> 5;
    int lc = (tid & 31)*4;
    int start = cs*2032, end = start + 2032;
    const float* wrow = Wproj + ((size_t)h*Ec + e)*DCORR;
    float acc = 0.f;
    for (int c0 = start; c0 < end; c0 += 128) {
        int lim = end - c0; if (lim > 128) lim = 128;
        float4 cv = make_float4(0.f,0.f,0.f,0.f);
        if (lc < lim) cv = *(const float4*)(g_corr + ((size_t)lrow*Hc + h)*DCORR + c0 + lc);
        *(float4*)&sc[lrow][lc] = cv;
        __syncthreads();
#pragma unroll 8
        for (int j = 0; j < lim; j += 4) {
            float4 wv = *(const float4*)(wrow + c0 + j);
            float4 sv = *(const float4*)&sc[b][j];
            acc += wv.x*sv.x + wv.y*sv.y + wv.z*sv.z + wv.w*sv.w;
        }
        __syncthreads();
    }
    atomicAdd(&g_outs[b*(Hc*Ec) + h*Ec + e], acc);
}

// ---------------- stage 5: final linears + mix ----------------
__global__ __launch_bounds__(256) void k_final(
    const float* __restrict__ WT, const float* __restrict__ bT,
    const float* __restrict__ Wp, const float* __restrict__ bp,
    float* __restrict__ out) {
    __shared__ float so1[Hc*Dc];
    __shared__ float sout[Hc*Ec];
    __shared__ float sred[256];
    int b = blockIdx.x, ec = blockIdx.y;
    int tid = threadIdx.x;
    for (int j = tid; j < Hc*Dc; j += 256) so1[j]  = g_o1[b*Hc*Dc + j];
    for (int j = tid; j < Hc*Ec; j += 256) sout[j] = g_outs[b*Hc*Ec + j];
    __syncthreads();
    int e_l = tid >> 3, js = tid & 7;
    int e = ec*32 + e_l;
    float a = 0.f;
    const float* wt = WT + (size_t)e*(Hc*Dc) + js*128;
    const float* s1p = so1 + js*128;
#pragma unroll 4
    for (int j = 0; j < 128; j += 4) {
        float4 wv = *(const float4*)(wt + j);
        float4 sv = *(const float4*)(s1p + j);
        a += wv.x*sv.x + wv.y*sv.y + wv.z*sv.z + wv.w*sv.w;
    }
    const float* wp = Wp + (size_t)e*(Hc*Ec) + js*256;
    const float* s2p = sout + js*256;
#pragma unroll 4
    for (int j = 0; j < 256; j += 4) {
        float4 wv = *(const float4*)(wp + j);
        float4 sv = *(const float4*)(s2p + j);
        a += wv.x*sv.x + wv.y*sv.y + wv.z*sv.z + wv.w*sv.w;
    }
    if (js == 0) a += bT[e] + bp[e];
    sred[tid] = a;
    __syncthreads();
    if (tid < 32) {
        float s = 0.f;
#pragma unroll
        for (int k = 0; k < 8; k++) s += sred[tid*8 + k];
        out[b*Ec + ec*32 + tid] = 0.5f*s;
    }
}

// ---------------- launch ----------------
extern "C" void kernel_launch(void* const* d_in, const int* in_sizes, int n_in,
                              void* d_out, int out_size) {
    const float* x     = (const float*)d_in[0];
    const float* wk    = (const float*)d_in[1];
    const float* wv    = (const float*)d_in[2];
    const float* q     = (const float*)d_in[3];
    const float* Wk    = (const float*)d_in[4];
    const float* bk    = (const float*)d_in[5];
    const float* Wv    = (const float*)d_in[6];
    const float* bv    = (const float*)d_in[7];
    const float* Wproj = (const float*)d_in[8];
    const float* bproj = (const float*)d_in[9];
    const float* WT    = (const float*)d_in[10];
    const float* bT    = (const float*)d_in[11];
    const float* Wp    = (const float*)d_in[12];
    const float* bp    = (const float*)d_in[13];
    float* out = (float*)d_out;

    cudaFuncSetAttribute(k_gemm, cudaFuncAttributeMaxDynamicSharedMemorySize, GSM);
    cudaFuncSetAttribute(k_as,   cudaFuncAttributeMaxDynamicSharedMemorySize, SSM);

    k_init<<<1056, 256>>>(wk, wv);
    k_raw<<<dim3(16, Fc/16, Bc), dim3(16, 8)>>>(x);
    k_wconv<<<dim3((Hc*Dc*Fc)/256, 2), 256>>>(Wk, Wv);
    k_gemm<<<dim3(8, Bc*Hc, 2), 256, GSM>>>(bk, bv);     // 4th launch -> ncu target
    k_statfin<<<65, 256>>>(bproj);
    k_as<<<192, 256, SSM>>>(q);                          // fused attn + smat
    k_corr<<<dim3((DCORR+255)/256, Bc*Hc), 256>>>();
    k_proj<<<dim3(Ec/32, Hc, 4), 256>>>(Wproj);
    k_final<<<dim3(Bc, Ec/32), 256>>>(WT, bT, Wp, bp, out);
}

// round 14
// speedup vs baseline: 1.2004x; 1.0141x over previous
#include <cuda_runtime.h>
#include <cuda_bf16.h>
#include <math.h>
#include <stdint.h>

// Problem constants
#define Bc 8
#define Hc 8
#define Fc 768
#define Dc 128
#define Ec 256
#define Lc 13
#define Tc 1000
#define DCORR 8128
#define TP 1024                 // padded T
#define DT (128*TP)             // plane size per (kv,bh)

// ---------------- device scratch ----------------
__device__ float g_kw[Hc*Lc];
__device__ float g_vw[Hc*Lc];
__device__ __nv_bfloat16 g_ahi[(size_t)2*Bc*Hc*Tc*Fc];   // raw activations [kv][bh][t][f]
__device__ __nv_bfloat16 g_alo[(size_t)2*Bc*Hc*Tc*Fc];
__device__ __nv_bfloat16 g_whi[(size_t)2*Hc*Dc*Fc];      // weights [kv][h][d][f]
__device__ __nv_bfloat16 g_wlo[(size_t)2*Hc*Dc*Fc];
__device__ __nv_bfloat16 g_chi[(size_t)2*Bc*Hc*DT];      // GEMM out planes [kv][bh][d][t]
__device__ __nv_bfloat16 g_clo[(size_t)2*Bc*Hc*DT];
__device__ float g_s1[2*Bc*Hc*Dc];
__device__ float g_s2[2*Bc*Hc*Dc];
__device__ float g_muk[Bc*Hc*Dc];
__device__ float g_sdk[Bc*Hc*Dc];
__device__ float g_muv[Bc*Hc*Dc];
__device__ float g_sdv[Bc*Hc*Dc];
__device__ float g_o1[Bc*Hc*Dc];
__device__ float g_S[(size_t)Bc*Hc*Dc*Dc];
__device__ float g_corr[(size_t)Bc*Hc*DCORR];
__device__ float g_outs[Bc*Hc*Ec];

__device__ __forceinline__ uint32_t smem_u32(const void* p) {
    uint32_t a;
    asm("{ .reg .u64 t; cvta.to.shared.u64 t, %1; cvt.u32.u64 %0, t; }" : "=r"(a) : "l"(p));
    return a;
}
#define CP_COMMIT()  asm volatile("cp.async.commit_group;" ::: "memory")
#define CP_WAIT(n)   asm volatile("cp.async.wait_group %0;" :: "n"(n) : "memory")
#define LDSM4(r0, r1, r2, r3, a) \
    asm volatile("ldmatrix.sync.aligned.m8n8.x4.shared.b16 {%0,%1,%2,%3}, [%4];" \
        : "=r"(r0), "=r"(r1), "=r"(r2), "=r"(r3) : "r"(a))
#define MMA_BF16(d, a, b) asm volatile( \
    "mma.sync.aligned.m16n8k16.row.col.f32.bf16.bf16.f32 " \
    "{%0,%1,%2,%3},{%4,%5,%6,%7},{%8,%9},{%0,%1,%2,%3};\n" \
    : "+f"((d)[0]), "+f"((d)[1]), "+f"((d)[2]), "+f"((d)[3]) \
    : "r"((a)[0]), "r"((a)[1]), "r"((a)[2]), "r"((a)[3]), "r"((b)[0]), "r"((b)[1]))

// hi+lo bf16 reconstruction of 4 packed values
__device__ __forceinline__ float4 un4(uint2 h, uint2 l) {
    float4 r;
    r.x = __int_as_float(h.x << 16)        + __int_as_float(l.x << 16);
    r.y = __int_as_float(h.x & 0xffff0000u) + __int_as_float(l.x & 0xffff0000u);
    r.z = __int_as_float(h.y << 16)        + __int_as_float(l.y << 16);
    r.w = __int_as_float(h.y & 0xffff0000u) + __int_as_float(l.y & 0xffff0000u);
    return r;
}

// ---------------- stage 0: init + softmax + W pack (merged) ----------------
// grid (3072, 2): all blocks pack W; (x<1056, y==0) also zero accumulators;
// block (0,0) also computes softmax weights.
__global__ void k_initw(const float* __restrict__ wk, const float* __restrict__ wv,
                        const float* __restrict__ Wk, const float* __restrict__ Wv) {
    int tid = threadIdx.x;
    size_t i = (size_t)blockIdx.x*256 + tid;
    const float* W = blockIdx.y ? Wv : Wk;
    float v = W[i];
    __nv_bfloat16 h16 = __float2bfloat16(v);
    __nv_bfloat16 l16 = __float2bfloat16(v - __bfloat162float(h16));
    size_t o = (size_t)blockIdx.y*(Hc*Dc*Fc) + i;
    g_whi[o] = h16;
    g_wlo[o] = l16;

    if (blockIdx.y == 0 && blockIdx.x < 1056) {
        int j = blockIdx.x*256 + tid;
        float4 z = make_float4(0.f,0.f,0.f,0.f);
        if (j < 262144) ((float4*)g_S)[j] = z;
        else {
            int k = j - 262144;
            if (k < 4096) ((float4*)g_s1)[k] = z;
            else ((float4*)g_s2)[k - 4096] = z;
        }
    }
    if (blockIdx.x == 0 && blockIdx.y == 0 && tid < 2*Hc) {
        int h = tid % Hc;
        const float* src = (tid < Hc ? wk : wv) + h*Lc;
        float* dst = (tid < Hc ? g_kw : g_vw) + h*Lc;
        float m = -1e30f;
        for (int l = 0; l < Lc; l++) m = fmaxf(m, src[l]);
        float e[Lc]; float s = 0.f;
        for (int l = 0; l < Lc; l++) { e[l] = expf(src[l]-m); s += e[l]; }
        float inv = 1.f/s;
        for (int l = 0; l < Lc; l++) dst[l] = e[l]*inv;
    }
}

// ---------------- stage 1: L-contraction -> bf16 hi/lo [t][f] ----------------
__global__ __launch_bounds__(128) void k_raw(const float* __restrict__ x) {
    __shared__ float2 skv[Hc*Lc];
    __shared__ float xs[2][16][212];
    __shared__ __align__(8) unsigned s_ohi[2][Hc][16][10];
    __shared__ __align__(8) unsigned s_olo[2][Hc][16][10];
    int tx = threadIdx.x;
    int ty = threadIdx.y;
    int tid = ty*16 + tx;
    if (tid < Hc*Lc) skv[tid] = make_float2(g_kw[tid], g_vw[tid]);

    int tbase = blockIdx.x*64;
    int f0 = blockIdx.y*16;
    int b  = blockIdx.z;
    const float* xb = x + (size_t)(b*Fc + f0)*Tc*13;

    auto stage_x = [&](int buf, int st0) {
        int n = Tc - st0;
        int maxf4 = (n >= 16) ? 52 : (n > 0 ? ((n*13) >> 2) : 0);
#pragma unroll
        for (int it = 0; it < 7; it++) {
            int idx = tid + it*128;
            if (idx < 832) {
                int row = idx / 52, col = idx % 52;
                unsigned sz = (col < maxf4) ? 16u : 0u;
                int scol = (col < maxf4) ? col : 0;
                uint32_t dst = smem_u32(&xs[buf][row][col*4]);
                const float* src = xb + (size_t)row*(Tc*13) + st0*13 + scol*4;
                asm volatile("cp.async.cg.shared.global [%0], [%1], 16, %2;"
                             :: "r"(dst), "l"(src), "r"(sz));
            }
        }
        CP_COMMIT();
    };

    stage_x(0, tbase);

#pragma unroll 1
    for (int s = 0; s < 4; s++) {
        int st0 = tbase + s*16;
        if (s < 3) { stage_x((s+1) & 1, st0 + 16); CP_WAIT(1); }
        else CP_WAIT(0);
        __syncthreads();

        int buf = s & 1;
        float xv0[Lc], xv1[Lc];
#pragma unroll
        for (int l = 0; l < Lc; l++) {
            xv0[l] = xs[buf][ty*2][tx*13 + l];
            xv1[l] = xs[buf][ty*2 + 1][tx*13 + l];
        }

#pragma unroll
        for (int h = 0; h < Hc; h++) {
            float k0 = 0.f, v0 = 0.f, k1 = 0.f, v1 = 0.f;
#pragma unroll
            for (int l = 0; l < Lc; l++) {
                float2 w = skv[h*Lc + l];
                k0 += xv0[l]*w.x; v0 += xv0[l]*w.y;
                k1 += xv1[l]*w.x; v1 += xv1[l]*w.y;
            }
            {
                unsigned b0 = __float_as_uint(k0), b1 = __float_as_uint(k1);
                unsigned hiw = __byte_perm(b0, b1, 0x7632);
                float d0 = k0 - __uint_as_float(b0 & 0xffff0000u);
                float d1 = k1 - __uint_as_float(b1 & 0xffff0000u);
                unsigned low;
                asm("cvt.rn.bf16x2.f32 %0, %1, %2;" : "=r"(low) : "f"(d1), "f"(d0));
                s_ohi[0][h][tx][ty] = hiw;
                s_olo[0][h][tx][ty] = low;
            }
            {
                unsigned b0 = __float_as_uint(v0), b1 = __float_as_uint(v1);
                unsigned hiw = __byte_perm(b0, b1, 0x7632);
                float d0 = v0 - __uint_as_float(b0 & 0xffff0000u);
                float d1 = v1 - __uint_as_float(b1 & 0xffff0000u);
                unsigned low;
                asm("cvt.rn.bf16x2.f32 %0, %1, %2;" : "=r"(low) : "f"(d1), "f"(d0));
                s_ohi[1][h][tx][ty] = hiw;
                s_olo[1][h][tx][ty] = low;
            }
        }
        __syncthreads();

        int w = tid >> 5, lane = tid & 31;
        int f4 = lane & 3;
        int tq = lane >> 2;
#pragma unroll
        for (int it = 0; it < 4; it++) {
            int job = w*4 + it;
            int kv = job >> 3;
            int h = job & 7;
            size_t rowbase = ((size_t)(kv*Bc + b)*Hc + h)*Tc;
#pragma unroll
            for (int ti = 0; ti < 2; ti++) {
                int tl = ti*8 + tq;
                int tt = st0 + tl;
                if (tt < Tc) {
                    size_t off = (rowbase + tt)*Fc + f0 + f4*4;
                    *(uint2*)(g_ahi + off) = *(uint2*)&s_ohi[kv][h][tl][f4*2];
                    *(uint2*)(g_alo + off) = *(uint2*)&s_olo[kv][h][tl][f4*2];
                }
            }
        }
        __syncthreads();
    }
}

// ---------------- stage 2: GEMM 128x128, XOR-swizzled smem, 3-stage ----------------
#define GA_PL 8192               // plane: 128 rows x 64B
#define GSTG (4*GA_PL)           // 32768: Ahi, Alo, Bhi, Blo
#define GSM (3*GSTG)             // 98304 per CTA; 2 CTAs = 192KB
#define NCH (Fc/32)

__device__ __forceinline__ void prefetch_g(
    int c, int stage, uint32_t sb, int t0, int tid,
    const __nv_bfloat16* __restrict__ Ahi, const __nv_bfloat16* __restrict__ Alo,
    const __nv_bfloat16* __restrict__ Bhi, const __nv_bfloat16* __restrict__ Blo) {
    int kc = c*32;
    uint32_t stb = sb + stage*GSTG;
#pragma unroll
    for (int it = 0; it < 8; it++) {
        int idx = tid + it*256;
        int plane = idx >> 9;
        int row = (idx >> 2) & 127;
        int seg = idx & 3;
        uint32_t dst = stb + plane*GA_PL + row*64 + (((seg ^ ((row >> 1) & 3))) << 4);
        const __nv_bfloat16* src;
        unsigned sz = 16;
        if (plane < 2) {
            int t = t0 + row;
            if (t >= Tc) { t = 0; sz = 0; }
            src = (plane ? Alo : Ahi) + (size_t)t*Fc + kc + seg*8;
        } else {
            src = (plane == 2 ? Bhi : Blo) + (size_t)row*Fc + kc + seg*8;
        }
        asm volatile("cp.async.cg.shared.global [%0], [%1], 16, %2;"
                     :: "r"(dst), "l"(src), "r"(sz));
    }
    CP_COMMIT();
}

__global__ __launch_bounds__(256, 2) void k_gemm(
    const float* __restrict__ bk, const float* __restrict__ bv) {
    extern __shared__ __align__(1024) char dynsmem[];
    uint32_t sb = smem_u32(dynsmem);

    int tid = threadIdx.x;
    int warp = tid >> 5, lane = tid & 31;
    int bh = blockIdx.y;
    int h = bh & 7;
    int kv = blockIdx.z;
    int t0 = blockIdx.x*128;

    const __nv_bfloat16* Ahi = g_ahi + (size_t)(kv*Bc*Hc + bh)*Tc*Fc;
    const __nv_bfloat16* Alo = g_alo + (size_t)(kv*Bc*Hc + bh)*Tc*Fc;
    const __nv_bfloat16* Bhi = g_whi + (size_t)(kv*Hc + h)*Dc*Fc;
    const __nv_bfloat16* Blo = g_wlo + (size_t)(kv*Hc + h)*Dc*Fc;
    const float* bias = (kv ? bv : bk) + h*Dc;

    int m0w = (warp >> 1)*32;
    int n0w = (warp & 1)*64;
    int arow = (lane & 7) + ((lane >> 3) & 1)*8;
    int abit = (lane >> 4) & 1;
    int brow = (lane & 7) + ((lane >> 4) & 1)*8;
    int bbit = (lane >> 3) & 1;

    float acc[2][8][4];
#pragma unroll
    for (int i = 0; i < 2; i++)
#pragma unroll
        for (int j = 0; j < 8; j++)
#pragma unroll
            for (int r = 0; r < 4; r++) acc[i][j][r] = 0.f;

    prefetch_g(0, 0, sb, t0, tid, Ahi, Alo, Bhi, Blo);
    prefetch_g(1, 1, sb, t0, tid, Ahi, Alo, Bhi, Blo);

#pragma unroll 1
    for (int c = 0; c < NCH; c++) {
        if (c < NCH-1) CP_WAIT(1); else CP_WAIT(0);
        __syncthreads();
        if (c + 2 < NCH)
            prefetch_g(c+2, (c+2)%3, sb, t0, tid, Ahi, Alo, Bhi, Blo);

        uint32_t st = sb + (c%3)*GSTG;
#pragma unroll
        for (int ks = 0; ks < 2; ks++) {
            unsigned ah[2][4], al[2][4];
#pragma unroll
            for (int mi = 0; mi < 2; mi++) {
                int rA = m0w + mi*16 + arow;
                uint32_t a0 = st + (uint32_t)(rA*64 + (((ks*2 + abit) ^ ((rA >> 1) & 3)) << 4));
                LDSM4(ah[mi][0], ah[mi][1], ah[mi][2], ah[mi][3], a0);
                LDSM4(al[mi][0], al[mi][1], al[mi][2], al[mi][3], a0 + GA_PL);
            }
#pragma unroll
            for (int ni = 0; ni < 4; ni++) {
                int rB = n0w + ni*16 + brow;
                uint32_t b0 = st + 2*GA_PL + (uint32_t)(rB*64 + (((ks*2 + bbit) ^ ((rB >> 1) & 3)) << 4));
                unsigned bhv[4], blv[4];
                LDSM4(bhv[0], bhv[1], bhv[2], bhv[3], b0);
                LDSM4(blv[0], blv[1], blv[2], blv[3], b0 + GA_PL);
#pragma unroll
                for (int mi = 0; mi < 2; mi++)
#pragma unroll
                    for (int j2 = 0; j2 < 2; j2++) {
                        int nj = ni*2 + j2;
                        MMA_BF16(acc[mi][nj], ah[mi], &bhv[j2*2]);
                        MMA_BF16(acc[mi][nj], ah[mi], &blv[j2*2]);
                        MMA_BF16(acc[mi][nj], al[mi], &bhv[j2*2]);
                    }
            }
        }
    }

    // epilogue: transpose through smem to [d][t], emit bf16 hi/lo planes + stats
    __syncthreads();
    float* Cs = (float*)dynsmem;           // [128 d][132]
    int g = lane >> 2, q = lane & 3;
#pragma unroll
    for (int nj = 0; nj < 8; nj++) {
        int d = n0w + nj*8 + q*2;
        float2 bb = *(const float2*)(bias + d);
#pragma unroll
        for (int mi = 0; mi < 2; mi++) {
            int r = m0w + mi*16 + g;
            Cs[d*132 + r]         = acc[mi][nj][0] + bb.x;
            Cs[(d+1)*132 + r]     = acc[mi][nj][1] + bb.y;
            Cs[d*132 + r + 8]     = acc[mi][nj][2] + bb.x;
            Cs[(d+1)*132 + r + 8] = acc[mi][nj][3] + bb.y;
        }
    }
    __syncthreads();

    __nv_bfloat16* Phi = g_chi + ((size_t)kv*64 + bh)*DT;
    __nv_bfloat16* Plo = g_clo + ((size_t)kv*64 + bh)*DT;
    size_t so = ((size_t)kv*64 + bh)*Dc;
    int tb = t0 + lane*4;
#pragma unroll 1
    for (int rr = 0; rr < 16; rr++) {
        int d = warp*16 + rr;
        float4 v = *(float4*)&Cs[d*132 + lane*4];
        v.x = (tb+0 < Tc) ? v.x : 0.f;
        v.y = (tb+1 < Tc) ? v.y : 0.f;
        v.z = (tb+2 < Tc) ? v.z : 0.f;
        v.w = (tb+3 < Tc) ? v.w : 0.f;
        __nv_bfloat162 h01 = __floats2bfloat162_rn(v.x, v.y);
        __nv_bfloat162 h23 = __floats2bfloat162_rn(v.z, v.w);
        unsigned uh01 = *(unsigned*)&h01, uh23 = *(unsigned*)&h23;
        float f0 = __int_as_float(uh01 << 16);
        float f1 = __int_as_float(uh01 & 0xffff0000u);
        float f2 = __int_as_float(uh23 << 16);
        float f3 = __int_as_float(uh23 & 0xffff0000u);
        __nv_bfloat162 l01 = __floats2bfloat162_rn(v.x - f0, v.y - f1);
        __nv_bfloat162 l23 = __floats2bfloat162_rn(v.z - f2, v.w - f3);
        *(uint2*)(Phi + (size_t)d*TP + tb) = make_uint2(uh01, uh23);
        *(uint2*)(Plo + (size_t)d*TP + tb) = make_uint2(*(unsigned*)&l01, *(unsigned*)&l23);
        float p1 = v.x + v.y + v.z + v.w;
        float p2 = v.x*v.x + v.y*v.y + v.z*v.z + v.w*v.w;
        for (int off = 16; off; off >>= 1) {
            p1 += __shfl_down_sync(~0u, p1, off);
            p2 += __shfl_down_sync(~0u, p2, off);
        }
        if (lane == 0) {
            atomicAdd(&g_s1[so + d], p1);
            atomicAdd(&g_s2[so + d], p2);
        }
    }
}

// ---------------- fused stage 3: attention (blocks 0..63) + S=K^T V (blocks 64..191) ----------------
#define NCHS 16

__device__ __forceinline__ void prefetch_smat(
    int c, int stage, uint32_t sb, int tid,
    const __nv_bfloat16* __restrict__ Ahi, const __nv_bfloat16* __restrict__ Alo,
    const __nv_bfloat16* __restrict__ Bhi, const __nv_bfloat16* __restrict__ Blo) {
    int kc = c*32;
    uint32_t stb = sb + stage*GSTG;
#pragma unroll
    for (int it = 0; it < 8; it++) {
        int idx = tid + it*256;
        int plane = idx >> 9;
        int row = (idx >> 2) & 127;
        int seg = idx & 3;
        uint32_t dst = stb + plane*GA_PL + row*64 + (((seg ^ ((row >> 1) & 3))) << 4);
        const __nv_bfloat16* src =
            (plane == 0 ? Ahi : plane == 1 ? Alo : plane == 2 ? Bhi : Blo)
            + (size_t)row*TP + kc + seg*8;
        asm volatile("cp.async.cg.shared.global [%0], [%1], 16;" :: "r"(dst), "l"(src));
    }
    CP_COMMIT();
}

__global__ __launch_bounds__(256, 2) void k_as(const float* __restrict__ q) {
    extern __shared__ __align__(1024) char dynsmem[];
    int tid = threadIdx.x;

    if (blockIdx.x < 64) {
        // ---------- attention branch ----------
        float* s_sc  = (float*)dynsmem;           // TP floats
        float* s_red = s_sc + TP;                 // 256
        float* s_q   = s_red + 256;               // 128
        int bh = blockIdx.x;
        int h = bh & 7;
        const __nv_bfloat16* Khi = g_chi + (size_t)bh*DT;
        const __nv_bfloat16* Klo = g_clo + (size_t)bh*DT;
        const __nv_bfloat16* Vhi = g_chi + (size_t)(64 + bh)*DT;
        const __nv_bfloat16* Vlo = g_clo + (size_t)(64 + bh)*DT;
        if (tid < Dc) s_q[tid] = q[h*Dc + tid];
        __syncthreads();

        if (tid < 250) {
            float a0 = 0.f, a1 = 0.f, a2 = 0.f, a3 = 0.f;
#pragma unroll 8
            for (int d = 0; d < Dc; d++) {
                uint2 ph = *(const uint2*)(Khi + (size_t)d*TP + tid*4);
                uint2 pl = *(const uint2*)(Klo + (size_t)d*TP + tid*4);
                float qd = s_q[d];
                float4 kv4 = un4(ph, pl);
                a0 += qd*kv4.x; a1 += qd*kv4.y; a2 += qd*kv4.z; a3 += qd*kv4.w;
            }
            const float sc = 0.08838834764831845f;
            *(float4*)&s_sc[tid*4] = make_float4(a0*sc, a1*sc, a2*sc, a3*sc);
        }
        if (tid < 24) s_sc[1000 + tid] = 0.f;
        __syncthreads();

        float lm = -1e30f;
        for (int t = tid; t < Tc; t += 256) lm = fmaxf(lm, s_sc[t]);
        s_red[tid] = lm; __syncthreads();
        for (int s = 128; s; s >>= 1) { if (tid < s) s_red[tid] = fmaxf(s_red[tid], s_red[tid+s]); __syncthreads(); }
        float m = s_red[0];
        __syncthreads();
        float ls = 0.f;
        for (int t = tid; t < Tc; t += 256) { float e = expf(s_sc[t]-m); s_sc[t] = e; ls += e; }
        s_red[tid] = ls; __syncthreads();
        for (int s = 128; s; s >>= 1) { if (tid < s) s_red[tid] += s_red[tid+s]; __syncthreads(); }
        float inv = 1.f / s_red[0];
        __syncthreads();

        int w = tid >> 5, lane = tid & 31;
#pragma unroll 1
        for (int rr = 0; rr < 16; rr++) {
            int d = w*16 + rr;
            float acc = 0.f;
#pragma unroll
            for (int cc = 0; cc < 8; cc++) {
                int grp = lane + cc*32;
                uint2 ph = *(const uint2*)(Vhi + (size_t)d*TP + grp*4);
                uint2 pl = *(const uint2*)(Vlo + (size_t)d*TP + grp*4);
                float4 vv = un4(ph, pl);
                float4 aa = *(float4*)&s_sc[grp*4];
                acc += aa.x*vv.x + aa.y*vv.y + aa.z*vv.z + aa.w*vv.w;
            }
            for (int off = 16; off; off >>= 1) acc += __shfl_down_sync(~0u, acc, off);
            if (lane == 0) g_o1[bh*Dc + d] = acc * inv;
        }
        return;
    }

    // ---------- S = K^T V branch (XOR-swizzled 3-stage) ----------
    uint32_t sb = smem_u32(dynsmem);
    int warp = tid >> 5, lane = tid & 31;
    int job = blockIdx.x - 64;       // 0..127
    int bh = job >> 1;
    int seg = job & 1;
    const __nv_bfloat16* Ahi = g_chi + (size_t)bh*DT + seg*512;
    const __nv_bfloat16* Alo = g_clo + (size_t)bh*DT + seg*512;
    const __nv_bfloat16* Bhi = g_chi + (size_t)(64 + bh)*DT + seg*512;
    const __nv_bfloat16* Blo = g_clo + (size_t)(64 + bh)*DT + seg*512;

    int m0w = (warp >> 1)*32;
    int n0w = (warp & 1)*64;
    int arow = (lane & 7) + ((lane >> 3) & 1)*8;
    int abit = (lane >> 4) & 1;
    int brow = (lane & 7) + ((lane >> 4) & 1)*8;
    int bbit = (lane >> 3) & 1;

    float acc[2][8][4];
#pragma unroll
    for (int i = 0; i < 2; i++)
#pragma unroll
        for (int j = 0; j < 8; j++)
#pragma unroll
            for (int r = 0; r < 4; r++) acc[i][j][r] = 0.f;

    prefetch_smat(0, 0, sb, tid, Ahi, Alo, Bhi, Blo);
    prefetch_smat(1, 1, sb, tid, Ahi, Alo, Bhi, Blo);

#pragma unroll 1
    for (int c = 0; c < NCHS; c++) {
        if (c < NCHS-1) CP_WAIT(1); else CP_WAIT(0);
        __syncthreads();
        if (c + 2 < NCHS)
            prefetch_smat(c+2, (c+2)%3, sb, tid, Ahi, Alo, Bhi, Blo);

        uint32_t st = sb + (c%3)*GSTG;
#pragma unroll
        for (int ks = 0; ks < 2; ks++) {
            unsigned ah[2][4], al[2][4];
#pragma unroll
            for (int mi = 0; mi < 2; mi++) {
                int rA = m0w + mi*16 + arow;
                uint32_t a0 = st + (uint32_t)(rA*64 + (((ks*2 + abit) ^ ((rA >> 1) & 3)) << 4));
                LDSM4(ah[mi][0], ah[mi][1], ah[mi][2], ah[mi][3], a0);
                LDSM4(al[mi][0], al[mi][1], al[mi][2], al[mi][3], a0 + GA_PL);
            }
#pragma unroll
            for (int ni = 0; ni < 4; ni++) {
                int rB = n0w + ni*16 + brow;
                uint32_t b0 = st + 2*GA_PL + (uint32_t)(rB*64 + (((ks*2 + bbit) ^ ((rB >> 1) & 3)) << 4));
                unsigned bhv[4], blv[4];
                LDSM4(bhv[0], bhv[1], bhv[2], bhv[3], b0);
                LDSM4(blv[0], blv[1], blv[2], blv[3], b0 + GA_PL);
#pragma unroll
                for (int mi = 0; mi < 2; mi++)
#pragma unroll
                    for (int j2 = 0; j2 < 2; j2++) {
                        int nj = ni*2 + j2;
                        MMA_BF16(acc[mi][nj], ah[mi], &bhv[j2*2]);
                        MMA_BF16(acc[mi][nj], ah[mi], &blv[j2*2]);
                        MMA_BF16(acc[mi][nj], al[mi], &bhv[j2*2]);
                    }
            }
        }
    }

    float* Sp = g_S + (size_t)bh*Dc*Dc;
    int g = lane >> 2, q4 = lane & 3;
#pragma unroll
    for (int nj = 0; nj < 8; nj++) {
        int l = n0w + nj*8 + q4*2;
#pragma unroll
        for (int mi = 0; mi < 2; mi++) {
            int k0 = m0w + mi*16 + g;
            atomicAdd(&Sp[k0*Dc + l],       acc[mi][nj][0]);
            atomicAdd(&Sp[k0*Dc + l + 1],   acc[mi][nj][1]);
            atomicAdd(&Sp[(k0+8)*Dc + l],   acc[mi][nj][2]);
            atomicAdd(&Sp[(k0+8)*Dc + l+1], acc[mi][nj][3]);
        }
    }
}

// ---------------- stats finalize + outs init (after k_as, before corr/proj) ----------------
__global__ void k_statfin(const float* __restrict__ bproj) {
    int bid = blockIdx.x;
    int tid = threadIdx.x;
    if (bid < 64) {
        int kv = tid >> 7;
        int d = tid & 127;
        size_t o = ((size_t)kv*64 + bid)*Dc + d;
        float s1 = g_s1[o], s2 = g_s2[o];
        float mu = s1 * (1.f/Tc);
        float var = (s2 - (float)Tc*mu*mu) * (1.f/(Tc-1));
        var = fmaxf(var, 0.f);
        float sd = sqrtf(var) + 1e-9f;
        if (kv == 0) { g_muk[bid*Dc + d] = mu; g_sdk[bid*Dc + d] = sd; }
        else         { g_muv[bid*Dc + d] = mu; g_sdv[bid*Dc + d] = sd; }
    } else {
        for (int i = tid; i < Bc*Hc*Ec; i += 256)
            g_outs[i] = bproj[i & (Hc*Ec - 1)];
    }
}

// ---------------- stage 3c: normalized correlation ----------------
__global__ void k_corr() {
    int c = blockIdx.x*256 + threadIdx.x;
    int bh = blockIdx.y;
    if (c >= DCORR) return;
    float disc = 65025.0f - 8.0f*(float)c;
    int k = (int)((255.0f - sqrtf(disc))*0.5f);
    if (k < 0) k = 0;
    if (k > 126) k = 126;
    while (k > 0 && k*(255-k)/2 > c) k--;
    while ((k+1)*(254-k)/2 <= c) k++;
    int l = k + 1 + (c - k*(255-k)/2);
    float muk = g_muk[bh*Dc + k], sdk = g_sdk[bh*Dc + k];
    float muv = g_muv[bh*Dc + l], sdv = g_sdv[bh*Dc + l];
    float S = g_S[(size_t)bh*Dc*Dc + k*Dc + l];
    g_corr[(size_t)bh*DCORR + c] = (S - (float)Tc*muk*muv) / ((float)Tc*sdk*sdv);
}

// ---------------- stage 4: outs += corr . Wproj ----------------
__global__ __launch_bounds__(256) void k_proj(const float* __restrict__ Wproj) {
    __shared__ float sc[8][128];
    int tid = threadIdx.x;
    int h = blockIdx.y;
    int cs = blockIdx.z;
    int el = tid & 31;
    int b = tid >> 5;
    int e = blockIdx.x*32 + el;
    int lrow = tid >> 5;
    int lc = (tid & 31)*4;
    int start = cs*2032, end = start + 2032;
    const float* wrow = Wproj + ((size_t)h*Ec + e)*DCORR;
    float acc = 0.f;
    for (int c0 = start; c0 < end; c0 += 128) {
        int lim = end - c0; if (lim > 128) lim = 128;
        float4 cv = make_float4(0.f,0.f,0.f,0.f);
        if (lc < lim) cv = *(const float4*)(g_corr + ((size_t)lrow*Hc + h)*DCORR + c0 + lc);
        *(float4*)&sc[lrow][lc] = cv;
        __syncthreads();
#pragma unroll 8
        for (int j = 0; j < lim; j += 4) {
            float4 wv = *(const float4*)(wrow + c0 + j);
            float4 sv = *(const float4*)&sc[b][j];
            acc += wv.x*sv.x + wv.y*sv.y + wv.z*sv.z + wv.w*sv.w;
        }
        __syncthreads();
    }
    atomicAdd(&g_outs[b*(Hc*Ec) + h*Ec + e], acc);
}

// ---------------- stage 5: final linears + mix ----------------
__global__ __launch_bounds__(256) void k_final(
    const float* __restrict__ WT, const float* __restrict__ bT,
    const float* __restrict__ Wp, const float* __restrict__ bp,
    float* __restrict__ out) {
    __shared__ float so1[Hc*Dc];
    __shared__ float sout[Hc*Ec];
    __shared__ float sred[256];
    int b = blockIdx.x, ec = blockIdx.y;
    int tid = threadIdx.x;
    for (int j = tid; j < Hc*Dc; j += 256) so1[j]  = g_o1[b*Hc*Dc + j];
    for (int j = tid; j < Hc*Ec; j += 256) sout[j] = g_outs[b*Hc*Ec + j];
    __syncthreads();
    int e_l = tid >> 3, js = tid & 7;
    int e = ec*32 + e_l;
    float a = 0.f;
    const float* wt = WT + (size_t)e*(Hc*Dc) + js*128;
    const float* s1p = so1 + js*128;
#pragma unroll 4
    for (int j = 0; j < 128; j += 4) {
        float4 wv = *(const float4*)(wt + j);
        float4 sv = *(const float4*)(s1p + j);
        a += wv.x*sv.x + wv.y*sv.y + wv.z*sv.z + wv.w*sv.w;
    }
    const float* wp = Wp + (size_t)e*(Hc*Ec) + js*256;
    const float* s2p = sout + js*256;
#pragma unroll 4
    for (int j = 0; j < 256; j += 4) {
        float4 wv = *(const float4*)(wp + j);
        float4 sv = *(const float4*)(s2p + j);
        a += wv.x*sv.x + wv.y*sv.y + wv.z*sv.z + wv.w*sv.w;
    }
    if (js == 0) a += bT[e] + bp[e];
    sred[tid] = a;
    __syncthreads();
    if (tid < 32) {
        float s = 0.f;
#pragma unroll
        for (int k = 0; k < 8; k++) s += sred[tid*8 + k];
        out[b*Ec + ec*32 + tid] = 0.5f*s;
    }
}

// ---------------- launch ----------------
extern "C" void kernel_launch(void* const* d_in, const int* in_sizes, int n_in,
                              void* d_out, int out_size) {
    const float* x     = (const float*)d_in[0];
    const float* wk    = (const float*)d_in[1];
    const float* wv    = (const float*)d_in[2];
    const float* q     = (const float*)d_in[3];
    const float* Wk    = (const float*)d_in[4];
    const float* bk    = (const float*)d_in[5];
    const float* Wv    = (const float*)d_in[6];
    const float* bv    = (const float*)d_in[7];
    const float* Wproj = (const float*)d_in[8];
    const float* bproj = (const float*)d_in[9];
    const float* WT    = (const float*)d_in[10];
    const float* bT    = (const float*)d_in[11];
    const float* Wp    = (const float*)d_in[12];
    const float* bp    = (const float*)d_in[13];
    float* out = (float*)d_out;

    cudaFuncSetAttribute(k_gemm, cudaFuncAttributeMaxDynamicSharedMemorySize, GSM);
    cudaFuncSetAttribute(k_as,   cudaFuncAttributeMaxDynamicSharedMemorySize, GSM);

    k_initw<<<dim3(3072, 2), 256>>>(wk, wv, Wk, Wv);
    k_raw<<<dim3(16, Fc/16, Bc), dim3(16, 8)>>>(x);
    k_gemm<<<dim3(8, Bc*Hc, 2), 256, GSM>>>(bk, bv);
    k_as<<<192, 256, GSM>>>(q);                          // 4th launch -> ncu target
    k_statfin<<<65, 256>>>(bproj);
    k_corr<<<dim3((DCORR+255)/256, Bc*Hc), 256>>>();
    k_proj<<<dim3(Ec/32, Hc, 4), 256>>>(Wproj);
    k_final<<<dim3(Bc, Ec/32), 256>>>(WT, bT, Wp, bp, out);
}

// round 15
// speedup vs baseline: 1.5032x; 1.2523x over previous
#include <cuda_runtime.h>
#include <cuda_bf16.h>
#include <math.h>
#include <stdint.h>

// Problem constants
#define Bc 8
#define Hc 8
#define Fc 768
#define Dc 128
#define Ec 256
#define Lc 13
#define Tc 1000
#define DCORR 8128
#define TP 1024                 // padded T
#define DT (128*TP)             // plane size per (kv,bh)

// ---------------- device scratch ----------------
__device__ float g_kw[Hc*Lc];
__device__ float g_vw[Hc*Lc];
__device__ __nv_bfloat16 g_ahi[(size_t)2*Bc*Hc*Tc*Fc];   // raw activations [kv][bh][t][f]
__device__ __nv_bfloat16 g_alo[(size_t)2*Bc*Hc*Tc*Fc];
__device__ __nv_bfloat16 g_whi[(size_t)2*Hc*Dc*Fc];      // weights [kv][h][d][f]
__device__ __nv_bfloat16 g_wlo[(size_t)2*Hc*Dc*Fc];
__device__ __nv_bfloat16 g_chi[(size_t)2*Bc*Hc*DT];      // GEMM out planes [kv][bh][d][t]
__device__ __nv_bfloat16 g_clo[(size_t)2*Bc*Hc*DT];
__device__ float g_s1[2*Bc*Hc*Dc];
__device__ float g_s2[2*Bc*Hc*Dc];
__device__ float g_muk[Bc*Hc*Dc];
__device__ float g_sdk[Bc*Hc*Dc];
__device__ float g_muv[Bc*Hc*Dc];
__device__ float g_sdv[Bc*Hc*Dc];
__device__ float g_o1[Bc*Hc*Dc];
__device__ float g_S[(size_t)Bc*Hc*Dc*Dc];
__device__ float g_corr[(size_t)Bc*Hc*DCORR];
__device__ float g_outs[Bc*Hc*Ec];

__device__ __forceinline__ uint32_t smem_u32(const void* p) {
    uint32_t a;
    asm("{ .reg .u64 t; cvta.to.shared.u64 t, %1; cvt.u32.u64 %0, t; }" : "=r"(a) : "l"(p));
    return a;
}
#define CP_COMMIT()  asm volatile("cp.async.commit_group;" ::: "memory")
#define CP_WAIT(n)   asm volatile("cp.async.wait_group %0;" :: "n"(n) : "memory")
#define LDSM4(r0, r1, r2, r3, a) \
    asm volatile("ldmatrix.sync.aligned.m8n8.x4.shared.b16 {%0,%1,%2,%3}, [%4];" \
        : "=r"(r0), "=r"(r1), "=r"(r2), "=r"(r3) : "r"(a))
#define MMA_BF16(d, a, b) asm volatile( \
    "mma.sync.aligned.m16n8k16.row.col.f32.bf16.bf16.f32 " \
    "{%0,%1,%2,%3},{%4,%5,%6,%7},{%8,%9},{%0,%1,%2,%3};\n" \
    : "+f"((d)[0]), "+f"((d)[1]), "+f"((d)[2]), "+f"((d)[3]) \
    : "r"((a)[0]), "r"((a)[1]), "r"((a)[2]), "r"((a)[3]), "r"((b)[0]), "r"((b)[1]))

// hi+lo bf16 reconstruction of 4 packed values
__device__ __forceinline__ float4 un4(uint2 h, uint2 l) {
    float4 r;
    r.x = __int_as_float(h.x << 16)        + __int_as_float(l.x << 16);
    r.y = __int_as_float(h.x & 0xffff0000u) + __int_as_float(l.x & 0xffff0000u);
    r.z = __int_as_float(h.y << 16)        + __int_as_float(l.y << 16);
    r.w = __int_as_float(h.y & 0xffff0000u) + __int_as_float(l.y & 0xffff0000u);
    return r;
}

// ---------------- stage 0: init + softmax + W pack (merged) ----------------
__global__ void k_initw(const float* __restrict__ wk, const float* __restrict__ wv,
                        const float* __restrict__ Wk, const float* __restrict__ Wv) {
    int tid = threadIdx.x;
    size_t i = (size_t)blockIdx.x*256 + tid;
    const float* W = blockIdx.y ? Wv : Wk;
    float v = W[i];
    __nv_bfloat16 h16 = __float2bfloat16(v);
    __nv_bfloat16 l16 = __float2bfloat16(v - __bfloat162float(h16));
    size_t o = (size_t)blockIdx.y*(Hc*Dc*Fc) + i;
    g_whi[o] = h16;
    g_wlo[o] = l16;

    if (blockIdx.y == 0 && blockIdx.x < 1056) {
        int j = blockIdx.x*256 + tid;
        float4 z = make_float4(0.f,0.f,0.f,0.f);
        if (j < 262144) ((float4*)g_S)[j] = z;
        else {
            int k = j - 262144;
            if (k < 4096) ((float4*)g_s1)[k] = z;
            else ((float4*)g_s2)[k - 4096] = z;
        }
    }
    if (blockIdx.x == 0 && blockIdx.y == 0 && tid < 2*Hc) {
        int h = tid % Hc;
        const float* src = (tid < Hc ? wk : wv) + h*Lc;
        float* dst = (tid < Hc ? g_kw : g_vw) + h*Lc;
        float m = -1e30f;
        for (int l = 0; l < Lc; l++) m = fmaxf(m, src[l]);
        float e[Lc]; float s = 0.f;
        for (int l = 0; l < Lc; l++) { e[l] = expf(src[l]-m); s += e[l]; }
        float inv = 1.f/s;
        for (int l = 0; l < Lc; l++) dst[l] = e[l]*inv;
    }
}

// ---------------- stage 1: L-contraction -> bf16 hi/lo [t][f] ----------------
__global__ __launch_bounds__(128) void k_raw(const float* __restrict__ x) {
    __shared__ float2 skv[Hc*Lc];
    __shared__ float xs[2][16][212];
    __shared__ __align__(8) unsigned s_ohi[2][Hc][16][10];
    __shared__ __align__(8) unsigned s_olo[2][Hc][16][10];
    int tx = threadIdx.x;
    int ty = threadIdx.y;
    int tid = ty*16 + tx;
    if (tid < Hc*Lc) skv[tid] = make_float2(g_kw[tid], g_vw[tid]);

    int tbase = blockIdx.x*64;
    int f0 = blockIdx.y*16;
    int b  = blockIdx.z;
    const float* xb = x + (size_t)(b*Fc + f0)*Tc*13;

    auto stage_x = [&](int buf, int st0) {
        int n = Tc - st0;
        int maxf4 = (n >= 16) ? 52 : (n > 0 ? ((n*13) >> 2) : 0);
#pragma unroll
        for (int it = 0; it < 7; it++) {
            int idx = tid + it*128;
            if (idx < 832) {
                int row = idx / 52, col = idx % 52;
                unsigned sz = (col < maxf4) ? 16u : 0u;
                int scol = (col < maxf4) ? col : 0;
                uint32_t dst = smem_u32(&xs[buf][row][col*4]);
                const float* src = xb + (size_t)row*(Tc*13) + st0*13 + scol*4;
                asm volatile("cp.async.cg.shared.global [%0], [%1], 16, %2;"
                             :: "r"(dst), "l"(src), "r"(sz));
            }
        }
        CP_COMMIT();
    };

    stage_x(0, tbase);

#pragma unroll 1
    for (int s = 0; s < 4; s++) {
        int st0 = tbase + s*16;
        if (s < 3) { stage_x((s+1) & 1, st0 + 16); CP_WAIT(1); }
        else CP_WAIT(0);
        __syncthreads();

        int buf = s & 1;
        float xv0[Lc], xv1[Lc];
#pragma unroll
        for (int l = 0; l < Lc; l++) {
            xv0[l] = xs[buf][ty*2][tx*13 + l];
            xv1[l] = xs[buf][ty*2 + 1][tx*13 + l];
        }

#pragma unroll
        for (int h = 0; h < Hc; h++) {
            float k0 = 0.f, v0 = 0.f, k1 = 0.f, v1 = 0.f;
#pragma unroll
            for (int l = 0; l < Lc; l++) {
                float2 w = skv[h*Lc + l];
                k0 += xv0[l]*w.x; v0 += xv0[l]*w.y;
                k1 += xv1[l]*w.x; v1 += xv1[l]*w.y;
            }
            {
                unsigned b0 = __float_as_uint(k0), b1 = __float_as_uint(k1);
                unsigned hiw = __byte_perm(b0, b1, 0x7632);
                float d0 = k0 - __uint_as_float(b0 & 0xffff0000u);
                float d1 = k1 - __uint_as_float(b1 & 0xffff0000u);
                unsigned low;
                asm("cvt.rn.bf16x2.f32 %0, %1, %2;" : "=r"(low) : "f"(d1), "f"(d0));
                s_ohi[0][h][tx][ty] = hiw;
                s_olo[0][h][tx][ty] = low;
            }
            {
                unsigned b0 = __float_as_uint(v0), b1 = __float_as_uint(v1);
                unsigned hiw = __byte_perm(b0, b1, 0x7632);
                float d0 = v0 - __uint_as_float(b0 & 0xffff0000u);
                float d1 = v1 - __uint_as_float(b1 & 0xffff0000u);
                unsigned low;
                asm("cvt.rn.bf16x2.f32 %0, %1, %2;" : "=r"(low) : "f"(d1), "f"(d0));
                s_ohi[1][h][tx][ty] = hiw;
                s_olo[1][h][tx][ty] = low;
            }
        }
        __syncthreads();

        int w = tid >> 5, lane = tid & 31;
        int f4 = lane & 3;
        int tq = lane >> 2;
#pragma unroll
        for (int it = 0; it < 4; it++) {
            int job = w*4 + it;
            int kv = job >> 3;
            int h = job & 7;
            size_t rowbase = ((size_t)(kv*Bc + b)*Hc + h)*Tc;
#pragma unroll
            for (int ti = 0; ti < 2; ti++) {
                int tl = ti*8 + tq;
                int tt = st0 + tl;
                if (tt < Tc) {
                    size_t off = (rowbase + tt)*Fc + f0 + f4*4;
                    *(uint2*)(g_ahi + off) = *(uint2*)&s_ohi[kv][h][tl][f4*2];
                    *(uint2*)(g_alo + off) = *(uint2*)&s_olo[kv][h][tl][f4*2];
                }
            }
        }
        __syncthreads();
    }
}

// ---------------- stage 2: GEMM 128x128, XOR-swizzled smem, 3-stage ----------------
#define GA_PL 8192
#define GSTG (4*GA_PL)
#define GSM (3*GSTG)
#define NCH (Fc/32)

__device__ __forceinline__ void prefetch_g(
    int c, int stage, uint32_t sb, int t0, int tid,
    const __nv_bfloat16* __restrict__ Ahi, const __nv_bfloat16* __restrict__ Alo,
    const __nv_bfloat16* __restrict__ Bhi, const __nv_bfloat16* __restrict__ Blo) {
    int kc = c*32;
    uint32_t stb = sb + stage*GSTG;
#pragma unroll
    for (int it = 0; it < 8; it++) {
        int idx = tid + it*256;
        int plane = idx >> 9;
        int row = (idx >> 2) & 127;
        int seg = idx & 3;
        uint32_t dst = stb + plane*GA_PL + row*64 + (((seg ^ ((row >> 1) & 3))) << 4);
        const __nv_bfloat16* src;
        unsigned sz = 16;
        if (plane < 2) {
            int t = t0 + row;
            if (t >= Tc) { t = 0; sz = 0; }
            src = (plane ? Alo : Ahi) + (size_t)t*Fc + kc + seg*8;
        } else {
            src = (plane == 2 ? Bhi : Blo) + (size_t)row*Fc + kc + seg*8;
        }
        asm volatile("cp.async.cg.shared.global [%0], [%1], 16, %2;"
                     :: "r"(dst), "l"(src), "r"(sz));
    }
    CP_COMMIT();
}

__global__ __launch_bounds__(256, 2) void k_gemm(
    const float* __restrict__ bk, const float* __restrict__ bv) {
    extern __shared__ __align__(1024) char dynsmem[];
    uint32_t sb = smem_u32(dynsmem);

    int tid = threadIdx.x;
    int warp = tid >> 5, lane = tid & 31;
    int bh = blockIdx.y;
    int h = bh & 7;
    int kv = blockIdx.z;
    int t0 = blockIdx.x*128;

    const __nv_bfloat16* Ahi = g_ahi + (size_t)(kv*Bc*Hc + bh)*Tc*Fc;
    const __nv_bfloat16* Alo = g_alo + (size_t)(kv*Bc*Hc + bh)*Tc*Fc;
    const __nv_bfloat16* Bhi = g_whi + (size_t)(kv*Hc + h)*Dc*Fc;
    const __nv_bfloat16* Blo = g_wlo + (size_t)(kv*Hc + h)*Dc*Fc;
    const float* bias = (kv ? bv : bk) + h*Dc;

    int m0w = (warp >> 1)*32;
    int n0w = (warp & 1)*64;
    int arow = (lane & 7) + ((lane >> 3) & 1)*8;
    int abit = (lane >> 4) & 1;
    int brow = (lane & 7) + ((lane >> 4) & 1)*8;
    int bbit = (lane >> 3) & 1;

    float acc[2][8][4];
#pragma unroll
    for (int i = 0; i < 2; i++)
#pragma unroll
        for (int j = 0; j < 8; j++)
#pragma unroll
            for (int r = 0; r < 4; r++) acc[i][j][r] = 0.f;

    prefetch_g(0, 0, sb, t0, tid, Ahi, Alo, Bhi, Blo);
    prefetch_g(1, 1, sb, t0, tid, Ahi, Alo, Bhi, Blo);

#pragma unroll 1
    for (int c = 0; c < NCH; c++) {
        if (c < NCH-1) CP_WAIT(1); else CP_WAIT(0);
        __syncthreads();
        if (c + 2 < NCH)
            prefetch_g(c+2, (c+2)%3, sb, t0, tid, Ahi, Alo, Bhi, Blo);

        uint32_t st = sb + (c%3)*GSTG;
#pragma unroll
        for (int ks = 0; ks < 2; ks++) {
            unsigned ah[2][4], al[2][4];
#pragma unroll
            for (int mi = 0; mi < 2; mi++) {
                int rA = m0w + mi*16 + arow;
                uint32_t a0 = st + (uint32_t)(rA*64 + (((ks*2 + abit) ^ ((rA >> 1) & 3)) << 4));
                LDSM4(ah[mi][0], ah[mi][1], ah[mi][2], ah[mi][3], a0);
                LDSM4(al[mi][0], al[mi][1], al[mi][2], al[mi][3], a0 + GA_PL);
            }
#pragma unroll
            for (int ni = 0; ni < 4; ni++) {
                int rB = n0w + ni*16 + brow;
                uint32_t b0 = st + 2*GA_PL + (uint32_t)(rB*64 + (((ks*2 + bbit) ^ ((rB >> 1) & 3)) << 4));
                unsigned bhv[4], blv[4];
                LDSM4(bhv[0], bhv[1], bhv[2], bhv[3], b0);
                LDSM4(blv[0], blv[1], blv[2], blv[3], b0 + GA_PL);
#pragma unroll
                for (int mi = 0; mi < 2; mi++)
#pragma unroll
                    for (int j2 = 0; j2 < 2; j2++) {
                        int nj = ni*2 + j2;
                        MMA_BF16(acc[mi][nj], ah[mi], &bhv[j2*2]);
                        MMA_BF16(acc[mi][nj], ah[mi], &blv[j2*2]);
                        MMA_BF16(acc[mi][nj], al[mi], &bhv[j2*2]);
                    }
            }
        }
    }

    // epilogue: transpose through smem to [d][t], emit bf16 hi/lo planes + stats
    __syncthreads();
    float* Cs = (float*)dynsmem;           // [128 d][132]
    int g = lane >> 2, q = lane & 3;
#pragma unroll
    for (int nj = 0; nj < 8; nj++) {
        int d = n0w + nj*8 + q*2;
        float2 bb = *(const float2*)(bias + d);
#pragma unroll
        for (int mi = 0; mi < 2; mi++) {
            int r = m0w + mi*16 + g;
            Cs[d*132 + r]         = acc[mi][nj][0] + bb.x;
            Cs[(d+1)*132 + r]     = acc[mi][nj][1] + bb.y;
            Cs[d*132 + r + 8]     = acc[mi][nj][2] + bb.x;
            Cs[(d+1)*132 + r + 8] = acc[mi][nj][3] + bb.y;
        }
    }
    __syncthreads();

    __nv_bfloat16* Phi = g_chi + ((size_t)kv*64 + bh)*DT;
    __nv_bfloat16* Plo = g_clo + ((size_t)kv*64 + bh)*DT;
    size_t so = ((size_t)kv*64 + bh)*Dc;
    int tb = t0 + lane*4;
#pragma unroll 1
    for (int rr = 0; rr < 16; rr++) {
        int d = warp*16 + rr;
        float4 v = *(float4*)&Cs[d*132 + lane*4];
        v.x = (tb+0 < Tc) ? v.x : 0.f;
        v.y = (tb+1 < Tc) ? v.y : 0.f;
        v.z = (tb+2 < Tc) ? v.z : 0.f;
        v.w = (tb+3 < Tc) ? v.w : 0.f;
        __nv_bfloat162 h01 = __floats2bfloat162_rn(v.x, v.y);
        __nv_bfloat162 h23 = __floats2bfloat162_rn(v.z, v.w);
        unsigned uh01 = *(unsigned*)&h01, uh23 = *(unsigned*)&h23;
        float f0 = __int_as_float(uh01 << 16);
        float f1 = __int_as_float(uh01 & 0xffff0000u);
        float f2 = __int_as_float(uh23 << 16);
        float f3 = __int_as_float(uh23 & 0xffff0000u);
        __nv_bfloat162 l01 = __floats2bfloat162_rn(v.x - f0, v.y - f1);
        __nv_bfloat162 l23 = __floats2bfloat162_rn(v.z - f2, v.w - f3);
        *(uint2*)(Phi + (size_t)d*TP + tb) = make_uint2(uh01, uh23);
        *(uint2*)(Plo + (size_t)d*TP + tb) = make_uint2(*(unsigned*)&l01, *(unsigned*)&l23);
        float p1 = v.x + v.y + v.z + v.w;
        float p2 = v.x*v.x + v.y*v.y + v.z*v.z + v.w*v.w;
        for (int off = 16; off; off >>= 1) {
            p1 += __shfl_down_sync(~0u, p1, off);
            p2 += __shfl_down_sync(~0u, p2, off);
        }
        if (lane == 0) {
            atomicAdd(&g_s1[so + d], p1);
            atomicAdd(&g_s2[so + d], p2);
        }
    }
}

// ---------------- fused stage 3: attention (blocks 0..63) + S=K^T V (blocks 64..191) ----------------
#define NCHS 16

__device__ __forceinline__ void prefetch_smat(
    int c, int stage, uint32_t sb, int tid,
    const __nv_bfloat16* __restrict__ Ahi, const __nv_bfloat16* __restrict__ Alo,
    const __nv_bfloat16* __restrict__ Bhi, const __nv_bfloat16* __restrict__ Blo) {
    int kc = c*32;
    uint32_t stb = sb + stage*GSTG;
#pragma unroll
    for (int it = 0; it < 8; it++) {
        int idx = tid + it*256;
        int plane = idx >> 9;
        int row = (idx >> 2) & 127;
        int seg = idx & 3;
        uint32_t dst = stb + plane*GA_PL + row*64 + (((seg ^ ((row >> 1) & 3))) << 4);
        const __nv_bfloat16* src =
            (plane == 0 ? Ahi : plane == 1 ? Alo : plane == 2 ? Bhi : Blo)
            + (size_t)row*TP + kc + seg*8;
        asm volatile("cp.async.cg.shared.global [%0], [%1], 16;" :: "r"(dst), "l"(src));
    }
    CP_COMMIT();
}

__global__ __launch_bounds__(256, 2) void k_as(const float* __restrict__ q) {
    extern __shared__ __align__(1024) char dynsmem[];
    int tid = threadIdx.x;

    if (blockIdx.x < 64) {
        // ---------- attention branch ----------
        float* s_sc  = (float*)dynsmem;
        float* s_red = s_sc + TP;
        float* s_q   = s_red + 256;
        int bh = blockIdx.x;
        int h = bh & 7;
        const __nv_bfloat16* Khi = g_chi + (size_t)bh*DT;
        const __nv_bfloat16* Klo = g_clo + (size_t)bh*DT;
        const __nv_bfloat16* Vhi = g_chi + (size_t)(64 + bh)*DT;
        const __nv_bfloat16* Vlo = g_clo + (size_t)(64 + bh)*DT;
        if (tid < Dc) s_q[tid] = q[h*Dc + tid];
        __syncthreads();

        if (tid < 250) {
            float a0 = 0.f, a1 = 0.f, a2 = 0.f, a3 = 0.f;
#pragma unroll 8
            for (int d = 0; d < Dc; d++) {
                uint2 ph = *(const uint2*)(Khi + (size_t)d*TP + tid*4);
                uint2 pl = *(const uint2*)(Klo + (size_t)d*TP + tid*4);
                float qd = s_q[d];
                float4 kv4 = un4(ph, pl);
                a0 += qd*kv4.x; a1 += qd*kv4.y; a2 += qd*kv4.z; a3 += qd*kv4.w;
            }
            const float sc = 0.08838834764831845f;
            *(float4*)&s_sc[tid*4] = make_float4(a0*sc, a1*sc, a2*sc, a3*sc);
        }
        if (tid < 24) s_sc[1000 + tid] = 0.f;
        __syncthreads();

        float lm = -1e30f;
        for (int t = tid; t < Tc; t += 256) lm = fmaxf(lm, s_sc[t]);
        s_red[tid] = lm; __syncthreads();
        for (int s = 128; s; s >>= 1) { if (tid < s) s_red[tid] = fmaxf(s_red[tid], s_red[tid+s]); __syncthreads(); }
        float m = s_red[0];
        __syncthreads();
        float ls = 0.f;
        for (int t = tid; t < Tc; t += 256) { float e = expf(s_sc[t]-m); s_sc[t] = e; ls += e; }
        s_red[tid] = ls; __syncthreads();
        for (int s = 128; s; s >>= 1) { if (tid < s) s_red[tid] += s_red[tid+s]; __syncthreads(); }
        float inv = 1.f / s_red[0];
        __syncthreads();

        int w = tid >> 5, lane = tid & 31;
#pragma unroll 1
        for (int rr = 0; rr < 16; rr++) {
            int d = w*16 + rr;
            float acc = 0.f;
#pragma unroll
            for (int cc = 0; cc < 8; cc++) {
                int grp = lane + cc*32;
                uint2 ph = *(const uint2*)(Vhi + (size_t)d*TP + grp*4);
                uint2 pl = *(const uint2*)(Vlo + (size_t)d*TP + grp*4);
                float4 vv = un4(ph, pl);
                float4 aa = *(float4*)&s_sc[grp*4];
                acc += aa.x*vv.x + aa.y*vv.y + aa.z*vv.z + aa.w*vv.w;
            }
            for (int off = 16; off; off >>= 1) acc += __shfl_down_sync(~0u, acc, off);
            if (lane == 0) g_o1[bh*Dc + d] = acc * inv;
        }
        return;
    }

    // ---------- S = K^T V branch (XOR-swizzled 3-stage) ----------
    uint32_t sb = smem_u32(dynsmem);
    int warp = tid >> 5, lane = tid & 31;
    int job = blockIdx.x - 64;
    int bh = job >> 1;
    int seg = job & 1;
    const __nv_bfloat16* Ahi = g_chi + (size_t)bh*DT + seg*512;
    const __nv_bfloat16* Alo = g_clo + (size_t)bh*DT + seg*512;
    const __nv_bfloat16* Bhi = g_chi + (size_t)(64 + bh)*DT + seg*512;
    const __nv_bfloat16* Blo = g_clo + (size_t)(64 + bh)*DT + seg*512;

    int m0w = (warp >> 1)*32;
    int n0w = (warp & 1)*64;
    int arow = (lane & 7) + ((lane >> 3) & 1)*8;
    int abit = (lane >> 4) & 1;
    int brow = (lane & 7) + ((lane >> 4) & 1)*8;
    int bbit = (lane >> 3) & 1;

    float acc[2][8][4];
#pragma unroll
    for (int i = 0; i < 2; i++)
#pragma unroll
        for (int j = 0; j < 8; j++)
#pragma unroll
            for (int r = 0; r < 4; r++) acc[i][j][r] = 0.f;

    prefetch_smat(0, 0, sb, tid, Ahi, Alo, Bhi, Blo);
    prefetch_smat(1, 1, sb, tid, Ahi, Alo, Bhi, Blo);

#pragma unroll 1
    for (int c = 0; c < NCHS; c++) {
        if (c < NCHS-1) CP_WAIT(1); else CP_WAIT(0);
        __syncthreads();
        if (c + 2 < NCHS)
            prefetch_smat(c+2, (c+2)%3, sb, tid, Ahi, Alo, Bhi, Blo);

        uint32_t st = sb + (c%3)*GSTG;
#pragma unroll
        for (int ks = 0; ks < 2; ks++) {
            unsigned ah[2][4], al[2][4];
#pragma unroll
            for (int mi = 0; mi < 2; mi++) {
                int rA = m0w + mi*16 + arow;
                uint32_t a0 = st + (uint32_t)(rA*64 + (((ks*2 + abit) ^ ((rA >> 1) & 3)) << 4));
                LDSM4(ah[mi][0], ah[mi][1], ah[mi][2], ah[mi][3], a0);
                LDSM4(al[mi][0], al[mi][1], al[mi][2], al[mi][3], a0 + GA_PL);
            }
#pragma unroll
            for (int ni = 0; ni < 4; ni++) {
                int rB = n0w + ni*16 + brow;
                uint32_t b0 = st + 2*GA_PL + (uint32_t)(rB*64 + (((ks*2 + bbit) ^ ((rB >> 1) & 3)) << 4));
                unsigned bhv[4], blv[4];
                LDSM4(bhv[0], bhv[1], bhv[2], bhv[3], b0);
                LDSM4(blv[0], blv[1], blv[2], blv[3], b0 + GA_PL);
#pragma unroll
                for (int mi = 0; mi < 2; mi++)
#pragma unroll
                    for (int j2 = 0; j2 < 2; j2++) {
                        int nj = ni*2 + j2;
                        MMA_BF16(acc[mi][nj], ah[mi], &bhv[j2*2]);
                        MMA_BF16(acc[mi][nj], ah[mi], &blv[j2*2]);
                        MMA_BF16(acc[mi][nj], al[mi], &bhv[j2*2]);
                    }
            }
        }
    }

    float* Sp = g_S + (size_t)bh*Dc*Dc;
    int g = lane >> 2, q4 = lane & 3;
#pragma unroll
    for (int nj = 0; nj < 8; nj++) {
        int l = n0w + nj*8 + q4*2;
#pragma unroll
        for (int mi = 0; mi < 2; mi++) {
            int k0 = m0w + mi*16 + g;
            atomicAdd(&Sp[k0*Dc + l],       acc[mi][nj][0]);
            atomicAdd(&Sp[k0*Dc + l + 1],   acc[mi][nj][1]);
            atomicAdd(&Sp[(k0+8)*Dc + l],   acc[mi][nj][2]);
            atomicAdd(&Sp[(k0+8)*Dc + l+1], acc[mi][nj][3]);
        }
    }
}

// ---------------- stats finalize + outs init ----------------
__global__ void k_statfin(const float* __restrict__ bproj) {
    int bid = blockIdx.x;
    int tid = threadIdx.x;
    if (bid < 64) {
        int kv = tid >> 7;
        int d = tid & 127;
        size_t o = ((size_t)kv*64 + bid)*Dc + d;
        float s1 = g_s1[o], s2 = g_s2[o];
        float mu = s1 * (1.f/Tc);
        float var = (s2 - (float)Tc*mu*mu) * (1.f/(Tc-1));
        var = fmaxf(var, 0.f);
        float sd = sqrtf(var) + 1e-9f;
        if (kv == 0) { g_muk[bid*Dc + d] = mu; g_sdk[bid*Dc + d] = sd; }
        else         { g_muv[bid*Dc + d] = mu; g_sdv[bid*Dc + d] = sd; }
    } else {
        for (int i = tid; i < Bc*Hc*Ec; i += 256)
            g_outs[i] = bproj[i & (Hc*Ec - 1)];
    }
}

// ---------------- stage 3c: normalized correlation ----------------
__global__ void k_corr() {
    int c = blockIdx.x*256 + threadIdx.x;
    int bh = blockIdx.y;
    if (c >= DCORR) return;
    float disc = 65025.0f - 8.0f*(float)c;
    int k = (int)((255.0f - sqrtf(disc))*0.5f);
    if (k < 0) k = 0;
    if (k > 126) k = 126;
    while (k > 0 && k*(255-k)/2 > c) k--;
    while ((k+1)*(254-k)/2 <= c) k++;
    int l = k + 1 + (c - k*(255-k)/2);
    float muk = g_muk[bh*Dc + k], sdk = g_sdk[bh*Dc + k];
    float muv = g_muv[bh*Dc + l], sdv = g_sdv[bh*Dc + l];
    float S = g_S[(size_t)bh*Dc*Dc + k*Dc + l];
    g_corr[(size_t)bh*DCORR + c] = (S - (float)Tc*muk*muv) / ((float)Tc*sdk*sdv);
}

// ---------------- stage 4: outs += corr . Wproj (warp-per-e, coalesced) ----------------
// grid (E/8, H, 4), block 256 = 8 warps; warp w owns e = bx*8 + w; lanes stride c.
__global__ __launch_bounds__(256) void k_proj(const float* __restrict__ Wproj) {
    __shared__ float sc[8][132];     // [b][c-chunk]
    int tid = threadIdx.x;
    int warp = tid >> 5, lane = tid & 31;
    int h = blockIdx.y;
    int cs = blockIdx.z;
    int e = blockIdx.x*8 + warp;
    int start = cs*2032;
    const float* wrow = Wproj + ((size_t)h*Ec + e)*DCORR;
    float acc[8];
#pragma unroll
    for (int b = 0; b < 8; b++) acc[b] = 0.f;

#pragma unroll 1
    for (int c0 = start; c0 < start + 2032; c0 += 128) {
        int lim = start + 2032 - c0; if (lim > 128) lim = 128;
        // stage corr chunk: warp w loads b = w's slice (coalesced float4)
        {
            float4 cv = make_float4(0.f,0.f,0.f,0.f);
            if (lane*4 < lim)
                cv = *(const float4*)(g_corr + ((size_t)warp*Hc + h)*DCORR + c0 + lane*4);
            *(float4*)&sc[warp][lane*4] = cv;
        }
        __syncthreads();
        float4 wv = make_float4(0.f,0.f,0.f,0.f);
        if (lane*4 < lim) wv = *(const float4*)(wrow + c0 + lane*4);
#pragma unroll
        for (int b = 0; b < 8; b++) {
            float4 sv = *(float4*)&sc[b][lane*4];
            acc[b] += wv.x*sv.x + wv.y*sv.y + wv.z*sv.z + wv.w*sv.w;
        }
        __syncthreads();
    }
#pragma unroll
    for (int b = 0; b < 8; b++) {
        float a = acc[b];
        for (int off = 16; off; off >>= 1) a += __shfl_down_sync(~0u, a, off);
        if (lane == 0) atomicAdd(&g_outs[b*(Hc*Ec) + h*Ec + e], a);
    }
}

// ---------------- stage 5: final linears + mix ----------------
__global__ __launch_bounds__(256) void k_final(
    const float* __restrict__ WT, const float* __restrict__ bT,
    const float* __restrict__ Wp, const float* __restrict__ bp,
    float* __restrict__ out) {
    __shared__ float so1[Hc*Dc];
    __shared__ float sout[Hc*Ec];
    __shared__ float sred[256];
    int b = blockIdx.x, ec = blockIdx.y;
    int tid = threadIdx.x;
    for (int j = tid; j < Hc*Dc; j += 256) so1[j]  = g_o1[b*Hc*Dc + j];
    for (int j = tid; j < Hc*Ec; j += 256) sout[j] = g_outs[b*Hc*Ec + j];
    __syncthreads();
    int e_l = tid >> 3, js = tid & 7;
    int e = ec*32 + e_l;
    float a = 0.f;
    const float* wt = WT + (size_t)e*(Hc*Dc) + js*128;
    const float* s1p = so1 + js*128;
#pragma unroll 4
    for (int j = 0; j < 128; j += 4) {
        float4 wv = *(const float4*)(wt + j);
        float4 sv = *(const float4*)(s1p + j);
        a += wv.x*sv.x + wv.y*sv.y + wv.z*sv.z + wv.w*sv.w;
    }
    const float* wp = Wp + (size_t)e*(Hc*Ec) + js*256;
    const float* s2p = sout + js*256;
#pragma unroll 4
    for (int j = 0; j < 256; j += 4) {
        float4 wv = *(const float4*)(wp + j);
        float4 sv = *(const float4*)(s2p + j);
        a += wv.x*sv.x + wv.y*sv.y + wv.z*sv.z + wv.w*sv.w;
    }
    if (js == 0) a += bT[e] + bp[e];
    sred[tid] = a;
    __syncthreads();
    if (tid < 32) {
        float s = 0.f;
#pragma unroll
        for (int k = 0; k < 8; k++) s += sred[tid*8 + k];
        out[b*Ec + ec*32 + tid] = 0.5f*s;
    }
}

// ---------------- launch ----------------
extern "C" void kernel_launch(void* const* d_in, const int* in_sizes, int n_in,
                              void* d_out, int out_size) {
    const float* x     = (const float*)d_in[0];
    const float* wk    = (const float*)d_in[1];
    const float* wv    = (const float*)d_in[2];
    const float* q     = (const float*)d_in[3];
    const float* Wk    = (const float*)d_in[4];
    const float* bk    = (const float*)d_in[5];
    const float* Wv    = (const float*)d_in[6];
    const float* bv    = (const float*)d_in[7];
    const float* Wproj = (const float*)d_in[8];
    const float* bproj = (const float*)d_in[9];
    const float* WT    = (const float*)d_in[10];
    const float* bT    = (const float*)d_in[11];
    const float* Wp    = (const float*)d_in[12];
    const float* bp    = (const float*)d_in[13];
    float* out = (float*)d_out;

    cudaFuncSetAttribute(k_gemm, cudaFuncAttributeMaxDynamicSharedMemorySize, GSM);
    cudaFuncSetAttribute(k_as,   cudaFuncAttributeMaxDynamicSharedMemorySize, GSM);

    k_initw<<<dim3(3072, 2), 256>>>(wk, wv, Wk, Wv);
    k_raw<<<dim3(16, Fc/16, Bc), dim3(16, 8)>>>(x);
    k_gemm<<<dim3(8, Bc*Hc, 2), 256, GSM>>>(bk, bv);
    k_as<<<192, 256, GSM>>>(q);
    k_statfin<<<65, 256>>>(bproj);
    k_corr<<<dim3((DCORR+255)/256, Bc*Hc), 256>>>();
    k_proj<<<dim3(Ec/8, Hc, 4), 256>>>(Wproj);
    k_final<<<dim3(Bc, Ec/32), 256>>>(WT, bT, Wp, bp, out);
}

// round 16
// speedup vs baseline: 1.5222x; 1.0126x over previous
#include <cuda_runtime.h>
#include <cuda_bf16.h>
#include <math.h>
#include <stdint.h>

// Problem constants
#define Bc 8
#define Hc 8
#define Fc 768
#define Dc 128
#define Ec 256
#define Lc 13
#define Tc 1000
#define DCORR 8128
#define TP 1024                 // padded T
#define DT (128*TP)             // plane size per (kv,bh)

// ---------------- device scratch ----------------
__device__ float g_kw[Hc*Lc];
__device__ float g_vw[Hc*Lc];
__device__ __nv_bfloat16 g_ahi[(size_t)2*Bc*Hc*Tc*Fc];   // raw activations [kv][bh][t][f]
__device__ __nv_bfloat16 g_alo[(size_t)2*Bc*Hc*Tc*Fc];
__device__ __nv_bfloat16 g_whi[(size_t)2*Hc*Dc*Fc];      // weights [kv][h][d][f]
__device__ __nv_bfloat16 g_wlo[(size_t)2*Hc*Dc*Fc];
__device__ __nv_bfloat16 g_chi[(size_t)2*Bc*Hc*DT];      // GEMM out planes [kv][bh][d][t]
__device__ __nv_bfloat16 g_clo[(size_t)2*Bc*Hc*DT];
__device__ float g_s1[2*Bc*Hc*Dc];
__device__ float g_s2[2*Bc*Hc*Dc];
__device__ float g_muk[Bc*Hc*Dc];
__device__ float g_sdk[Bc*Hc*Dc];
__device__ float g_muv[Bc*Hc*Dc];
__device__ float g_sdv[Bc*Hc*Dc];
__device__ float g_o1[Bc*Hc*Dc];
__device__ float g_S[(size_t)Bc*Hc*Dc*Dc];
__device__ float g_corr[(size_t)Bc*Hc*DCORR];
__device__ float g_outs[Bc*Hc*Ec];

__device__ __forceinline__ uint32_t smem_u32(const void* p) {
    uint32_t a;
    asm("{ .reg .u64 t; cvta.to.shared.u64 t, %1; cvt.u32.u64 %0, t; }" : "=r"(a) : "l"(p));
    return a;
}
#define CP_COMMIT()  asm volatile("cp.async.commit_group;" ::: "memory")
#define CP_WAIT(n)   asm volatile("cp.async.wait_group %0;" :: "n"(n) : "memory")
#define LDSM4(r0, r1, r2, r3, a) \
    asm volatile("ldmatrix.sync.aligned.m8n8.x4.shared.b16 {%0,%1,%2,%3}, [%4];" \
        : "=r"(r0), "=r"(r1), "=r"(r2), "=r"(r3) : "r"(a))
#define MMA_BF16(d, a, b) asm volatile( \
    "mma.sync.aligned.m16n8k16.row.col.f32.bf16.bf16.f32 " \
    "{%0,%1,%2,%3},{%4,%5,%6,%7},{%8,%9},{%0,%1,%2,%3};\n" \
    : "+f"((d)[0]), "+f"((d)[1]), "+f"((d)[2]), "+f"((d)[3]) \
    : "r"((a)[0]), "r"((a)[1]), "r"((a)[2]), "r"((a)[3]), "r"((b)[0]), "r"((b)[1]))

// hi+lo bf16 reconstruction of 4 packed values
__device__ __forceinline__ float4 un4(uint2 h, uint2 l) {
    float4 r;
    r.x = __int_as_float(h.x << 16)        + __int_as_float(l.x << 16);
    r.y = __int_as_float(h.x & 0xffff0000u) + __int_as_float(l.x & 0xffff0000u);
    r.z = __int_as_float(h.y << 16)        + __int_as_float(l.y << 16);
    r.w = __int_as_float(h.y & 0xffff0000u) + __int_as_float(l.y & 0xffff0000u);
    return r;
}

// ---------------- stage 0: init + softmax + W pack (merged) ----------------
__global__ void k_initw(const float* __restrict__ wk, const float* __restrict__ wv,
                        const float* __restrict__ Wk, const float* __restrict__ Wv) {
    int tid = threadIdx.x;
    size_t i = (size_t)blockIdx.x*256 + tid;
    const float* W = blockIdx.y ? Wv : Wk;
    float v = W[i];
    __nv_bfloat16 h16 = __float2bfloat16(v);
    __nv_bfloat16 l16 = __float2bfloat16(v - __bfloat162float(h16));
    size_t o = (size_t)blockIdx.y*(Hc*Dc*Fc) + i;
    g_whi[o] = h16;
    g_wlo[o] = l16;

    if (blockIdx.y == 0 && blockIdx.x < 1056) {
        int j = blockIdx.x*256 + tid;
        float4 z = make_float4(0.f,0.f,0.f,0.f);
        if (j < 262144) ((float4*)g_S)[j] = z;
        else {
            int k = j - 262144;
            if (k < 4096) ((float4*)g_s1)[k] = z;
            else ((float4*)g_s2)[k - 4096] = z;
        }
    }
    if (blockIdx.x == 0 && blockIdx.y == 0 && tid < 2*Hc) {
        int h = tid % Hc;
        const float* src = (tid < Hc ? wk : wv) + h*Lc;
        float* dst = (tid < Hc ? g_kw : g_vw) + h*Lc;
        float m = -1e30f;
        for (int l = 0; l < Lc; l++) m = fmaxf(m, src[l]);
        float e[Lc]; float s = 0.f;
        for (int l = 0; l < Lc; l++) { e[l] = expf(src[l]-m); s += e[l]; }
        float inv = 1.f/s;
        for (int l = 0; l < Lc; l++) dst[l] = e[l]*inv;
    }
}

// ---------------- stage 1: L-contraction -> bf16 hi/lo [t][f] ----------------
__global__ __launch_bounds__(128) void k_raw(const float* __restrict__ x) {
    __shared__ float2 skv[Hc*Lc];
    __shared__ float xs[2][16][212];
    __shared__ __align__(8) unsigned s_ohi[2][Hc][16][10];
    __shared__ __align__(8) unsigned s_olo[2][Hc][16][10];
    int tx = threadIdx.x;
    int ty = threadIdx.y;
    int tid = ty*16 + tx;
    if (tid < Hc*Lc) skv[tid] = make_float2(g_kw[tid], g_vw[tid]);

    int tbase = blockIdx.x*64;
    int f0 = blockIdx.y*16;
    int b  = blockIdx.z;
    const float* xb = x + (size_t)(b*Fc + f0)*Tc*13;

    auto stage_x = [&](int buf, int st0) {
        int n = Tc - st0;
        int maxf4 = (n >= 16) ? 52 : (n > 0 ? ((n*13) >> 2) : 0);
        unsigned tbeg = (unsigned)st0*13u;
#pragma unroll
        for (int it = 0; it < 7; it++) {
            int idx = tid + it*128;
            if (idx < 832) {
                int row = idx / 52, col = idx % 52;
                unsigned sz = (col < maxf4) ? 16u : 0u;
                int scol = (col < maxf4) ? col : 0;
                uint32_t dst = smem_u32(&xs[buf][row][col*4]);
                const float* src = xb + (unsigned)row*13000u + tbeg + (unsigned)scol*4u;
                asm volatile("cp.async.cg.shared.global [%0], [%1], 16, %2;"
                             :: "r"(dst), "l"(src), "r"(sz));
            }
        }
        CP_COMMIT();
    };

    stage_x(0, tbase);

#pragma unroll 1
    for (int s = 0; s < 4; s++) {
        int st0 = tbase + s*16;
        if (s < 3) { stage_x((s+1) & 1, st0 + 16); CP_WAIT(1); }
        else CP_WAIT(0);
        __syncthreads();

        int buf = s & 1;
        float xv0[Lc], xv1[Lc];
#pragma unroll
        for (int l = 0; l < Lc; l++) {
            xv0[l] = xs[buf][ty*2][tx*13 + l];
            xv1[l] = xs[buf][ty*2 + 1][tx*13 + l];
        }

#pragma unroll
        for (int h = 0; h < Hc; h++) {
            float k0 = 0.f, v0 = 0.f, k1 = 0.f, v1 = 0.f;
#pragma unroll
            for (int l = 0; l < Lc; l++) {
                float2 w = skv[h*Lc + l];
                k0 += xv0[l]*w.x; v0 += xv0[l]*w.y;
                k1 += xv1[l]*w.x; v1 += xv1[l]*w.y;
            }
            {
                unsigned b0 = __float_as_uint(k0), b1 = __float_as_uint(k1);
                unsigned hiw = __byte_perm(b0, b1, 0x7632);
                float d0 = k0 - __uint_as_float(b0 & 0xffff0000u);
                float d1 = k1 - __uint_as_float(b1 & 0xffff0000u);
                unsigned low;
                asm("cvt.rn.bf16x2.f32 %0, %1, %2;" : "=r"(low) : "f"(d1), "f"(d0));
                s_ohi[0][h][tx][ty] = hiw;
                s_olo[0][h][tx][ty] = low;
            }
            {
                unsigned b0 = __float_as_uint(v0), b1 = __float_as_uint(v1);
                unsigned hiw = __byte_perm(b0, b1, 0x7632);
                float d0 = v0 - __uint_as_float(b0 & 0xffff0000u);
                float d1 = v1 - __uint_as_float(b1 & 0xffff0000u);
                unsigned low;
                asm("cvt.rn.bf16x2.f32 %0, %1, %2;" : "=r"(low) : "f"(d1), "f"(d0));
                s_ohi[1][h][tx][ty] = hiw;
                s_olo[1][h][tx][ty] = low;
            }
        }
        __syncthreads();

        // write phase: 32-bit offset math (element offsets < 2^27)
        int w = tid >> 5, lane = tid & 31;
        int f4 = lane & 3;
        int tq = lane >> 2;
        unsigned foff = (unsigned)f0 + (unsigned)(f4*4);
#pragma unroll
        for (int it = 0; it < 4; it++) {
            int job = w*4 + it;
            int kv = job >> 3;
            int h = job & 7;
            unsigned rowbase = ((unsigned)(kv*Bc + b)*Hc + (unsigned)h)*(unsigned)Tc + (unsigned)st0;
            unsigned base0 = (rowbase + (unsigned)tq)*(unsigned)Fc + foff;
#pragma unroll
            for (int ti = 0; ti < 2; ti++) {
                int tl = ti*8 + tq;
                if (st0 + tl < Tc) {
                    unsigned off = base0 + (unsigned)(ti*8*Fc);
                    *(uint2*)(g_ahi + off) = *(uint2*)&s_ohi[kv][h][tl][f4*2];
                    *(uint2*)(g_alo + off) = *(uint2*)&s_olo[kv][h][tl][f4*2];
                }
            }
        }
        __syncthreads();
    }
}

// ---------------- stage 2: GEMM 128x128, XOR-swizzled smem, 3-stage ----------------
#define GA_PL 8192
#define GSTG (4*GA_PL)
#define GSM (3*GSTG)
#define NCH (Fc/32)

__device__ __forceinline__ void prefetch_g(
    int c, int stage, uint32_t sb, int t0, int tid,
    const __nv_bfloat16* __restrict__ Ahi, const __nv_bfloat16* __restrict__ Alo,
    const __nv_bfloat16* __restrict__ Bhi, const __nv_bfloat16* __restrict__ Blo) {
    int kc = c*32;
    uint32_t stb = sb + stage*GSTG;
#pragma unroll
    for (int it = 0; it < 8; it++) {
        int idx = tid + it*256;
        int plane = idx >> 9;
        int row = (idx >> 2) & 127;
        int seg = idx & 3;
        uint32_t dst = stb + plane*GA_PL + row*64 + (((seg ^ ((row >> 1) & 3))) << 4);
        const __nv_bfloat16* src;
        unsigned sz = 16;
        if (plane < 2) {
            int t = t0 + row;
            if (t >= Tc) { t = 0; sz = 0; }
            src = (plane ? Alo : Ahi) + (size_t)t*Fc + kc + seg*8;
        } else {
            src = (plane == 2 ? Bhi : Blo) + (size_t)row*Fc + kc + seg*8;
        }
        asm volatile("cp.async.cg.shared.global [%0], [%1], 16, %2;"
                     :: "r"(dst), "l"(src), "r"(sz));
    }
    CP_COMMIT();
}

__global__ __launch_bounds__(256, 2) void k_gemm(
    const float* __restrict__ bk, const float* __restrict__ bv) {
    extern __shared__ __align__(1024) char dynsmem[];
    uint32_t sb = smem_u32(dynsmem);

    int tid = threadIdx.x;
    int warp = tid >> 5, lane = tid & 31;
    int bh = blockIdx.y;
    int h = bh & 7;
    int kv = blockIdx.z;
    int t0 = blockIdx.x*128;

    const __nv_bfloat16* Ahi = g_ahi + (size_t)(kv*Bc*Hc + bh)*Tc*Fc;
    const __nv_bfloat16* Alo = g_alo + (size_t)(kv*Bc*Hc + bh)*Tc*Fc;
    const __nv_bfloat16* Bhi = g_whi + (size_t)(kv*Hc + h)*Dc*Fc;
    const __nv_bfloat16* Blo = g_wlo + (size_t)(kv*Hc + h)*Dc*Fc;
    const float* bias = (kv ? bv : bk) + h*Dc;

    int m0w = (warp >> 1)*32;
    int n0w = (warp & 1)*64;
    int arow = (lane & 7) + ((lane >> 3) & 1)*8;
    int abit = (lane >> 4) & 1;
    int brow = (lane & 7) + ((lane >> 4) & 1)*8;
    int bbit = (lane >> 3) & 1;

    float acc[2][8][4];
#pragma unroll
    for (int i = 0; i < 2; i++)
#pragma unroll
        for (int j = 0; j < 8; j++)
#pragma unroll
            for (int r = 0; r < 4; r++) acc[i][j][r] = 0.f;

    prefetch_g(0, 0, sb, t0, tid, Ahi, Alo, Bhi, Blo);
    prefetch_g(1, 1, sb, t0, tid, Ahi, Alo, Bhi, Blo);

#pragma unroll 1
    for (int c = 0; c < NCH; c++) {
        if (c < NCH-1) CP_WAIT(1); else CP_WAIT(0);
        __syncthreads();
        if (c + 2 < NCH)
            prefetch_g(c+2, (c+2)%3, sb, t0, tid, Ahi, Alo, Bhi, Blo);

        uint32_t st = sb + (c%3)*GSTG;
#pragma unroll
        for (int ks = 0; ks < 2; ks++) {
            unsigned ah[2][4], al[2][4];
#pragma unroll
            for (int mi = 0; mi < 2; mi++) {
                int rA = m0w + mi*16 + arow;
                uint32_t a0 = st + (uint32_t)(rA*64 + (((ks*2 + abit) ^ ((rA >> 1) & 3)) << 4));
                LDSM4(ah[mi][0], ah[mi][1], ah[mi][2], ah[mi][3], a0);
                LDSM4(al[mi][0], al[mi][1], al[mi][2], al[mi][3], a0 + GA_PL);
            }
#pragma unroll
            for (int ni = 0; ni < 4; ni++) {
                int rB = n0w + ni*16 + brow;
                uint32_t b0 = st + 2*GA_PL + (uint32_t)(rB*64 + (((ks*2 + bbit) ^ ((rB >> 1) & 3)) << 4));
                unsigned bhv[4], blv[4];
                LDSM4(bhv[0], bhv[1], bhv[2], bhv[3], b0);
                LDSM4(blv[0], blv[1], blv[2], blv[3], b0 + GA_PL);
#pragma unroll
                for (int mi = 0; mi < 2; mi++)
#pragma unroll
                    for (int j2 = 0; j2 < 2; j2++) {
                        int nj = ni*2 + j2;
                        MMA_BF16(acc[mi][nj], ah[mi], &bhv[j2*2]);
                        MMA_BF16(acc[mi][nj], ah[mi], &blv[j2*2]);
                        MMA_BF16(acc[mi][nj], al[mi], &bhv[j2*2]);
                    }
            }
        }
    }

    // epilogue: transpose through smem to [d][t], emit bf16 hi/lo planes + stats
    __syncthreads();
    float* Cs = (float*)dynsmem;           // [128 d][132]
    int g = lane >> 2, q = lane & 3;
#pragma unroll
    for (int nj = 0; nj < 8; nj++) {
        int d = n0w + nj*8 + q*2;
        float2 bb = *(const float2*)(bias + d);
#pragma unroll
        for (int mi = 0; mi < 2; mi++) {
            int r = m0w + mi*16 + g;
            Cs[d*132 + r]         = acc[mi][nj][0] + bb.x;
            Cs[(d+1)*132 + r]     = acc[mi][nj][1] + bb.y;
            Cs[d*132 + r + 8]     = acc[mi][nj][2] + bb.x;
            Cs[(d+1)*132 + r + 8] = acc[mi][nj][3] + bb.y;
        }
    }
    __syncthreads();

    __nv_bfloat16* Phi = g_chi + ((size_t)kv*64 + bh)*DT;
    __nv_bfloat16* Plo = g_clo + ((size_t)kv*64 + bh)*DT;
    size_t so = ((size_t)kv*64 + bh)*Dc;
    int tb = t0 + lane*4;
#pragma unroll 1
    for (int rr = 0; rr < 16; rr++) {
        int d = warp*16 + rr;
        float4 v = *(float4*)&Cs[d*132 + lane*4];
        v.x = (tb+0 < Tc) ? v.x : 0.f;
        v.y = (tb+1 < Tc) ? v.y : 0.f;
        v.z = (tb+2 < Tc) ? v.z : 0.f;
        v.w = (tb+3 < Tc) ? v.w : 0.f;
        __nv_bfloat162 h01 = __floats2bfloat162_rn(v.x, v.y);
        __nv_bfloat162 h23 = __floats2bfloat162_rn(v.z, v.w);
        unsigned uh01 = *(unsigned*)&h01, uh23 = *(unsigned*)&h23;
        float f0 = __int_as_float(uh01 << 16);
        float f1 = __int_as_float(uh01 & 0xffff0000u);
        float f2 = __int_as_float(uh23 << 16);
        float f3 = __int_as_float(uh23 & 0xffff0000u);
        __nv_bfloat162 l01 = __floats2bfloat162_rn(v.x - f0, v.y - f1);
        __nv_bfloat162 l23 = __floats2bfloat162_rn(v.z - f2, v.w - f3);
        *(uint2*)(Phi + (size_t)d*TP + tb) = make_uint2(uh01, uh23);
        *(uint2*)(Plo + (size_t)d*TP + tb) = make_uint2(*(unsigned*)&l01, *(unsigned*)&l23);
        float p1 = v.x + v.y + v.z + v.w;
        float p2 = v.x*v.x + v.y*v.y + v.z*v.z + v.w*v.w;
        for (int off = 16; off; off >>= 1) {
            p1 += __shfl_down_sync(~0u, p1, off);
            p2 += __shfl_down_sync(~0u, p2, off);
        }
        if (lane == 0) {
            atomicAdd(&g_s1[so + d], p1);
            atomicAdd(&g_s2[so + d], p2);
        }
    }
}

// ---------------- fused stage 3: attn (0..63) + S=K^T V (64..191) + statfin (192..256) ----------------
#define NCHS 16

__device__ __forceinline__ void prefetch_smat(
    int c, int stage, uint32_t sb, int tid,
    const __nv_bfloat16* __restrict__ Ahi, const __nv_bfloat16* __restrict__ Alo,
    const __nv_bfloat16* __restrict__ Bhi, const __nv_bfloat16* __restrict__ Blo) {
    int kc = c*32;
    uint32_t stb = sb + stage*GSTG;
#pragma unroll
    for (int it = 0; it < 8; it++) {
        int idx = tid + it*256;
        int plane = idx >> 9;
        int row = (idx >> 2) & 127;
        int seg = idx & 3;
        uint32_t dst = stb + plane*GA_PL + row*64 + (((seg ^ ((row >> 1) & 3))) << 4);
        const __nv_bfloat16* src =
            (plane == 0 ? Ahi : plane == 1 ? Alo : plane == 2 ? Bhi : Blo)
            + (size_t)row*TP + kc + seg*8;
        asm volatile("cp.async.cg.shared.global [%0], [%1], 16;" :: "r"(dst), "l"(src));
    }
    CP_COMMIT();
}

__global__ __launch_bounds__(256, 2) void k_as(const float* __restrict__ q,
                                               const float* __restrict__ bproj) {
    extern __shared__ __align__(1024) char dynsmem[];
    int tid = threadIdx.x;

    if (blockIdx.x >= 192) {
        // ---------- statfin branch (depends only on k_gemm stats + bproj) ----------
        int bid = blockIdx.x - 192;         // 0..64
        if (bid < 64) {
            int kv = tid >> 7;
            int d = tid & 127;
            size_t o = ((size_t)kv*64 + bid)*Dc + d;
            float s1 = g_s1[o], s2 = g_s2[o];
            float mu = s1 * (1.f/Tc);
            float var = (s2 - (float)Tc*mu*mu) * (1.f/(Tc-1));
            var = fmaxf(var, 0.f);
            float sd = sqrtf(var) + 1e-9f;
            if (kv == 0) { g_muk[bid*Dc + d] = mu; g_sdk[bid*Dc + d] = sd; }
            else         { g_muv[bid*Dc + d] = mu; g_sdv[bid*Dc + d] = sd; }
        } else {
            for (int i = tid; i < Bc*Hc*Ec; i += 256)
                g_outs[i] = bproj[i & (Hc*Ec - 1)];
        }
        return;
    }

    if (blockIdx.x < 64) {
        // ---------- attention branch ----------
        float* s_sc  = (float*)dynsmem;
        float* s_red = s_sc + TP;
        float* s_q   = s_red + 256;
        int bh = blockIdx.x;
        int h = bh & 7;
        const __nv_bfloat16* Khi = g_chi + (size_t)bh*DT;
        const __nv_bfloat16* Klo = g_clo + (size_t)bh*DT;
        const __nv_bfloat16* Vhi = g_chi + (size_t)(64 + bh)*DT;
        const __nv_bfloat16* Vlo = g_clo + (size_t)(64 + bh)*DT;
        if (tid < Dc) s_q[tid] = q[h*Dc + tid];
        __syncthreads();

        if (tid < 250) {
            float a0 = 0.f, a1 = 0.f, a2 = 0.f, a3 = 0.f;
#pragma unroll 8
            for (int d = 0; d < Dc; d++) {
                uint2 ph = *(const uint2*)(Khi + (size_t)d*TP + tid*4);
                uint2 pl = *(const uint2*)(Klo + (size_t)d*TP + tid*4);
                float qd = s_q[d];
                float4 kv4 = un4(ph, pl);
                a0 += qd*kv4.x; a1 += qd*kv4.y; a2 += qd*kv4.z; a3 += qd*kv4.w;
            }
            const float sc = 0.08838834764831845f;
            *(float4*)&s_sc[tid*4] = make_float4(a0*sc, a1*sc, a2*sc, a3*sc);
        }
        if (tid < 24) s_sc[1000 + tid] = 0.f;
        __syncthreads();

        float lm = -1e30f;
        for (int t = tid; t < Tc; t += 256) lm = fmaxf(lm, s_sc[t]);
        s_red[tid] = lm; __syncthreads();
        for (int s = 128; s; s >>= 1) { if (tid < s) s_red[tid] = fmaxf(s_red[tid], s_red[tid+s]); __syncthreads(); }
        float m = s_red[0];
        __syncthreads();
        float ls = 0.f;
        for (int t = tid; t < Tc; t += 256) { float e = expf(s_sc[t]-m); s_sc[t] = e; ls += e; }
        s_red[tid] = ls; __syncthreads();
        for (int s = 128; s; s >>= 1) { if (tid < s) s_red[tid] += s_red[tid+s]; __syncthreads(); }
        float inv = 1.f / s_red[0];
        __syncthreads();

        int w = tid >> 5, lane = tid & 31;
#pragma unroll 1
        for (int rr = 0; rr < 16; rr++) {
            int d = w*16 + rr;
            float acc = 0.f;
#pragma unroll
            for (int cc = 0; cc < 8; cc++) {
                int grp = lane + cc*32;
                uint2 ph = *(const uint2*)(Vhi + (size_t)d*TP + grp*4);
                uint2 pl = *(const uint2*)(Vlo + (size_t)d*TP + grp*4);
                float4 vv = un4(ph, pl);
                float4 aa = *(float4*)&s_sc[grp*4];
                acc += aa.x*vv.x + aa.y*vv.y + aa.z*vv.z + aa.w*vv.w;
            }
            for (int off = 16; off; off >>= 1) acc += __shfl_down_sync(~0u, acc, off);
            if (lane == 0) g_o1[bh*Dc + d] = acc * inv;
        }
        return;
    }

    // ---------- S = K^T V branch (XOR-swizzled 3-stage) ----------
    uint32_t sb = smem_u32(dynsmem);
    int warp = tid >> 5, lane = tid & 31;
    int job = blockIdx.x - 64;
    int bh = job >> 1;
    int seg = job & 1;
    const __nv_bfloat16* Ahi = g_chi + (size_t)bh*DT + seg*512;
    const __nv_bfloat16* Alo = g_clo + (size_t)bh*DT + seg*512;
    const __nv_bfloat16* Bhi = g_chi + (size_t)(64 + bh)*DT + seg*512;
    const __nv_bfloat16* Blo = g_clo + (size_t)(64 + bh)*DT + seg*512;

    int m0w = (warp >> 1)*32;
    int n0w = (warp & 1)*64;
    int arow = (lane & 7) + ((lane >> 3) & 1)*8;
    int abit = (lane >> 4) & 1;
    int brow = (lane & 7) + ((lane >> 4) & 1)*8;
    int bbit = (lane >> 3) & 1;

    float acc[2][8][4];
#pragma unroll
    for (int i = 0; i < 2; i++)
#pragma unroll
        for (int j = 0; j < 8; j++)
#pragma unroll
            for (int r = 0; r < 4; r++) acc[i][j][r] = 0.f;

    prefetch_smat(0, 0, sb, tid, Ahi, Alo, Bhi, Blo);
    prefetch_smat(1, 1, sb, tid, Ahi, Alo, Bhi, Blo);

#pragma unroll 1
    for (int c = 0; c < NCHS; c++) {
        if (c < NCHS-1) CP_WAIT(1); else CP_WAIT(0);
        __syncthreads();
        if (c + 2 < NCHS)
            prefetch_smat(c+2, (c+2)%3, sb, tid, Ahi, Alo, Bhi, Blo);

        uint32_t st = sb + (c%3)*GSTG;
#pragma unroll
        for (int ks = 0; ks < 2; ks++) {
            unsigned ah[2][4], al[2][4];
#pragma unroll
            for (int mi = 0; mi < 2; mi++) {
                int rA = m0w + mi*16 + arow;
                uint32_t a0 = st + (uint32_t)(rA*64 + (((ks*2 + abit) ^ ((rA >> 1) & 3)) << 4));
                LDSM4(ah[mi][0], ah[mi][1], ah[mi][2], ah[mi][3], a0);
                LDSM4(al[mi][0], al[mi][1], al[mi][2], al[mi][3], a0 + GA_PL);
            }
#pragma unroll
            for (int ni = 0; ni < 4; ni++) {
                int rB = n0w + ni*16 + brow;
                uint32_t b0 = st + 2*GA_PL + (uint32_t)(rB*64 + (((ks*2 + bbit) ^ ((rB >> 1) & 3)) << 4));
                unsigned bhv[4], blv[4];
                LDSM4(bhv[0], bhv[1], bhv[2], bhv[3], b0);
                LDSM4(blv[0], blv[1], blv[2], blv[3], b0 + GA_PL);
#pragma unroll
                for (int mi = 0; mi < 2; mi++)
#pragma unroll
                    for (int j2 = 0; j2 < 2; j2++) {
                        int nj = ni*2 + j2;
                        MMA_BF16(acc[mi][nj], ah[mi], &bhv[j2*2]);
                        MMA_BF16(acc[mi][nj], ah[mi], &blv[j2*2]);
                        MMA_BF16(acc[mi][nj], al[mi], &bhv[j2*2]);
                    }
            }
        }
    }

    float* Sp = g_S + (size_t)bh*Dc*Dc;
    int g = lane >> 2, q4 = lane & 3;
#pragma unroll
    for (int nj = 0; nj < 8; nj++) {
        int l = n0w + nj*8 + q4*2;
#pragma unroll
        for (int mi = 0; mi < 2; mi++) {
            int k0 = m0w + mi*16 + g;
            atomicAdd(&Sp[k0*Dc + l],       acc[mi][nj][0]);
            atomicAdd(&Sp[k0*Dc + l + 1],   acc[mi][nj][1]);
            atomicAdd(&Sp[(k0+8)*Dc + l],   acc[mi][nj][2]);
            atomicAdd(&Sp[(k0+8)*Dc + l+1], acc[mi][nj][3]);
        }
    }
}

// ---------------- stage 3c: normalized correlation ----------------
__global__ void k_corr() {
    int c = blockIdx.x*256 + threadIdx.x;
    int bh = blockIdx.y;
    if (c >= DCORR) return;
    float disc = 65025.0f - 8.0f*(float)c;
    int k = (int)((255.0f - sqrtf(disc))*0.5f);
    if (k < 0) k = 0;
    if (k > 126) k = 126;
    while (k > 0 && k*(255-k)/2 > c) k--;
    while ((k+1)*(254-k)/2 <= c) k++;
    int l = k + 1 + (c - k*(255-k)/2);
    float muk = g_muk[bh*Dc + k], sdk = g_sdk[bh*Dc + k];
    float muv = g_muv[bh*Dc + l], sdv = g_sdv[bh*Dc + l];
    float S = g_S[(size_t)bh*Dc*Dc + k*Dc + l];
    g_corr[(size_t)bh*DCORR + c] = (S - (float)Tc*muk*muv) / ((float)Tc*sdk*sdv);
}

// ---------------- stage 4: outs += corr . Wproj (warp-per-e, coalesced) ----------------
__global__ __launch_bounds__(256) void k_proj(const float* __restrict__ Wproj) {
    __shared__ float sc[8][132];
    int tid = threadIdx.x;
    int warp = tid >> 5, lane = tid & 31;
    int h = blockIdx.y;
    int cs = blockIdx.z;
    int e = blockIdx.x*8 + warp;
    int start = cs*2032;
    const float* wrow = Wproj + ((size_t)h*Ec + e)*DCORR;
    float acc[8];
#pragma unroll
    for (int b = 0; b < 8; b++) acc[b] = 0.f;

#pragma unroll 1
    for (int c0 = start; c0 < start + 2032; c0 += 128) {
        int lim = start + 2032 - c0; if (lim > 128) lim = 128;
        {
            float4 cv = make_float4(0.f,0.f,0.f,0.f);
            if (lane*4 < lim)
                cv = *(const float4*)(g_corr + ((size_t)warp*Hc + h)*DCORR + c0 + lane*4);
            *(float4*)&sc[warp][lane*4] = cv;
        }
        __syncthreads();
        float4 wv = make_float4(0.f,0.f,0.f,0.f);
        if (lane*4 < lim) wv = *(const float4*)(wrow + c0 + lane*4);
#pragma unroll
        for (int b = 0; b < 8; b++) {
            float4 sv = *(float4*)&sc[b][lane*4];
            acc[b] += wv.x*sv.x + wv.y*sv.y + wv.z*sv.z + wv.w*sv.w;
        }
        __syncthreads();
    }
#pragma unroll
    for (int b = 0; b < 8; b++) {
        float a = acc[b];
        for (int off = 16; off; off >>= 1) a += __shfl_down_sync(~0u, a, off);
        if (lane == 0) atomicAdd(&g_outs[b*(Hc*Ec) + h*Ec + e], a);
    }
}

// ---------------- stage 5: final linears + mix ----------------
__global__ __launch_bounds__(256) void k_final(
    const float* __restrict__ WT, const float* __restrict__ bT,
    const float* __restrict__ Wp, const float* __restrict__ bp,
    float* __restrict__ out) {
    __shared__ float so1[Hc*Dc];
    __shared__ float sout[Hc*Ec];
    __shared__ float sred[256];
    int b = blockIdx.x, ec = blockIdx.y;
    int tid = threadIdx.x;
    for (int j = tid; j < Hc*Dc; j += 256) so1[j]  = g_o1[b*Hc*Dc + j];
    for (int j = tid; j < Hc*Ec; j += 256) sout[j] = g_outs[b*Hc*Ec + j];
    __syncthreads();
    int e_l = tid >> 3, js = tid & 7;
    int e = ec*32 + e_l;
    float a = 0.f;
    const float* wt = WT + (size_t)e*(Hc*Dc) + js*128;
    const float* s1p = so1 + js*128;
#pragma unroll 4
    for (int j = 0; j < 128; j += 4) {
        float4 wv = *(const float4*)(wt + j);
        float4 sv = *(const float4*)(s1p + j);
        a += wv.x*sv.x + wv.y*sv.y + wv.z*sv.z + wv.w*sv.w;
    }
    const float* wp = Wp + (size_t)e*(Hc*Ec) + js*256;
    const float* s2p = sout + js*256;
#pragma unroll 4
    for (int j = 0; j < 256; j += 4) {
        float4 wv = *(const float4*)(wp + j);
        float4 sv = *(const float4*)(s2p + j);
        a += wv.x*sv.x + wv.y*sv.y + wv.z*sv.z + wv.w*sv.w;
    }
    if (js == 0) a += bT[e] + bp[e];
    sred[tid] = a;
    __syncthreads();
    if (tid < 32) {
        float s = 0.f;
#pragma unroll
        for (int k = 0; k < 8; k++) s += sred[tid*8 + k];
        out[b*Ec + ec*32 + tid] = 0.5f*s;
    }
}

// ---------------- launch ----------------
extern "C" void kernel_launch(void* const* d_in, const int* in_sizes, int n_in,
                              void* d_out, int out_size) {
    const float* x     = (const float*)d_in[0];
    const float* wk    = (const float*)d_in[1];
    const float* wv    = (const float*)d_in[2];
    const float* q     = (const float*)d_in[3];
    const float* Wk    = (const float*)d_in[4];
    const float* bk    = (const float*)d_in[5];
    const float* Wv    = (const float*)d_in[6];
    const float* bv    = (const float*)d_in[7];
    const float* Wproj = (const float*)d_in[8];
    const float* bproj = (const float*)d_in[9];
    const float* WT    = (const float*)d_in[10];
    const float* bT    = (const float*)d_in[11];
    const float* Wp    = (const float*)d_in[12];
    const float* bp    = (const float*)d_in[13];
    float* out = (float*)d_out;

    cudaFuncSetAttribute(k_gemm, cudaFuncAttributeMaxDynamicSharedMemorySize, GSM);
    cudaFuncSetAttribute(k_as,   cudaFuncAttributeMaxDynamicSharedMemorySize, GSM);

    k_initw<<<dim3(3072, 2), 256>>>(wk, wv, Wk, Wv);
    k_raw<<<dim3(16, Fc/16, Bc), dim3(16, 8)>>>(x);
    k_gemm<<<dim3(8, Bc*Hc, 2), 256, GSM>>>(bk, bv);
    k_as<<<257, 256, GSM>>>(q, bproj);                   // attn + smat + statfin
    k_corr<<<dim3((DCORR+255)/256, Bc*Hc), 256>>>();
    k_proj<<<dim3(Ec/8, Hc, 4), 256>>>(Wproj);
    k_final<<<dim3(Bc, Ec/32), 256>>>(WT, bT, Wp, bp, out);
}

// round 17
// speedup vs baseline: 1.5359x; 1.0090x over previous
#include <cuda_runtime.h>
#include <cuda_bf16.h>
#include <math.h>
#include <stdint.h>

// Problem constants
#define Bc 8
#define Hc 8
#define Fc 768
#define Dc 128
#define Ec 256
#define Lc 13
#define Tc 1000
#define DCORR 8128
#define TP 1024                 // padded T
#define DT (128*TP)             // plane size per (kv,bh)

// ---------------- device scratch ----------------
__device__ float g_kw[Hc*Lc];
__device__ float g_vw[Hc*Lc];
__device__ __nv_bfloat16 g_ahi[(size_t)2*Bc*Hc*Tc*Fc];   // raw activations [kv][bh][t][f]
__device__ __nv_bfloat16 g_alo[(size_t)2*Bc*Hc*Tc*Fc];
__device__ __nv_bfloat16 g_whi[(size_t)2*Hc*Dc*Fc];      // weights [kv][h][d][f]
__device__ __nv_bfloat16 g_wlo[(size_t)2*Hc*Dc*Fc];
__device__ __nv_bfloat16 g_chi[(size_t)2*Bc*Hc*DT];      // GEMM out planes [kv][bh][d][t]
__device__ __nv_bfloat16 g_clo[(size_t)2*Bc*Hc*DT];
__device__ float g_s1[2*Bc*Hc*Dc];
__device__ float g_s2[2*Bc*Hc*Dc];
__device__ float g_muk[Bc*Hc*Dc];
__device__ float g_sdk[Bc*Hc*Dc];
__device__ float g_muv[Bc*Hc*Dc];
__device__ float g_sdv[Bc*Hc*Dc];
__device__ float g_o1[Bc*Hc*Dc];
__device__ float g_S[(size_t)Bc*Hc*Dc*Dc];
__device__ float g_corr[(size_t)Bc*Hc*DCORR];
__device__ float g_outs[Bc*Hc*Ec];
__device__ unsigned short g_iu[DCORR];

__device__ __forceinline__ uint32_t smem_u32(const void* p) {
    uint32_t a;
    asm("{ .reg .u64 t; cvta.to.shared.u64 t, %1; cvt.u32.u64 %0, t; }" : "=r"(a) : "l"(p));
    return a;
}
#define CP_COMMIT()  asm volatile("cp.async.commit_group;" ::: "memory")
#define CP_WAIT(n)   asm volatile("cp.async.wait_group %0;" :: "n"(n) : "memory")
#define LDSM4(r0, r1, r2, r3, a) \
    asm volatile("ldmatrix.sync.aligned.m8n8.x4.shared.b16 {%0,%1,%2,%3}, [%4];" \
        : "=r"(r0), "=r"(r1), "=r"(r2), "=r"(r3) : "r"(a))
#define MMA_BF16(d, a, b) asm volatile( \
    "mma.sync.aligned.m16n8k16.row.col.f32.bf16.bf16.f32 " \
    "{%0,%1,%2,%3},{%4,%5,%6,%7},{%8,%9},{%0,%1,%2,%3};\n" \
    : "+f"((d)[0]), "+f"((d)[1]), "+f"((d)[2]), "+f"((d)[3]) \
    : "r"((a)[0]), "r"((a)[1]), "r"((a)[2]), "r"((a)[3]), "r"((b)[0]), "r"((b)[1]))

// hi+lo bf16 reconstruction of 4 packed values
__device__ __forceinline__ float4 un4(uint2 h, uint2 l) {
    float4 r;
    r.x = __int_as_float(h.x << 16)        + __int_as_float(l.x << 16);
    r.y = __int_as_float(h.x & 0xffff0000u) + __int_as_float(l.x & 0xffff0000u);
    r.z = __int_as_float(h.y << 16)        + __int_as_float(l.y << 16);
    r.w = __int_as_float(h.y & 0xffff0000u) + __int_as_float(l.y & 0xffff0000u);
    return r;
}

// ---------------- stage 0: init + softmax + W pack + iu table (merged) ----------------
__global__ void k_initw(const float* __restrict__ wk, const float* __restrict__ wv,
                        const float* __restrict__ Wk, const float* __restrict__ Wv) {
    int tid = threadIdx.x;
    size_t i = (size_t)blockIdx.x*256 + tid;
    const float* W = blockIdx.y ? Wv : Wk;
    float v = W[i];
    __nv_bfloat16 h16 = __float2bfloat16(v);
    __nv_bfloat16 l16 = __float2bfloat16(v - __bfloat162float(h16));
    size_t o = (size_t)blockIdx.y*(Hc*Dc*Fc) + i;
    g_whi[o] = h16;
    g_wlo[o] = l16;

    if (blockIdx.y == 0 && blockIdx.x < 1056) {
        int j = blockIdx.x*256 + tid;
        float4 z = make_float4(0.f,0.f,0.f,0.f);
        if (j < 262144) ((float4*)g_S)[j] = z;
        else {
            int k = j - 262144;
            if (k < 4096) ((float4*)g_s1)[k] = z;
            else ((float4*)g_s2)[k - 4096] = z;
        }
    }
    if (blockIdx.y == 1 && blockIdx.x < 32) {
        int c = blockIdx.x*256 + tid;
        if (c < DCORR) {
            float disc = 65025.0f - 8.0f*(float)c;
            int k = (int)((255.0f - sqrtf(disc))*0.5f);
            if (k < 0) k = 0;
            if (k > 126) k = 126;
            while (k > 0 && k*(255-k)/2 > c) k--;
            while ((k+1)*(254-k)/2 <= c) k++;
            int l = k + 1 + (c - k*(255-k)/2);
            g_iu[c] = (unsigned short)((k << 8) | l);
        }
    }
    if (blockIdx.x == 0 && blockIdx.y == 0 && tid < 2*Hc) {
        int h = tid % Hc;
        const float* src = (tid < Hc ? wk : wv) + h*Lc;
        float* dst = (tid < Hc ? g_kw : g_vw) + h*Lc;
        float m = -1e30f;
        for (int l = 0; l < Lc; l++) m = fmaxf(m, src[l]);
        float e[Lc]; float s = 0.f;
        for (int l = 0; l < Lc; l++) { e[l] = expf(src[l]-m); s += e[l]; }
        float inv = 1.f/s;
        for (int l = 0; l < Lc; l++) dst[l] = e[l]*inv;
    }
}

// ---------------- stage 1: L-contraction -> bf16 hi/lo [t][f] (packed f32x2 FMA) ----------------
__global__ __launch_bounds__(128) void k_raw(const float* __restrict__ x) {
    __shared__ __align__(8) float2 skv[Hc*Lc];
    __shared__ float xs[2][16][212];
    __shared__ __align__(8) unsigned s_ohi[2][Hc][16][10];
    __shared__ __align__(8) unsigned s_olo[2][Hc][16][10];
    int tx = threadIdx.x;
    int ty = threadIdx.y;
    int tid = ty*16 + tx;
    if (tid < Hc*Lc) skv[tid] = make_float2(g_kw[tid], g_vw[tid]);

    int tbase = blockIdx.x*64;
    int f0 = blockIdx.y*16;
    int b  = blockIdx.z;
    const float* xb = x + (size_t)(b*Fc + f0)*Tc*13;

    auto stage_x = [&](int buf, int st0) {
        int n = Tc - st0;
        int maxf4 = (n >= 16) ? 52 : (n > 0 ? ((n*13) >> 2) : 0);
        unsigned tbeg = (unsigned)st0*13u;
#pragma unroll
        for (int it = 0; it < 7; it++) {
            int idx = tid + it*128;
            if (idx < 832) {
                int row = idx / 52, col = idx % 52;
                unsigned sz = (col < maxf4) ? 16u : 0u;
                int scol = (col < maxf4) ? col : 0;
                uint32_t dst = smem_u32(&xs[buf][row][col*4]);
                const float* src = xb + (unsigned)row*13000u + tbeg + (unsigned)scol*4u;
                asm volatile("cp.async.cg.shared.global [%0], [%1], 16, %2;"
                             :: "r"(dst), "l"(src), "r"(sz));
            }
        }
        CP_COMMIT();
    };

    stage_x(0, tbase);

#pragma unroll 1
    for (int s = 0; s < 4; s++) {
        int st0 = tbase + s*16;
        if (s < 3) { stage_x((s+1) & 1, st0 + 16); CP_WAIT(1); }
        else CP_WAIT(0);
        __syncthreads();

        int buf = s & 1;
        float xv0[Lc], xv1[Lc];
#pragma unroll
        for (int l = 0; l < Lc; l++) {
            xv0[l] = xs[buf][ty*2][tx*13 + l];
            xv1[l] = xs[buf][ty*2 + 1][tx*13 + l];
        }

        // packed (k,v) accumulators: acc[f][h] = (k_acc, v_acc)
        unsigned long long acc0[Hc], acc1[Hc];
#pragma unroll
        for (int h = 0; h < Hc; h++) { acc0[h] = 0ull; acc1[h] = 0ull; }
#pragma unroll
        for (int l = 0; l < Lc; l++) {
            unsigned long long x0, x1;
            asm("mov.b64 %0, {%1, %1};" : "=l"(x0) : "f"(xv0[l]));
            asm("mov.b64 %0, {%1, %1};" : "=l"(x1) : "f"(xv1[l]));
#pragma unroll
            for (int h = 0; h < Hc; h++) {
                unsigned long long w2 = *(const unsigned long long*)&skv[h*Lc + l];
                asm("fma.rn.f32x2 %0, %1, %2, %0;" : "+l"(acc0[h]) : "l"(x0), "l"(w2));
                asm("fma.rn.f32x2 %0, %1, %2, %0;" : "+l"(acc1[h]) : "l"(x1), "l"(w2));
            }
        }

#pragma unroll
        for (int h = 0; h < Hc; h++) {
            float k0, v0, k1, v1;
            asm("mov.b64 {%0, %1}, %2;" : "=f"(k0), "=f"(v0) : "l"(acc0[h]));
            asm("mov.b64 {%0, %1}, %2;" : "=f"(k1), "=f"(v1) : "l"(acc1[h]));
            {
                unsigned b0 = __float_as_uint(k0), b1 = __float_as_uint(k1);
                unsigned hiw = __byte_perm(b0, b1, 0x7632);
                float d0 = k0 - __uint_as_float(b0 & 0xffff0000u);
                float d1 = k1 - __uint_as_float(b1 & 0xffff0000u);
                unsigned low;
                asm("cvt.rn.bf16x2.f32 %0, %1, %2;" : "=r"(low) : "f"(d1), "f"(d0));
                s_ohi[0][h][tx][ty] = hiw;
                s_olo[0][h][tx][ty] = low;
            }
            {
                unsigned b0 = __float_as_uint(v0), b1 = __float_as_uint(v1);
                unsigned hiw = __byte_perm(b0, b1, 0x7632);
                float d0 = v0 - __uint_as_float(b0 & 0xffff0000u);
                float d1 = v1 - __uint_as_float(b1 & 0xffff0000u);
                unsigned low;
                asm("cvt.rn.bf16x2.f32 %0, %1, %2;" : "=r"(low) : "f"(d1), "f"(d0));
                s_ohi[1][h][tx][ty] = hiw;
                s_olo[1][h][tx][ty] = low;
            }
        }
        __syncthreads();

        // write phase: 32-bit offset math
        int w = tid >> 5, lane = tid & 31;
        int f4 = lane & 3;
        int tq = lane >> 2;
        unsigned foff = (unsigned)f0 + (unsigned)(f4*4);
#pragma unroll
        for (int it = 0; it < 4; it++) {
            int job = w*4 + it;
            int kv = job >> 3;
            int h = job & 7;
            unsigned rowbase = ((unsigned)(kv*Bc + b)*Hc + (unsigned)h)*(unsigned)Tc + (unsigned)st0;
            unsigned base0 = (rowbase + (unsigned)tq)*(unsigned)Fc + foff;
#pragma unroll
            for (int ti = 0; ti < 2; ti++) {
                int tl = ti*8 + tq;
                if (st0 + tl < Tc) {
                    unsigned off = base0 + (unsigned)(ti*8*Fc);
                    *(uint2*)(g_ahi + off) = *(uint2*)&s_ohi[kv][h][tl][f4*2];
                    *(uint2*)(g_alo + off) = *(uint2*)&s_olo[kv][h][tl][f4*2];
                }
            }
        }
        __syncthreads();
    }
}

// ---------------- stage 2: GEMM 128x128, XOR-swizzled smem, 3-stage ----------------
#define GA_PL 8192
#define GSTG (4*GA_PL)
#define GSM (3*GSTG)
#define NCH (Fc/32)

__device__ __forceinline__ void prefetch_g(
    int c, int stage, uint32_t sb, int t0, int tid,
    const __nv_bfloat16* __restrict__ Ahi, const __nv_bfloat16* __restrict__ Alo,
    const __nv_bfloat16* __restrict__ Bhi, const __nv_bfloat16* __restrict__ Blo) {
    int kc = c*32;
    uint32_t stb = sb + stage*GSTG;
#pragma unroll
    for (int it = 0; it < 8; it++) {
        int idx = tid + it*256;
        int plane = idx >> 9;
        int row = (idx >> 2) & 127;
        int seg = idx & 3;
        uint32_t dst = stb + plane*GA_PL + row*64 + (((seg ^ ((row >> 1) & 3))) << 4);
        const __nv_bfloat16* src;
        unsigned sz = 16;
        if (plane < 2) {
            int t = t0 + row;
            if (t >= Tc) { t = 0; sz = 0; }
            src = (plane ? Alo : Ahi) + (size_t)t*Fc + kc + seg*8;
        } else {
            src = (plane == 2 ? Bhi : Blo) + (size_t)row*Fc + kc + seg*8;
        }
        asm volatile("cp.async.cg.shared.global [%0], [%1], 16, %2;"
                     :: "r"(dst), "l"(src), "r"(sz));
    }
    CP_COMMIT();
}

__global__ __launch_bounds__(256, 2) void k_gemm(
    const float* __restrict__ bk, const float* __restrict__ bv) {
    extern __shared__ __align__(1024) char dynsmem[];
    uint32_t sb = smem_u32(dynsmem);

    int tid = threadIdx.x;
    int warp = tid >> 5, lane = tid & 31;
    int bh = blockIdx.y;
    int h = bh & 7;
    int kv = blockIdx.z;
    int t0 = blockIdx.x*128;

    const __nv_bfloat16* Ahi = g_ahi + (size_t)(kv*Bc*Hc + bh)*Tc*Fc;
    const __nv_bfloat16* Alo = g_alo + (size_t)(kv*Bc*Hc + bh)*Tc*Fc;
    const __nv_bfloat16* Bhi = g_whi + (size_t)(kv*Hc + h)*Dc*Fc;
    const __nv_bfloat16* Blo = g_wlo + (size_t)(kv*Hc + h)*Dc*Fc;
    const float* bias = (kv ? bv : bk) + h*Dc;

    int m0w = (warp >> 1)*32;
    int n0w = (warp & 1)*64;
    int arow = (lane & 7) + ((lane >> 3) & 1)*8;
    int abit = (lane >> 4) & 1;
    int brow = (lane & 7) + ((lane >> 4) & 1)*8;
    int bbit = (lane >> 3) & 1;

    float acc[2][8][4];
#pragma unroll
    for (int i = 0; i < 2; i++)
#pragma unroll
        for (int j = 0; j < 8; j++)
#pragma unroll
            for (int r = 0; r < 4; r++) acc[i][j][r] = 0.f;

    prefetch_g(0, 0, sb, t0, tid, Ahi, Alo, Bhi, Blo);
    prefetch_g(1, 1, sb, t0, tid, Ahi, Alo, Bhi, Blo);

#pragma unroll 1
    for (int c = 0; c < NCH; c++) {
        if (c < NCH-1) CP_WAIT(1); else CP_WAIT(0);
        __syncthreads();
        if (c + 2 < NCH)
            prefetch_g(c+2, (c+2)%3, sb, t0, tid, Ahi, Alo, Bhi, Blo);

        uint32_t st = sb + (c%3)*GSTG;
#pragma unroll
        for (int ks = 0; ks < 2; ks++) {
            unsigned ah[2][4], al[2][4];
#pragma unroll
            for (int mi = 0; mi < 2; mi++) {
                int rA = m0w + mi*16 + arow;
                uint32_t a0 = st + (uint32_t)(rA*64 + (((ks*2 + abit) ^ ((rA >> 1) & 3)) << 4));
                LDSM4(ah[mi][0], ah[mi][1], ah[mi][2], ah[mi][3], a0);
                LDSM4(al[mi][0], al[mi][1], al[mi][2], al[mi][3], a0 + GA_PL);
            }
#pragma unroll
            for (int ni = 0; ni < 4; ni++) {
                int rB = n0w + ni*16 + brow;
                uint32_t b0 = st + 2*GA_PL + (uint32_t)(rB*64 + (((ks*2 + bbit) ^ ((rB >> 1) & 3)) << 4));
                unsigned bhv[4], blv[4];
                LDSM4(bhv[0], bhv[1], bhv[2], bhv[3], b0);
                LDSM4(blv[0], blv[1], blv[2], blv[3], b0 + GA_PL);
#pragma unroll
                for (int mi = 0; mi < 2; mi++)
#pragma unroll
                    for (int j2 = 0; j2 < 2; j2++) {
                        int nj = ni*2 + j2;
                        MMA_BF16(acc[mi][nj], ah[mi], &bhv[j2*2]);
                        MMA_BF16(acc[mi][nj], ah[mi], &blv[j2*2]);
                        MMA_BF16(acc[mi][nj], al[mi], &bhv[j2*2]);
                    }
            }
        }
    }

    // epilogue: transpose through smem to [d][t], emit bf16 hi/lo planes + stats
    __syncthreads();
    float* Cs = (float*)dynsmem;           // [128 d][132]
    int g = lane >> 2, q = lane & 3;
#pragma unroll
    for (int nj = 0; nj < 8; nj++) {
        int d = n0w + nj*8 + q*2;
        float2 bb = *(const float2*)(bias + d);
#pragma unroll
        for (int mi = 0; mi < 2; mi++) {
            int r = m0w + mi*16 + g;
            Cs[d*132 + r]         = acc[mi][nj][0] + bb.x;
            Cs[(d+1)*132 + r]     = acc[mi][nj][1] + bb.y;
            Cs[d*132 + r + 8]     = acc[mi][nj][2] + bb.x;
            Cs[(d+1)*132 + r + 8] = acc[mi][nj][3] + bb.y;
        }
    }
    __syncthreads();

    __nv_bfloat16* Phi = g_chi + ((size_t)kv*64 + bh)*DT;
    __nv_bfloat16* Plo = g_clo + ((size_t)kv*64 + bh)*DT;
    size_t so = ((size_t)kv*64 + bh)*Dc;
    int tb = t0 + lane*4;
#pragma unroll 1
    for (int rr = 0; rr < 16; rr++) {
        int d = warp*16 + rr;
        float4 v = *(float4*)&Cs[d*132 + lane*4];
        v.x = (tb+0 < Tc) ? v.x : 0.f;
        v.y = (tb+1 < Tc) ? v.y : 0.f;
        v.z = (tb+2 < Tc) ? v.z : 0.f;
        v.w = (tb+3 < Tc) ? v.w : 0.f;
        __nv_bfloat162 h01 = __floats2bfloat162_rn(v.x, v.y);
        __nv_bfloat162 h23 = __floats2bfloat162_rn(v.z, v.w);
        unsigned uh01 = *(unsigned*)&h01, uh23 = *(unsigned*)&h23;
        float f0 = __int_as_float(uh01 << 16);
        float f1 = __int_as_float(uh01 & 0xffff0000u);
        float f2 = __int_as_float(uh23 << 16);
        float f3 = __int_as_float(uh23 & 0xffff0000u);
        __nv_bfloat162 l01 = __floats2bfloat162_rn(v.x - f0, v.y - f1);
        __nv_bfloat162 l23 = __floats2bfloat162_rn(v.z - f2, v.w - f3);
        *(uint2*)(Phi + (size_t)d*TP + tb) = make_uint2(uh01, uh23);
        *(uint2*)(Plo + (size_t)d*TP + tb) = make_uint2(*(unsigned*)&l01, *(unsigned*)&l23);
        float p1 = v.x + v.y + v.z + v.w;
        float p2 = v.x*v.x + v.y*v.y + v.z*v.z + v.w*v.w;
        for (int off = 16; off; off >>= 1) {
            p1 += __shfl_down_sync(~0u, p1, off);
            p2 += __shfl_down_sync(~0u, p2, off);
        }
        if (lane == 0) {
            atomicAdd(&g_s1[so + d], p1);
            atomicAdd(&g_s2[so + d], p2);
        }
    }
}

// ---------------- fused stage 3: attn (0..63) + S=K^T V (64..191) + statfin (192..256) ----------------
#define NCHS 16

__device__ __forceinline__ void prefetch_smat(
    int c, int stage, uint32_t sb, int tid,
    const __nv_bfloat16* __restrict__ Ahi, const __nv_bfloat16* __restrict__ Alo,
    const __nv_bfloat16* __restrict__ Bhi, const __nv_bfloat16* __restrict__ Blo) {
    int kc = c*32;
    uint32_t stb = sb + stage*GSTG;
#pragma unroll
    for (int it = 0; it < 8; it++) {
        int idx = tid + it*256;
        int plane = idx >> 9;
        int row = (idx >> 2) & 127;
        int seg = idx & 3;
        uint32_t dst = stb + plane*GA_PL + row*64 + (((seg ^ ((row >> 1) & 3))) << 4);
        const __nv_bfloat16* src =
            (plane == 0 ? Ahi : plane == 1 ? Alo : plane == 2 ? Bhi : Blo)
            + (size_t)row*TP + kc + seg*8;
        asm volatile("cp.async.cg.shared.global [%0], [%1], 16;" :: "r"(dst), "l"(src));
    }
    CP_COMMIT();
}

__global__ __launch_bounds__(256, 2) void k_as(const float* __restrict__ q,
                                               const float* __restrict__ bproj) {
    extern __shared__ __align__(1024) char dynsmem[];
    int tid = threadIdx.x;

    if (blockIdx.x >= 192) {
        int bid = blockIdx.x - 192;
        if (bid < 64) {
            int kv = tid >> 7;
            int d = tid & 127;
            size_t o = ((size_t)kv*64 + bid)*Dc + d;
            float s1 = g_s1[o], s2 = g_s2[o];
            float mu = s1 * (1.f/Tc);
            float var = (s2 - (float)Tc*mu*mu) * (1.f/(Tc-1));
            var = fmaxf(var, 0.f);
            float sd = sqrtf(var) + 1e-9f;
            if (kv == 0) { g_muk[bid*Dc + d] = mu; g_sdk[bid*Dc + d] = sd; }
            else         { g_muv[bid*Dc + d] = mu; g_sdv[bid*Dc + d] = sd; }
        } else {
            for (int i = tid; i < Bc*Hc*Ec; i += 256)
                g_outs[i] = bproj[i & (Hc*Ec - 1)];
        }
        return;
    }

    if (blockIdx.x < 64) {
        // ---------- attention branch ----------
        float* s_sc  = (float*)dynsmem;
        float* s_red = s_sc + TP;
        float* s_q   = s_red + 256;
        int bh = blockIdx.x;
        int h = bh & 7;
        const __nv_bfloat16* Khi = g_chi + (size_t)bh*DT;
        const __nv_bfloat16* Klo = g_clo + (size_t)bh*DT;
        const __nv_bfloat16* Vhi = g_chi + (size_t)(64 + bh)*DT;
        const __nv_bfloat16* Vlo = g_clo + (size_t)(64 + bh)*DT;
        if (tid < Dc) s_q[tid] = q[h*Dc + tid];
        __syncthreads();

        if (tid < 250) {
            float a0 = 0.f, a1 = 0.f, a2 = 0.f, a3 = 0.f;
#pragma unroll 8
            for (int d = 0; d < Dc; d++) {
                uint2 ph = *(const uint2*)(Khi + (size_t)d*TP + tid*4);
                uint2 pl = *(const uint2*)(Klo + (size_t)d*TP + tid*4);
                float qd = s_q[d];
                float4 kv4 = un4(ph, pl);
                a0 += qd*kv4.x; a1 += qd*kv4.y; a2 += qd*kv4.z; a3 += qd*kv4.w;
            }
            const float sc = 0.08838834764831845f;
            *(float4*)&s_sc[tid*4] = make_float4(a0*sc, a1*sc, a2*sc, a3*sc);
        }
        if (tid < 24) s_sc[1000 + tid] = 0.f;
        __syncthreads();

        float lm = -1e30f;
        for (int t = tid; t < Tc; t += 256) lm = fmaxf(lm, s_sc[t]);
        s_red[tid] = lm; __syncthreads();
        for (int s = 128; s; s >>= 1) { if (tid < s) s_red[tid] = fmaxf(s_red[tid], s_red[tid+s]); __syncthreads(); }
        float m = s_red[0];
        __syncthreads();
        float ls = 0.f;
        for (int t = tid; t < Tc; t += 256) { float e = expf(s_sc[t]-m); s_sc[t] = e; ls += e; }
        s_red[tid] = ls; __syncthreads();
        for (int s = 128; s; s >>= 1) { if (tid < s) s_red[tid] += s_red[tid+s]; __syncthreads(); }
        float inv = 1.f / s_red[0];
        __syncthreads();

        int w = tid >> 5, lane = tid & 31;
#pragma unroll 1
        for (int rr = 0; rr < 16; rr++) {
            int d = w*16 + rr;
            float acc = 0.f;
#pragma unroll
            for (int cc = 0; cc < 8; cc++) {
                int grp = lane + cc*32;
                uint2 ph = *(const uint2*)(Vhi + (size_t)d*TP + grp*4);
                uint2 pl = *(const uint2*)(Vlo + (size_t)d*TP + grp*4);
                float4 vv = un4(ph, pl);
                float4 aa = *(float4*)&s_sc[grp*4];
                acc += aa.x*vv.x + aa.y*vv.y + aa.z*vv.z + aa.w*vv.w;
            }
            for (int off = 16; off; off >>= 1) acc += __shfl_down_sync(~0u, acc, off);
            if (lane == 0) g_o1[bh*Dc + d] = acc * inv;
        }
        return;
    }

    // ---------- S = K^T V branch (XOR-swizzled 3-stage) ----------
    uint32_t sb = smem_u32(dynsmem);
    int warp = tid >> 5, lane = tid & 31;
    int job = blockIdx.x - 64;
    int bh = job >> 1;
    int seg = job & 1;
    const __nv_bfloat16* Ahi = g_chi + (size_t)bh*DT + seg*512;
    const __nv_bfloat16* Alo = g_clo + (size_t)bh*DT + seg*512;
    const __nv_bfloat16* Bhi = g_chi + (size_t)(64 + bh)*DT + seg*512;
    const __nv_bfloat16* Blo = g_clo + (size_t)(64 + bh)*DT + seg*512;

    int m0w = (warp >> 1)*32;
    int n0w = (warp & 1)*64;
    int arow = (lane & 7) + ((lane >> 3) & 1)*8;
    int abit = (lane >> 4) & 1;
    int brow = (lane & 7) + ((lane >> 4) & 1)*8;
    int bbit = (lane >> 3) & 1;

    float acc[2][8][4];
#pragma unroll
    for (int i = 0; i < 2; i++)
#pragma unroll
        for (int j = 0; j < 8; j++)
#pragma unroll
            for (int r = 0; r < 4; r++) acc[i][j][r] = 0.f;

    prefetch_smat(0, 0, sb, tid, Ahi, Alo, Bhi, Blo);
    prefetch_smat(1, 1, sb, tid, Ahi, Alo, Bhi, Blo);

#pragma unroll 1
    for (int c = 0; c < NCHS; c++) {
        if (c < NCHS-1) CP_WAIT(1); else CP_WAIT(0);
        __syncthreads();
        if (c + 2 < NCHS)
            prefetch_smat(c+2, (c+2)%3, sb, tid, Ahi, Alo, Bhi, Blo);

        uint32_t st = sb + (c%3)*GSTG;
#pragma unroll
        for (int ks = 0; ks < 2; ks++) {
            unsigned ah[2][4], al[2][4];
#pragma unroll
            for (int mi = 0; mi < 2; mi++) {
                int rA = m0w + mi*16 + arow;
                uint32_t a0 = st + (uint32_t)(rA*64 + (((ks*2 + abit) ^ ((rA >> 1) & 3)) << 4));
                LDSM4(ah[mi][0], ah[mi][1], ah[mi][2], ah[mi][3], a0);
                LDSM4(al[mi][0], al[mi][1], al[mi][2], al[mi][3], a0 + GA_PL);
            }
#pragma unroll
            for (int ni = 0; ni < 4; ni++) {
                int rB = n0w + ni*16 + brow;
                uint32_t b0 = st + 2*GA_PL + (uint32_t)(rB*64 + (((ks*2 + bbit) ^ ((rB >> 1) & 3)) << 4));
                unsigned bhv[4], blv[4];
                LDSM4(bhv[0], bhv[1], bhv[2], bhv[3], b0);
                LDSM4(blv[0], blv[1], blv[2], blv[3], b0 + GA_PL);
#pragma unroll
                for (int mi = 0; mi < 2; mi++)
#pragma unroll
                    for (int j2 = 0; j2 < 2; j2++) {
                        int nj = ni*2 + j2;
                        MMA_BF16(acc[mi][nj], ah[mi], &bhv[j2*2]);
                        MMA_BF16(acc[mi][nj], ah[mi], &blv[j2*2]);
                        MMA_BF16(acc[mi][nj], al[mi], &bhv[j2*2]);
                    }
            }
        }
    }

    float* Sp = g_S + (size_t)bh*Dc*Dc;
    int g = lane >> 2, q4 = lane & 3;
#pragma unroll
    for (int nj = 0; nj < 8; nj++) {
        int l = n0w + nj*8 + q4*2;
#pragma unroll
        for (int mi = 0; mi < 2; mi++) {
            int k0 = m0w + mi*16 + g;
            atomicAdd(&Sp[k0*Dc + l],       acc[mi][nj][0]);
            atomicAdd(&Sp[k0*Dc + l + 1],   acc[mi][nj][1]);
            atomicAdd(&Sp[(k0+8)*Dc + l],   acc[mi][nj][2]);
            atomicAdd(&Sp[(k0+8)*Dc + l+1], acc[mi][nj][3]);
        }
    }
}

// ---------------- stage 3c: normalized correlation (table-driven) ----------------
__global__ void k_corr() {
    int c = blockIdx.x*256 + threadIdx.x;
    int bh = blockIdx.y;
    if (c >= DCORR) return;
    int pr = g_iu[c];
    int k = pr >> 8, l = pr & 255;
    float muk = g_muk[bh*Dc + k], sdk = g_sdk[bh*Dc + k];
    float muv = g_muv[bh*Dc + l], sdv = g_sdv[bh*Dc + l];
    float S = g_S[(size_t)bh*Dc*Dc + k*Dc + l];
    g_corr[(size_t)bh*DCORR + c] = (S - (float)Tc*muk*muv) / ((float)Tc*sdk*sdv);
}

// ---------------- stage 4: outs += corr . Wproj (warp-per-e, coalesced) ----------------
__global__ __launch_bounds__(256) void k_proj(const float* __restrict__ Wproj) {
    __shared__ float sc[8][132];
    int tid = threadIdx.x;
    int warp = tid >> 5, lane = tid & 31;
    int h = blockIdx.y;
    int cs = blockIdx.z;
    int e = blockIdx.x*8 + warp;
    int start = cs*2032;
    const float* wrow = Wproj + ((size_t)h*Ec + e)*DCORR;
    float acc[8];
#pragma unroll
    for (int b = 0; b < 8; b++) acc[b] = 0.f;

#pragma unroll 1
    for (int c0 = start; c0 < start + 2032; c0 += 128) {
        int lim = start + 2032 - c0; if (lim > 128) lim = 128;
        {
            float4 cv = make_float4(0.f,0.f,0.f,0.f);
            if (lane*4 < lim)
                cv = *(const float4*)(g_corr + ((size_t)warp*Hc + h)*DCORR + c0 + lane*4);
            *(float4*)&sc[warp][lane*4] = cv;
        }
        __syncthreads();
        float4 wv = make_float4(0.f,0.f,0.f,0.f);
        if (lane*4 < lim) wv = *(const float4*)(wrow + c0 + lane*4);
#pragma unroll
        for (int b = 0; b < 8; b++) {
            float4 sv = *(float4*)&sc[b][lane*4];
            acc[b] += wv.x*sv.x + wv.y*sv.y + wv.z*sv.z + wv.w*sv.w;
        }
        __syncthreads();
    }
#pragma unroll
    for (int b = 0; b < 8; b++) {
        float a = acc[b];
        for (int off = 16; off; off >>= 1) a += __shfl_down_sync(~0u, a, off);
        if (lane == 0) atomicAdd(&g_outs[b*(Hc*Ec) + h*Ec + e], a);
    }
}

// ---------------- stage 5: final linears + mix ----------------
__global__ __launch_bounds__(256) void k_final(
    const float* __restrict__ WT, const float* __restrict__ bT,
    const float* __restrict__ Wp, const float* __restrict__ bp,
    float* __restrict__ out) {
    __shared__ float so1[Hc*Dc];
    __shared__ float sout[Hc*Ec];
    __shared__ float sred[256];
    int b = blockIdx.x, ec = blockIdx.y;
    int tid = threadIdx.x;
    for (int j = tid; j < Hc*Dc; j += 256) so1[j]  = g_o1[b*Hc*Dc + j];
    for (int j = tid; j < Hc*Ec; j += 256) sout[j] = g_outs[b*Hc*Ec + j];
    __syncthreads();
    int e_l = tid >> 3, js = tid & 7;
    int e = ec*32 + e_l;
    float a = 0.f;
    const float* wt = WT + (size_t)e*(Hc*Dc) + js*128;
    const float* s1p = so1 + js*128;
#pragma unroll 4
    for (int j = 0; j < 128; j += 4) {
        float4 wv = *(const float4*)(wt + j);
        float4 sv = *(const float4*)(s1p + j);
        a += wv.x*sv.x + wv.y*sv.y + wv.z*sv.z + wv.w*sv.w;
    }
    const float* wp = Wp + (size_t)e*(Hc*Ec) + js*256;
    const float* s2p = sout + js*256;
#pragma unroll 4
    for (int j = 0; j < 256; j += 4) {
        float4 wv = *(const float4*)(wp + j);
        float4 sv = *(const float4*)(s2p + j);
        a += wv.x*sv.x + wv.y*sv.y + wv.z*sv.z + wv.w*sv.w;
    }
    if (js == 0) a += bT[e] + bp[e];
    sred[tid] = a;
    __syncthreads();
    if (tid < 32) {
        float s = 0.f;
#pragma unroll
        for (int k = 0; k < 8; k++) s += sred[tid*8 + k];
        out[b*Ec + ec*32 + tid] = 0.5f*s;
    }
}

// ---------------- launch ----------------
extern "C" void kernel_launch(void* const* d_in, const int* in_sizes, int n_in,
                              void* d_out, int out_size) {
    const float* x     = (const float*)d_in[0];
    const float* wk    = (const float*)d_in[1];
    const float* wv    = (const float*)d_in[2];
    const float* q     = (const float*)d_in[3];
    const float* Wk    = (const float*)d_in[4];
    const float* bk    = (const float*)d_in[5];
    const float* Wv    = (const float*)d_in[6];
    const float* bv    = (const float*)d_in[7];
    const float* Wproj = (const float*)d_in[8];
    const float* bproj = (const float*)d_in[9];
    const float* WT    = (const float*)d_in[10];
    const float* bT    = (const float*)d_in[11];
    const float* Wp    = (const float*)d_in[12];
    const float* bp    = (const float*)d_in[13];
    float* out = (float*)d_out;

    cudaFuncSetAttribute(k_gemm, cudaFuncAttributeMaxDynamicSharedMemorySize, GSM);
    cudaFuncSetAttribute(k_as,   cudaFuncAttributeMaxDynamicSharedMemorySize, GSM);

    k_initw<<<dim3(3072, 2), 256>>>(wk, wv, Wk, Wv);
    k_raw<<<dim3(16, Fc/16, Bc), dim3(16, 8)>>>(x);
    k_gemm<<<dim3(8, Bc*Hc, 2), 256, GSM>>>(bk, bv);
    k_as<<<257, 256, GSM>>>(q, bproj);
    k_corr<<<dim3((DCORR+255)/256, Bc*Hc), 256>>>();
    k_proj<<<dim3(Ec/8, Hc, 4), 256>>>(Wproj);
    k_final<<<dim3(Bc, Ec/32), 256>>>(WT, bT, Wp, bp, out);
}